// round 1
// baseline (speedup 1.0000x reference)
#include <cuda_runtime.h>
#include <math.h>

#define BATCH 2
#define SEQ   2048
#define CLEN  2048
#define NH    16
#define NKVH  4
#define HD    128
#define HIDDIM 2048
#define EPSF  1e-6f
#define SCALEF 0.08838834764831845f   // 1/sqrt(128)

// ---------------- scratch (device globals: no allocation allowed) ----------
__device__ float g_q [BATCH*SEQ*HIDDIM];          // Q after proj+rmsnorm  [b][s][h][d]
__device__ float g_kv[BATCH*CLEN*NKVH*HD*2];      // raw packed KV proj
__device__ float g_kT[BATCH*NKVH*HD*CLEN];        // K normalized, transposed [b][kvh][d][l]
__device__ float g_v [BATCH*NKVH*CLEN*HD];        // V [b][kvh][l][d]
__device__ float g_o [BATCH*SEQ*HIDDIM];          // attention output [b][s][h*d]

// ---------------- generic SGEMM: C[M,N] = A[M,K] * B[K,N], row-major ------
// M%128==0, N%128==0, K%16==0. 256 threads, 128x128 block tile, 8x8 thread tile.
__global__ __launch_bounds__(256) void sgemm_kernel(
    const float* __restrict__ A, const float* __restrict__ B, float* __restrict__ C,
    int M, int N, int K)
{
    __shared__ float As[16 * 132];   // A^T tile: As[k][m], pitch 132
    __shared__ float Bs[16 * 128];   // B tile:   Bs[k][n]

    const int tid = threadIdx.x;
    const int bm  = blockIdx.y * 128;
    const int bn  = blockIdx.x * 128;
    const int tx  = tid & 15;
    const int ty  = tid >> 4;

    const int arow = tid >> 2;          // 0..63
    const int ac4  = (tid & 3) << 2;    // 0,4,8,12
    const int brow = tid >> 5;          // 0..7
    const int bc4  = (tid & 31) << 2;   // 0..124

    float acc[8][8];
#pragma unroll
    for (int i = 0; i < 8; i++)
#pragma unroll
        for (int j = 0; j < 8; j++) acc[i][j] = 0.f;

    for (int k0 = 0; k0 < K; k0 += 16) {
        float4 a0 = *(const float4*)(A + (bm + arow)      * K + k0 + ac4);
        float4 a1 = *(const float4*)(A + (bm + arow + 64) * K + k0 + ac4);
        float4 b0 = *(const float4*)(B + (k0 + brow)      * N + bn + bc4);
        float4 b1 = *(const float4*)(B + (k0 + brow + 8)  * N + bn + bc4);

        __syncthreads();   // previous iteration's compute done
        As[(ac4 + 0) * 132 + arow]      = a0.x;
        As[(ac4 + 1) * 132 + arow]      = a0.y;
        As[(ac4 + 2) * 132 + arow]      = a0.z;
        As[(ac4 + 3) * 132 + arow]      = a0.w;
        As[(ac4 + 0) * 132 + arow + 64] = a1.x;
        As[(ac4 + 1) * 132 + arow + 64] = a1.y;
        As[(ac4 + 2) * 132 + arow + 64] = a1.z;
        As[(ac4 + 3) * 132 + arow + 64] = a1.w;
        *(float4*)&Bs[ brow      * 128 + bc4] = b0;
        *(float4*)&Bs[(brow + 8) * 128 + bc4] = b1;
        __syncthreads();

#pragma unroll
        for (int k = 0; k < 16; k++) {
            float av[8], bv[8];
            *(float4*)&av[0] = *(float4*)&As[k * 132 + ty * 8];
            *(float4*)&av[4] = *(float4*)&As[k * 132 + ty * 8 + 4];
            *(float4*)&bv[0] = *(float4*)&Bs[k * 128 + tx * 8];
            *(float4*)&bv[4] = *(float4*)&Bs[k * 128 + tx * 8 + 4];
#pragma unroll
            for (int i = 0; i < 8; i++)
#pragma unroll
                for (int j = 0; j < 8; j++)
                    acc[i][j] += av[i] * bv[j];
        }
    }

#pragma unroll
    for (int i = 0; i < 8; i++) {
        int row = bm + ty * 8 + i;
        *(float4*)(C + row * N + bn + tx * 8)     = make_float4(acc[i][0], acc[i][1], acc[i][2], acc[i][3]);
        *(float4*)(C + row * N + bn + tx * 8 + 4) = make_float4(acc[i][4], acc[i][5], acc[i][6], acc[i][7]);
    }
}

// ---------------- per-head RMSNorm on Q (in-place), one warp per (token,head)
__global__ __launch_bounds__(256) void rmsnorm_q_kernel(float* __restrict__ q,
                                                        const float* __restrict__ w)
{
    int row  = blockIdx.x * 8 + (threadIdx.x >> 5);   // B*S*H rows of length 128
    int lane = threadIdx.x & 31;
    float4 v = *(float4*)(q + row * HD + lane * 4);
    float ss = v.x * v.x + v.y * v.y + v.z * v.z + v.w * v.w;
#pragma unroll
    for (int o = 16; o > 0; o >>= 1) ss += __shfl_xor_sync(0xffffffffu, ss, o);
    float r = rsqrtf(ss * (1.f / 128.f) + EPSF);
    float4 wv = *(const float4*)(w + lane * 4);
    v.x *= r * wv.x; v.y *= r * wv.y; v.z *= r * wv.z; v.w *= r * wv.w;
    *(float4*)(q + row * HD + lane * 4) = v;
}

// ---------------- split packed KV, rmsnorm K, write K transposed + V -------
__global__ __launch_bounds__(256) void kvsplit_kernel(
    const float* __restrict__ kv, const float* __restrict__ wk,
    float* __restrict__ kT, float* __restrict__ v)
{
    int row  = blockIdx.x * 8 + (threadIdx.x >> 5);   // (b*CLEN + l)*NKVH + kvh
    int lane = threadIdx.x & 31;
    int kvh  = row & 3;
    int bl   = row >> 2;
    int b    = bl >> 11;     // / 2048
    int l    = bl & 2047;

    const float* base = kv + row * 256;
    float4 f0 = *(const float4*)(base + lane * 8);
    float4 f1 = *(const float4*)(base + lane * 8 + 4);
    float k0 = f0.x, k1 = f0.z, k2 = f1.x, k3 = f1.z;
    float v0 = f0.y, v1 = f0.w, v2 = f1.y, v3 = f1.w;

    float ss = k0 * k0 + k1 * k1 + k2 * k2 + k3 * k3;
#pragma unroll
    for (int o = 16; o > 0; o >>= 1) ss += __shfl_xor_sync(0xffffffffu, ss, o);
    float r = rsqrtf(ss * (1.f / 128.f) + EPSF);

    int d0 = lane * 4;
    float4 wv = *(const float4*)(wk + d0);
    int kTb = ((b * NKVH + kvh) * HD + d0) * CLEN + l;
    kT[kTb]            = k0 * r * wv.x;
    kT[kTb + CLEN]     = k1 * r * wv.y;
    kT[kTb + 2 * CLEN] = k2 * r * wv.z;
    kT[kTb + 3 * CLEN] = k3 * r * wv.w;

    int vb = ((b * NKVH + kvh) * CLEN + l) * HD + d0;
    *(float4*)(v + vb) = make_float4(v0, v1, v2, v3);
}

// ---------------- flash attention: BQ=64, BK=64, fp32 ----------------------
__global__ __launch_bounds__(256) void attn_kernel(
    const float* __restrict__ q, const float* __restrict__ kT,
    const float* __restrict__ v, float* __restrict__ o)
{
    extern __shared__ float sm[];
    float* Qs = sm;                 // 64 x 132
    float* Kt = Qs + 64 * 132;      // 128 x 64   (K transposed: [d][key])
    float* Vs = Kt + 128 * 64;      // 64 x 128
    float* Ps = Vs + 64 * 128;      // 64 x 65

    const int tid = threadIdx.x;
    const int tx = tid & 15, ty = tid >> 4;
    const int qt = blockIdx.x;
    const int h  = blockIdx.y;
    const int b  = blockIdx.z;
    const int kvh = h >> 2;
    const int s0  = qt * 64;

    // Q tile (rows = queries, stride HIDDIM between consecutive s)
    {
        const float* qbase = q + ((b * SEQ + s0) * NH + h) * HD;
#pragma unroll
        for (int it = 0; it < 8; it++) {
            int slot = tid + it * 256;
            int row = slot >> 5;
            int c4  = (slot & 31) << 2;
            *(float4*)&Qs[row * 132 + c4] = *(const float4*)(qbase + row * HIDDIM + c4);
        }
    }

    float m[4], lsum[4], acc[4][8];
#pragma unroll
    for (int i = 0; i < 4; i++) { m[i] = -1e30f; lsum[i] = 0.f; }
#pragma unroll
    for (int i = 0; i < 4; i++)
#pragma unroll
        for (int j = 0; j < 8; j++) acc[i][j] = 0.f;

    const float* kbase = kT + ((b * NKVH + kvh) * HD) * CLEN;  // [128][CLEN]
    const float* vbase = v  + ((b * NKVH + kvh) * CLEN) * HD;  // [CLEN][128]

    for (int l0 = 0; l0 < CLEN; l0 += 64) {
        __syncthreads();
#pragma unroll
        for (int it = 0; it < 8; it++) {           // K tile: Kt[128][64]
            int slot = tid + it * 256;
            int row = slot >> 4;
            int c4  = (slot & 15) << 2;
            *(float4*)&Kt[row * 64 + c4] = *(const float4*)(kbase + row * CLEN + l0 + c4);
        }
#pragma unroll
        for (int it = 0; it < 8; it++) {           // V tile: Vs[64][128]
            int slot = tid + it * 256;
            int row = slot >> 5;
            int c4  = (slot & 31) << 2;
            *(float4*)&Vs[row * 128 + c4] = *(const float4*)(vbase + (l0 + row) * HD + c4);
        }
        __syncthreads();

        // scores: sc[i][j] = Q[ty*4+i][:] . K[tx*4+j][:]
        float sc[4][4];
#pragma unroll
        for (int i = 0; i < 4; i++)
#pragma unroll
            for (int j = 0; j < 4; j++) sc[i][j] = 0.f;

#pragma unroll 8
        for (int d = 0; d < 128; d += 4) {
            float qr[4][4], kr[4][4];
#pragma unroll
            for (int i = 0; i < 4; i++)
                *(float4*)qr[i] = *(float4*)&Qs[(ty * 4 + i) * 132 + d];
#pragma unroll
            for (int dd = 0; dd < 4; dd++)
                *(float4*)kr[dd] = *(float4*)&Kt[(d + dd) * 64 + tx * 4];
#pragma unroll
            for (int i = 0; i < 4; i++)
#pragma unroll
                for (int j = 0; j < 4; j++)
#pragma unroll
                    for (int dd = 0; dd < 4; dd++)
                        sc[i][j] += qr[i][dd] * kr[dd][j];
        }

        // online softmax update
#pragma unroll
        for (int i = 0; i < 4; i++) {
#pragma unroll
            for (int j = 0; j < 4; j++) sc[i][j] *= SCALEF;
            float rm = fmaxf(fmaxf(sc[i][0], sc[i][1]), fmaxf(sc[i][2], sc[i][3]));
#pragma unroll
            for (int off = 8; off > 0; off >>= 1)
                rm = fmaxf(rm, __shfl_xor_sync(0xffffffffu, rm, off));
            float mnew = fmaxf(m[i], rm);
            float corr = __expf(m[i] - mnew);
            m[i] = mnew;
            float ps0 = __expf(sc[i][0] - mnew);
            float ps1 = __expf(sc[i][1] - mnew);
            float ps2 = __expf(sc[i][2] - mnew);
            float ps3 = __expf(sc[i][3] - mnew);
            float rs = ps0 + ps1 + ps2 + ps3;
#pragma unroll
            for (int off = 8; off > 0; off >>= 1)
                rs += __shfl_xor_sync(0xffffffffu, rs, off);
            lsum[i] = lsum[i] * corr + rs;
#pragma unroll
            for (int j = 0; j < 8; j++) acc[i][j] *= corr;
            float* prow = &Ps[(ty * 4 + i) * 65 + tx * 4];
            prow[0] = ps0; prow[1] = ps1; prow[2] = ps2; prow[3] = ps3;
        }
        __syncthreads();

        // O += P @ V
#pragma unroll 4
        for (int kk = 0; kk < 64; kk++) {
            float p0 = Ps[(ty * 4 + 0) * 65 + kk];
            float p1 = Ps[(ty * 4 + 1) * 65 + kk];
            float p2 = Ps[(ty * 4 + 2) * 65 + kk];
            float p3 = Ps[(ty * 4 + 3) * 65 + kk];
            float vv[8];
            *(float4*)&vv[0] = *(float4*)&Vs[kk * 128 + tx * 8];
            *(float4*)&vv[4] = *(float4*)&Vs[kk * 128 + tx * 8 + 4];
#pragma unroll
            for (int j = 0; j < 8; j++) {
                acc[0][j] += p0 * vv[j];
                acc[1][j] += p1 * vv[j];
                acc[2][j] += p2 * vv[j];
                acc[3][j] += p3 * vv[j];
            }
        }
    }

    // epilogue: normalize and write [b][s][h*D]
#pragma unroll
    for (int i = 0; i < 4; i++) {
        float inv = 1.f / lsum[i];
        int srow = s0 + ty * 4 + i;
        float* op = o + (b * SEQ + srow) * HIDDIM + h * HD + tx * 8;
        *(float4*)op       = make_float4(acc[i][0] * inv, acc[i][1] * inv, acc[i][2] * inv, acc[i][3] * inv);
        *(float4*)(op + 4) = make_float4(acc[i][4] * inv, acc[i][5] * inv, acc[i][6] * inv, acc[i][7] * inv);
    }
}

// ---------------- launch ----------------------------------------------------
extern "C" void kernel_launch(void* const* d_in, const int* in_sizes, int n_in,
                              void* d_out, int out_size)
{
    (void)in_sizes; (void)n_in; (void)out_size;
    const float* x   = (const float*)d_in[0];
    const float* c   = (const float*)d_in[1];
    const float* wq  = (const float*)d_in[2];
    const float* wkv = (const float*)d_in[3];
    const float* wo  = (const float*)d_in[4];
    const float* nqw = (const float*)d_in[5];
    const float* nkw = (const float*)d_in[6];
    float* out = (float*)d_out;

    float *q, *kv, *kT, *v, *o;
    cudaGetSymbolAddress((void**)&q,  g_q);
    cudaGetSymbolAddress((void**)&kv, g_kv);
    cudaGetSymbolAddress((void**)&kT, g_kT);
    cudaGetSymbolAddress((void**)&v,  g_v);
    cudaGetSymbolAddress((void**)&o,  g_o);

    // 1) Q projection: [4096,2048] = x @ wq
    dim3 gq(HIDDIM / 128, (BATCH * SEQ) / 128);
    sgemm_kernel<<<gq, 256>>>(x, wq, q, BATCH * SEQ, HIDDIM, HIDDIM);

    // 2) per-head RMSNorm on Q
    rmsnorm_q_kernel<<<(BATCH * SEQ * NH) / 8, 256>>>(q, nqw);

    // 3) KV projection: [4096,1024] = c @ wkv
    dim3 gkv((NKVH * HD * 2) / 128, (BATCH * CLEN) / 128);
    sgemm_kernel<<<gkv, 256>>>(c, wkv, kv, BATCH * CLEN, NKVH * HD * 2, HIDDIM);

    // 4) split K/V, rmsnorm K, K transposed
    kvsplit_kernel<<<(BATCH * CLEN * NKVH) / 8, 256>>>(kv, nkw, kT, v);

    // 5) attention
    int smem = (64 * 132 + 128 * 64 + 64 * 128 + 64 * 65) * 4;
    cudaFuncSetAttribute(attn_kernel, cudaFuncAttributeMaxDynamicSharedMemorySize, smem);
    attn_kernel<<<dim3(SEQ / 64, NH, BATCH), 256, smem>>>(q, kT, v, o);

    // 6) output projection: [4096,2048] = o @ wo
    sgemm_kernel<<<gq, 256>>>(o, wo, out, BATCH * SEQ, HIDDIM, HIDDIM);
}

// round 3
// speedup vs baseline: 1.2208x; 1.2208x over previous
#include <cuda_runtime.h>
#include <cuda_bf16.h>
#include <math.h>
#include <stdint.h>

#define BATCH 2
#define SEQ   2048
#define CLEN  2048
#define NH    16
#define NKVH  4
#define HD    128
#define HIDDIM 2048
#define EPSF  1e-6f
#define SCALEF 0.08838834764831845f   // 1/sqrt(128)

// ---------------- scratch (device globals: no allocation allowed) ----------
__device__ float g_q [BATCH*SEQ*HIDDIM];
__device__ float g_kv[BATCH*CLEN*NKVH*HD*2];
__device__ float g_kT[BATCH*NKVH*HD*CLEN];
__device__ float g_v [BATCH*NKVH*CLEN*HD];
__device__ float g_o [BATCH*SEQ*HIDDIM];

__device__ __nv_bfloat16 g_ah[BATCH*SEQ*HIDDIM];
__device__ __nv_bfloat16 g_al[BATCH*SEQ*HIDDIM];
__device__ __nv_bfloat16 g_bh[HIDDIM*HIDDIM];
__device__ __nv_bfloat16 g_bl[HIDDIM*HIDDIM];

// ======================= family-common tensor helpers ======================
__device__ __forceinline__ uint32_t smem_u32(const void* p) {
    uint32_t a;
    asm("{ .reg .u64 t; cvta.to.shared.u64 t, %1; cvt.u32.u64 %0, t; }" : "=r"(a) : "l"(p));
    return a;
}
__device__ __forceinline__ void cpa16(uint32_t d, const void* g) {
    asm volatile("cp.async.cg.shared.global [%0], [%1], 16;" :: "r"(d), "l"(g) : "memory");
}
#define CP_COMMIT() asm volatile("cp.async.commit_group;" ::: "memory")

__device__ __forceinline__ void ldsm4(uint32_t& r0, uint32_t& r1, uint32_t& r2, uint32_t& r3,
                                      uint32_t a) {
    asm volatile("ldmatrix.sync.aligned.m8n8.x4.shared.b16 {%0,%1,%2,%3}, [%4];"
                 : "=r"(r0), "=r"(r1), "=r"(r2), "=r"(r3) : "r"(a));
}
__device__ __forceinline__ void mma16816(float* c, const uint32_t* a, uint32_t b0, uint32_t b1) {
    asm volatile(
        "mma.sync.aligned.m16n8k16.row.col.f32.bf16.bf16.f32 "
        "{%0,%1,%2,%3}, {%4,%5,%6,%7}, {%8,%9}, {%0,%1,%2,%3};"
        : "+f"(c[0]), "+f"(c[1]), "+f"(c[2]), "+f"(c[3])
        : "r"(a[0]), "r"(a[1]), "r"(a[2]), "r"(a[3]), "r"(b0), "r"(b1));
}

// ---------------- split-bf16 conversion kernels ----------------------------
__global__ __launch_bounds__(256) void convA_kernel(
    const float4* __restrict__ in, __nv_bfloat16* __restrict__ hi,
    __nv_bfloat16* __restrict__ lo)
{
    size_t i = (size_t)blockIdx.x * 256 + threadIdx.x;
    float4 v = in[i];
    __nv_bfloat16 h0 = __float2bfloat16(v.x), h1 = __float2bfloat16(v.y);
    __nv_bfloat16 h2 = __float2bfloat16(v.z), h3 = __float2bfloat16(v.w);
    __nv_bfloat16 l0 = __float2bfloat16(v.x - __bfloat162float(h0));
    __nv_bfloat16 l1 = __float2bfloat16(v.y - __bfloat162float(h1));
    __nv_bfloat16 l2 = __float2bfloat16(v.z - __bfloat162float(h2));
    __nv_bfloat16 l3 = __float2bfloat16(v.w - __bfloat162float(h3));
    ((__nv_bfloat162*)hi)[i * 2]     = __nv_bfloat162(h0, h1);
    ((__nv_bfloat162*)hi)[i * 2 + 1] = __nv_bfloat162(h2, h3);
    ((__nv_bfloat162*)lo)[i * 2]     = __nv_bfloat162(l0, l1);
    ((__nv_bfloat162*)lo)[i * 2 + 1] = __nv_bfloat162(l2, l3);
}

// weight transpose + split: W[K,N] fp32 -> Wt_h/Wt_l[N,K] bf16
__global__ __launch_bounds__(256) void convWT_kernel(
    const float* __restrict__ w, __nv_bfloat16* __restrict__ th,
    __nv_bfloat16* __restrict__ tl, int K, int N)
{
    __shared__ float s[32][33];
    int n0 = blockIdx.x * 32, k0 = blockIdx.y * 32;
    int tx = threadIdx.x & 31, ty = threadIdx.x >> 5;
#pragma unroll
    for (int i = ty; i < 32; i += 8)
        s[i][tx] = w[(size_t)(k0 + i) * N + n0 + tx];
    __syncthreads();
#pragma unroll
    for (int j = ty; j < 32; j += 8) {
        float v = s[tx][j];
        __nv_bfloat16 h = __float2bfloat16(v);
        __nv_bfloat16 l = __float2bfloat16(v - __bfloat162float(h));
        size_t idx = (size_t)(n0 + j) * K + k0 + tx;
        th[idx] = h;
        tl[idx] = l;
    }
}

// ---------------- HMMA split-bf16 GEMM: C[M,N] = A[M,K] @ Wt[N,K]^T --------
// CTA tile 128x128, block-K 32, 3-stage cp.async pipeline.
// smem tile: 128 rows x 32 bf16, row pitch 80B (conflict-free ldmatrix).
#define TPITCH 80
#define TBYTES (128 * TPITCH)          // 10240
#define STAGEB (4 * TBYTES)            // 40960: Ah, Al, Bh, Bl
#define NSTAGE 3

__global__ __launch_bounds__(256, 1) void gemm_hmma_kernel(
    const __nv_bfloat16* __restrict__ Ah, const __nv_bfloat16* __restrict__ Al,
    const __nv_bfloat16* __restrict__ Bh, const __nv_bfloat16* __restrict__ Bl,
    float* __restrict__ C, int M, int N, int K)
{
    extern __shared__ char smc[];
    const uint32_t sb = smem_u32(smc);

    const int tid  = threadIdx.x;
    const int lane = tid & 31;
    const int wid  = tid >> 5;
    const int wm   = wid & 1;          // 2 warps along M
    const int wn   = wid >> 1;         // 4 warps along N
    const int bm   = blockIdx.y * 128;
    const int bn   = blockIdx.x * 128;

    // cp.async thread mapping: per tile, thread t -> row t>>1, 32B half (t&1)
    const int crow = tid >> 1;
    const int chalf = (tid & 1) * 16;          // element offset within 32-k
    const size_t gOffA = (size_t)(bm + crow) * K + chalf;
    const size_t gOffB = (size_t)(bn + crow) * K + chalf;
    const uint32_t sOff = crow * TPITCH + chalf * 2;

    // ldmatrix lane addressing
    const uint32_t aLaneOff = (lane & 15) * TPITCH + (lane >> 4) * 16;

    float acc[4][4][4];
#pragma unroll
    for (int i = 0; i < 4; i++)
#pragma unroll
        for (int j = 0; j < 4; j++)
#pragma unroll
            for (int r = 0; r < 4; r++) acc[i][j][r] = 0.f;

    const int nst = K / 32;

    // prologue: stages 0,1
#pragma unroll
    for (int p = 0; p < 2; ++p) {
        uint32_t st = sb + p * STAGEB;
        int k0 = p * 32;
        cpa16(st + sOff,              Ah + gOffA + k0);
        cpa16(st + sOff + 16,         Ah + gOffA + k0 + 8);
        cpa16(st + TBYTES + sOff,     Al + gOffA + k0);
        cpa16(st + TBYTES + sOff + 16, Al + gOffA + k0 + 8);
        cpa16(st + 2 * TBYTES + sOff,      Bh + gOffB + k0);
        cpa16(st + 2 * TBYTES + sOff + 16, Bh + gOffB + k0 + 8);
        cpa16(st + 3 * TBYTES + sOff,      Bl + gOffB + k0);
        cpa16(st + 3 * TBYTES + sOff + 16, Bl + gOffB + k0 + 8);
        CP_COMMIT();
    }

    int buf = 0;
    for (int s = 0; s < nst; ++s) {
        if (s + 1 < nst) asm volatile("cp.async.wait_group 1;" ::: "memory");
        else             asm volatile("cp.async.wait_group 0;" ::: "memory");
        __syncthreads();

        // prefetch stage s+2
        if (s + 2 < nst) {
            int pb = (buf + 2) % NSTAGE;
            uint32_t st = sb + pb * STAGEB;
            int k0 = (s + 2) * 32;
            cpa16(st + sOff,               Ah + gOffA + k0);
            cpa16(st + sOff + 16,          Ah + gOffA + k0 + 8);
            cpa16(st + TBYTES + sOff,      Al + gOffA + k0);
            cpa16(st + TBYTES + sOff + 16, Al + gOffA + k0 + 8);
            cpa16(st + 2 * TBYTES + sOff,      Bh + gOffB + k0);
            cpa16(st + 2 * TBYTES + sOff + 16, Bh + gOffB + k0 + 8);
            cpa16(st + 3 * TBYTES + sOff,      Bl + gOffB + k0);
            cpa16(st + 3 * TBYTES + sOff + 16, Bl + gOffB + k0 + 8);
            CP_COMMIT();
        }

        uint32_t st = sb + buf * STAGEB;
        uint32_t aBaseH = st + (wm * 64) * TPITCH + aLaneOff;
        uint32_t aBaseL = aBaseH + TBYTES;
        uint32_t bBaseH = st + 2 * TBYTES + (wn * 32) * TPITCH + aLaneOff;
        uint32_t bBaseL = bBaseH + TBYTES;

#pragma unroll
        for (int ks = 0; ks < 2; ++ks) {
            uint32_t ko = ks * 32;   // bytes: 16 bf16
            uint32_t ahf[4][4], alf[4][4];
#pragma unroll
            for (int mi = 0; mi < 4; ++mi) {
                ldsm4(ahf[mi][0], ahf[mi][1], ahf[mi][2], ahf[mi][3],
                      aBaseH + mi * 16 * TPITCH + ko);
                ldsm4(alf[mi][0], alf[mi][1], alf[mi][2], alf[mi][3],
                      aBaseL + mi * 16 * TPITCH + ko);
            }
            uint32_t bh[2][4], bl[2][4];
#pragma unroll
            for (int bi = 0; bi < 2; ++bi) {
                ldsm4(bh[bi][0], bh[bi][1], bh[bi][2], bh[bi][3],
                      bBaseH + bi * 16 * TPITCH + ko);
                ldsm4(bl[bi][0], bl[bi][1], bl[bi][2], bl[bi][3],
                      bBaseL + bi * 16 * TPITCH + ko);
            }
            // b frag (nj): nj=bi*2+sub, sub0 -> (r0,r2), sub1 -> (r1,r3)
#pragma unroll
            for (int mi = 0; mi < 4; ++mi) {
#pragma unroll
                for (int bi = 0; bi < 2; ++bi) {
#pragma unroll
                    for (int sub = 0; sub < 2; ++sub) {
                        int nj = bi * 2 + sub;
                        uint32_t b0h = bh[bi][sub], b1h = bh[bi][sub + 2];
                        uint32_t b0l = bl[bi][sub], b1l = bl[bi][sub + 2];
                        mma16816(acc[mi][nj], ahf[mi], b0h, b1h);
                        mma16816(acc[mi][nj], ahf[mi], b0l, b1l);
                        mma16816(acc[mi][nj], alf[mi], b0h, b1h);
                    }
                }
            }
        }
        buf = (buf + 1) % NSTAGE;
        __syncthreads();
    }

    // epilogue: register fragments -> global
    const int g  = lane >> 2;
    const int q4 = lane & 3;
#pragma unroll
    for (int mi = 0; mi < 4; ++mi) {
#pragma unroll
        for (int nj = 0; nj < 4; ++nj) {
            int r0 = bm + wm * 64 + mi * 16 + g;
            int c0 = bn + wn * 32 + nj * 8 + q4 * 2;
            *(float2*)(C + (size_t)r0 * N + c0)       = make_float2(acc[mi][nj][0], acc[mi][nj][1]);
            *(float2*)(C + (size_t)(r0 + 8) * N + c0) = make_float2(acc[mi][nj][2], acc[mi][nj][3]);
        }
    }
}

// ---------------- per-head RMSNorm on Q (in-place) -------------------------
__global__ __launch_bounds__(256) void rmsnorm_q_kernel(float* __restrict__ q,
                                                        const float* __restrict__ w)
{
    int row  = blockIdx.x * 8 + (threadIdx.x >> 5);
    int lane = threadIdx.x & 31;
    float4 v = *(float4*)(q + row * HD + lane * 4);
    float ss = v.x * v.x + v.y * v.y + v.z * v.z + v.w * v.w;
#pragma unroll
    for (int o = 16; o > 0; o >>= 1) ss += __shfl_xor_sync(0xffffffffu, ss, o);
    float r = rsqrtf(ss * (1.f / 128.f) + EPSF);
    float4 wv = *(const float4*)(w + lane * 4);
    v.x *= r * wv.x; v.y *= r * wv.y; v.z *= r * wv.z; v.w *= r * wv.w;
    *(float4*)(q + row * HD + lane * 4) = v;
}

// ---------------- split packed KV, rmsnorm K, K transposed + V -------------
__global__ __launch_bounds__(256) void kvsplit_kernel(
    const float* __restrict__ kv, const float* __restrict__ wk,
    float* __restrict__ kT, float* __restrict__ v)
{
    int row  = blockIdx.x * 8 + (threadIdx.x >> 5);
    int lane = threadIdx.x & 31;
    int kvh  = row & 3;
    int bl   = row >> 2;
    int b    = bl >> 11;
    int l    = bl & 2047;

    const float* base = kv + row * 256;
    float4 f0 = *(const float4*)(base + lane * 8);
    float4 f1 = *(const float4*)(base + lane * 8 + 4);
    float k0 = f0.x, k1 = f0.z, k2 = f1.x, k3 = f1.z;
    float v0 = f0.y, v1 = f0.w, v2 = f1.y, v3 = f1.w;

    float ss = k0 * k0 + k1 * k1 + k2 * k2 + k3 * k3;
#pragma unroll
    for (int o = 16; o > 0; o >>= 1) ss += __shfl_xor_sync(0xffffffffu, ss, o);
    float r = rsqrtf(ss * (1.f / 128.f) + EPSF);

    int d0 = lane * 4;
    float4 wv = *(const float4*)(wk + d0);
    int kTb = ((b * NKVH + kvh) * HD + d0) * CLEN + l;
    kT[kTb]            = k0 * r * wv.x;
    kT[kTb + CLEN]     = k1 * r * wv.y;
    kT[kTb + 2 * CLEN] = k2 * r * wv.z;
    kT[kTb + 3 * CLEN] = k3 * r * wv.w;

    int vb = ((b * NKVH + kvh) * CLEN + l) * HD + d0;
    *(float4*)(v + vb) = make_float4(v0, v1, v2, v3);
}

// ---------------- flash attention: BQ=64, BK=64, fp32 ----------------------
__global__ __launch_bounds__(256) void attn_kernel(
    const float* __restrict__ q, const float* __restrict__ kT,
    const float* __restrict__ v, float* __restrict__ o)
{
    extern __shared__ float smf[];
    float* Qs = smf;                // 64 x 132
    float* Kt = Qs + 64 * 132;      // 128 x 64
    float* Vs = Kt + 128 * 64;      // 64 x 128
    float* Ps = Vs + 64 * 128;      // 64 x 65

    const int tid = threadIdx.x;
    const int tx = tid & 15, ty = tid >> 4;
    const int qt = blockIdx.x;
    const int h  = blockIdx.y;
    const int b  = blockIdx.z;
    const int kvh = h >> 2;
    const int s0  = qt * 64;

    {
        const float* qbase = q + ((b * SEQ + s0) * NH + h) * HD;
#pragma unroll
        for (int it = 0; it < 8; it++) {
            int slot = tid + it * 256;
            int row = slot >> 5;
            int c4  = (slot & 31) << 2;
            *(float4*)&Qs[row * 132 + c4] = *(const float4*)(qbase + row * HIDDIM + c4);
        }
    }

    float m[4], lsum[4], acc[4][8];
#pragma unroll
    for (int i = 0; i < 4; i++) { m[i] = -1e30f; lsum[i] = 0.f; }
#pragma unroll
    for (int i = 0; i < 4; i++)
#pragma unroll
        for (int j = 0; j < 8; j++) acc[i][j] = 0.f;

    const float* kbase = kT + ((b * NKVH + kvh) * HD) * CLEN;
    const float* vbase = v  + ((b * NKVH + kvh) * CLEN) * HD;

    for (int l0 = 0; l0 < CLEN; l0 += 64) {
        __syncthreads();
#pragma unroll
        for (int it = 0; it < 8; it++) {
            int slot = tid + it * 256;
            int row = slot >> 4;
            int c4  = (slot & 15) << 2;
            *(float4*)&Kt[row * 64 + c4] = *(const float4*)(kbase + row * CLEN + l0 + c4);
        }
#pragma unroll
        for (int it = 0; it < 8; it++) {
            int slot = tid + it * 256;
            int row = slot >> 5;
            int c4  = (slot & 31) << 2;
            *(float4*)&Vs[row * 128 + c4] = *(const float4*)(vbase + (l0 + row) * HD + c4);
        }
        __syncthreads();

        float sc[4][4];
#pragma unroll
        for (int i = 0; i < 4; i++)
#pragma unroll
            for (int j = 0; j < 4; j++) sc[i][j] = 0.f;

#pragma unroll 8
        for (int d = 0; d < 128; d += 4) {
            float qr[4][4], kr[4][4];
#pragma unroll
            for (int i = 0; i < 4; i++)
                *(float4*)qr[i] = *(float4*)&Qs[(ty * 4 + i) * 132 + d];
#pragma unroll
            for (int dd = 0; dd < 4; dd++)
                *(float4*)kr[dd] = *(float4*)&Kt[(d + dd) * 64 + tx * 4];
#pragma unroll
            for (int i = 0; i < 4; i++)
#pragma unroll
                for (int j = 0; j < 4; j++)
#pragma unroll
                    for (int dd = 0; dd < 4; dd++)
                        sc[i][j] += qr[i][dd] * kr[dd][j];
        }

#pragma unroll
        for (int i = 0; i < 4; i++) {
#pragma unroll
            for (int j = 0; j < 4; j++) sc[i][j] *= SCALEF;
            float rm = fmaxf(fmaxf(sc[i][0], sc[i][1]), fmaxf(sc[i][2], sc[i][3]));
#pragma unroll
            for (int off = 8; off > 0; off >>= 1)
                rm = fmaxf(rm, __shfl_xor_sync(0xffffffffu, rm, off));
            float mnew = fmaxf(m[i], rm);
            float corr = __expf(m[i] - mnew);
            m[i] = mnew;
            float ps0 = __expf(sc[i][0] - mnew);
            float ps1 = __expf(sc[i][1] - mnew);
            float ps2 = __expf(sc[i][2] - mnew);
            float ps3 = __expf(sc[i][3] - mnew);
            float rs = ps0 + ps1 + ps2 + ps3;
#pragma unroll
            for (int off = 8; off > 0; off >>= 1)
                rs += __shfl_xor_sync(0xffffffffu, rs, off);
            lsum[i] = lsum[i] * corr + rs;
#pragma unroll
            for (int j = 0; j < 8; j++) acc[i][j] *= corr;
            float* prow = &Ps[(ty * 4 + i) * 65 + tx * 4];
            prow[0] = ps0; prow[1] = ps1; prow[2] = ps2; prow[3] = ps3;
        }
        __syncthreads();

#pragma unroll 4
        for (int kk = 0; kk < 64; kk++) {
            float p0 = Ps[(ty * 4 + 0) * 65 + kk];
            float p1 = Ps[(ty * 4 + 1) * 65 + kk];
            float p2 = Ps[(ty * 4 + 2) * 65 + kk];
            float p3 = Ps[(ty * 4 + 3) * 65 + kk];
            float vv[8];
            *(float4*)&vv[0] = *(float4*)&Vs[kk * 128 + tx * 8];
            *(float4*)&vv[4] = *(float4*)&Vs[kk * 128 + tx * 8 + 4];
#pragma unroll
            for (int j = 0; j < 8; j++) {
                acc[0][j] += p0 * vv[j];
                acc[1][j] += p1 * vv[j];
                acc[2][j] += p2 * vv[j];
                acc[3][j] += p3 * vv[j];
            }
        }
    }

#pragma unroll
    for (int i = 0; i < 4; i++) {
        float inv = 1.f / lsum[i];
        int srow = s0 + ty * 4 + i;
        float* op = o + (b * SEQ + srow) * HIDDIM + h * HD + tx * 8;
        *(float4*)op       = make_float4(acc[i][0] * inv, acc[i][1] * inv, acc[i][2] * inv, acc[i][3] * inv);
        *(float4*)(op + 4) = make_float4(acc[i][4] * inv, acc[i][5] * inv, acc[i][6] * inv, acc[i][7] * inv);
    }
}

// ---------------- launch ----------------------------------------------------
extern "C" void kernel_launch(void* const* d_in, const int* in_sizes, int n_in,
                              void* d_out, int out_size)
{
    (void)in_sizes; (void)n_in; (void)out_size;
    const float* x   = (const float*)d_in[0];
    const float* c   = (const float*)d_in[1];
    const float* wq  = (const float*)d_in[2];
    const float* wkv = (const float*)d_in[3];
    const float* wo  = (const float*)d_in[4];
    const float* nqw = (const float*)d_in[5];
    const float* nkw = (const float*)d_in[6];
    float* out = (float*)d_out;

    float *q, *kv, *kT, *v, *o;
    __nv_bfloat16 *ah, *al, *bh, *bl;
    cudaGetSymbolAddress((void**)&q,  g_q);
    cudaGetSymbolAddress((void**)&kv, g_kv);
    cudaGetSymbolAddress((void**)&kT, g_kT);
    cudaGetSymbolAddress((void**)&v,  g_v);
    cudaGetSymbolAddress((void**)&o,  g_o);
    cudaGetSymbolAddress((void**)&ah, g_ah);
    cudaGetSymbolAddress((void**)&al, g_al);
    cudaGetSymbolAddress((void**)&bh, g_bh);
    cudaGetSymbolAddress((void**)&bl, g_bl);

    const int M = BATCH * SEQ;            // 4096
    const int K = HIDDIM;                 // 2048
    const int gemm_smem = NSTAGE * STAGEB;  // 122880
    cudaFuncSetAttribute(gemm_hmma_kernel,
                         cudaFuncAttributeMaxDynamicSharedMemorySize, gemm_smem);

    int convA_grid = (M * K) / 4 / 256;   // 8192

    // 1) Q projection: q = x @ wq   [4096,2048]
    convA_kernel<<<convA_grid, 256>>>((const float4*)x, ah, al);
    convWT_kernel<<<dim3(HIDDIM / 32, K / 32), 256>>>(wq, bh, bl, K, HIDDIM);
    gemm_hmma_kernel<<<dim3(HIDDIM / 128, M / 128), 256, gemm_smem>>>(
        ah, al, bh, bl, q, M, HIDDIM, K);

    // 2) per-head RMSNorm on Q
    rmsnorm_q_kernel<<<(M * NH) / 8, 256>>>(q, nqw);

    // 3) KV projection: kv = c @ wkv   [4096,1024]
    convA_kernel<<<convA_grid, 256>>>((const float4*)c, ah, al);
    convWT_kernel<<<dim3((NKVH * HD * 2) / 32, K / 32), 256>>>(wkv, bh, bl, K, NKVH * HD * 2);
    gemm_hmma_kernel<<<dim3((NKVH * HD * 2) / 128, M / 128), 256, gemm_smem>>>(
        ah, al, bh, bl, kv, M, NKVH * HD * 2, K);

    // 4) split K/V, rmsnorm K, K transposed
    kvsplit_kernel<<<(BATCH * CLEN * NKVH) / 8, 256>>>(kv, nkw, kT, v);

    // 5) attention (fp32)
    int attn_smem = (64 * 132 + 128 * 64 + 64 * 128 + 64 * 65) * 4;
    cudaFuncSetAttribute(attn_kernel, cudaFuncAttributeMaxDynamicSharedMemorySize, attn_smem);
    attn_kernel<<<dim3(SEQ / 64, NH, BATCH), 256, attn_smem>>>(q, kT, v, o);

    // 6) output projection: out = o @ wo   [4096,2048]
    convA_kernel<<<convA_grid, 256>>>((const float4*)o, ah, al);
    convWT_kernel<<<dim3(HIDDIM / 32, K / 32), 256>>>(wo, bh, bl, K, HIDDIM);
    gemm_hmma_kernel<<<dim3(HIDDIM / 128, M / 128), 256, gemm_smem>>>(
        ah, al, bh, bl, out, M, HIDDIM, K);
}

// round 4
// speedup vs baseline: 2.3073x; 1.8900x over previous
#include <cuda_runtime.h>
#include <cuda_bf16.h>
#include <math.h>
#include <stdint.h>

#define BATCH 2
#define SEQ   2048
#define CLEN  2048
#define NH    16
#define NKVH  4
#define HD    128
#define HIDDIM 2048
#define EPSF  1e-6f
#define SCALEF 0.08838834764831845f   // 1/sqrt(128)

// ---------------- scratch (device globals) ---------------------------------
__device__ float g_q [BATCH*SEQ*HIDDIM];          // fp32 Q proj out
__device__ float g_kv[BATCH*CLEN*NKVH*HD*2];      // fp32 KV proj out

__device__ __nv_bfloat16 g_qh[BATCH*SEQ*HIDDIM];  // Q post-rmsnorm split
__device__ __nv_bfloat16 g_ql[BATCH*SEQ*HIDDIM];
__device__ __nv_bfloat16 g_kh[BATCH*NKVH*CLEN*HD];
__device__ __nv_bfloat16 g_kl[BATCH*NKVH*CLEN*HD];
__device__ __nv_bfloat16 g_vh[BATCH*NKVH*CLEN*HD];
__device__ __nv_bfloat16 g_vl[BATCH*NKVH*CLEN*HD];

__device__ __nv_bfloat16 g_ah[BATCH*SEQ*HIDDIM];  // GEMM activation hi/lo
__device__ __nv_bfloat16 g_al[BATCH*SEQ*HIDDIM];
__device__ __nv_bfloat16 g_bh[HIDDIM*HIDDIM];     // weight^T hi/lo
__device__ __nv_bfloat16 g_bl[HIDDIM*HIDDIM];

// ======================= family-common tensor helpers ======================
__device__ __forceinline__ uint32_t smem_u32(const void* p) {
    uint32_t a;
    asm("{ .reg .u64 t; cvta.to.shared.u64 t, %1; cvt.u32.u64 %0, t; }" : "=r"(a) : "l"(p));
    return a;
}
__device__ __forceinline__ void cpa16(uint32_t d, const void* g) {
    asm volatile("cp.async.cg.shared.global [%0], [%1], 16;" :: "r"(d), "l"(g) : "memory");
}
#define CP_COMMIT() asm volatile("cp.async.commit_group;" ::: "memory")

__device__ __forceinline__ void ldsm4(uint32_t& r0, uint32_t& r1, uint32_t& r2, uint32_t& r3,
                                      uint32_t a) {
    asm volatile("ldmatrix.sync.aligned.m8n8.x4.shared.b16 {%0,%1,%2,%3}, [%4];"
                 : "=r"(r0), "=r"(r1), "=r"(r2), "=r"(r3) : "r"(a));
}
__device__ __forceinline__ void ldsm4t(uint32_t& r0, uint32_t& r1, uint32_t& r2, uint32_t& r3,
                                       uint32_t a) {
    asm volatile("ldmatrix.sync.aligned.m8n8.x4.trans.shared.b16 {%0,%1,%2,%3}, [%4];"
                 : "=r"(r0), "=r"(r1), "=r"(r2), "=r"(r3) : "r"(a));
}
__device__ __forceinline__ void mma16816(float* c, const uint32_t* a, uint32_t b0, uint32_t b1) {
    asm volatile(
        "mma.sync.aligned.m16n8k16.row.col.f32.bf16.bf16.f32 "
        "{%0,%1,%2,%3}, {%4,%5,%6,%7}, {%8,%9}, {%0,%1,%2,%3};"
        : "+f"(c[0]), "+f"(c[1]), "+f"(c[2]), "+f"(c[3])
        : "r"(a[0]), "r"(a[1]), "r"(a[2]), "r"(a[3]), "r"(b0), "r"(b1));
}
__device__ __forceinline__ uint32_t pack_bf2(float a, float b) {
    __nv_bfloat162 h = __halves2bfloat162(__float2bfloat16(a), __float2bfloat16(b));
    return *(uint32_t*)&h;
}

// ---------------- split-bf16 conversion kernels ----------------------------
__global__ __launch_bounds__(256) void convA_kernel(
    const float4* __restrict__ in, __nv_bfloat16* __restrict__ hi,
    __nv_bfloat16* __restrict__ lo)
{
    size_t i = (size_t)blockIdx.x * 256 + threadIdx.x;
    float4 v = in[i];
    __nv_bfloat16 h0 = __float2bfloat16(v.x), h1 = __float2bfloat16(v.y);
    __nv_bfloat16 h2 = __float2bfloat16(v.z), h3 = __float2bfloat16(v.w);
    __nv_bfloat16 l0 = __float2bfloat16(v.x - __bfloat162float(h0));
    __nv_bfloat16 l1 = __float2bfloat16(v.y - __bfloat162float(h1));
    __nv_bfloat16 l2 = __float2bfloat16(v.z - __bfloat162float(h2));
    __nv_bfloat16 l3 = __float2bfloat16(v.w - __bfloat162float(h3));
    ((__nv_bfloat162*)hi)[i * 2]     = __nv_bfloat162(h0, h1);
    ((__nv_bfloat162*)hi)[i * 2 + 1] = __nv_bfloat162(h2, h3);
    ((__nv_bfloat162*)lo)[i * 2]     = __nv_bfloat162(l0, l1);
    ((__nv_bfloat162*)lo)[i * 2 + 1] = __nv_bfloat162(l2, l3);
}

__global__ __launch_bounds__(256) void convWT_kernel(
    const float* __restrict__ w, __nv_bfloat16* __restrict__ th,
    __nv_bfloat16* __restrict__ tl, int K, int N)
{
    __shared__ float s[32][33];
    int n0 = blockIdx.x * 32, k0 = blockIdx.y * 32;
    int tx = threadIdx.x & 31, ty = threadIdx.x >> 5;
#pragma unroll
    for (int i = ty; i < 32; i += 8)
        s[i][tx] = w[(size_t)(k0 + i) * N + n0 + tx];
    __syncthreads();
#pragma unroll
    for (int j = ty; j < 32; j += 8) {
        float v = s[tx][j];
        __nv_bfloat16 h = __float2bfloat16(v);
        __nv_bfloat16 l = __float2bfloat16(v - __bfloat162float(h));
        size_t idx = (size_t)(n0 + j) * K + k0 + tx;
        th[idx] = h;
        tl[idx] = l;
    }
}

// ---------------- HMMA split-bf16 GEMM (unchanged from R3) -----------------
#define TPITCH 80
#define TBYTES (128 * TPITCH)
#define STAGEB (4 * TBYTES)
#define NSTAGE 3

__global__ __launch_bounds__(256, 1) void gemm_hmma_kernel(
    const __nv_bfloat16* __restrict__ Ah, const __nv_bfloat16* __restrict__ Al,
    const __nv_bfloat16* __restrict__ Bh, const __nv_bfloat16* __restrict__ Bl,
    float* __restrict__ C, int M, int N, int K)
{
    extern __shared__ char smc[];
    const uint32_t sb = smem_u32(smc);

    const int tid  = threadIdx.x;
    const int lane = tid & 31;
    const int wid  = tid >> 5;
    const int wm   = wid & 1;
    const int wn   = wid >> 1;
    const int bm   = blockIdx.y * 128;
    const int bn   = blockIdx.x * 128;

    const int crow = tid >> 1;
    const int chalf = (tid & 1) * 16;
    const size_t gOffA = (size_t)(bm + crow) * K + chalf;
    const size_t gOffB = (size_t)(bn + crow) * K + chalf;
    const uint32_t sOff = crow * TPITCH + chalf * 2;

    const uint32_t aLaneOff = (lane & 15) * TPITCH + (lane >> 4) * 16;

    float acc[4][4][4];
#pragma unroll
    for (int i = 0; i < 4; i++)
#pragma unroll
        for (int j = 0; j < 4; j++)
#pragma unroll
            for (int r = 0; r < 4; r++) acc[i][j][r] = 0.f;

    const int nst = K / 32;

#pragma unroll
    for (int p = 0; p < 2; ++p) {
        uint32_t st = sb + p * STAGEB;
        int k0 = p * 32;
        cpa16(st + sOff,               Ah + gOffA + k0);
        cpa16(st + sOff + 16,          Ah + gOffA + k0 + 8);
        cpa16(st + TBYTES + sOff,      Al + gOffA + k0);
        cpa16(st + TBYTES + sOff + 16, Al + gOffA + k0 + 8);
        cpa16(st + 2 * TBYTES + sOff,      Bh + gOffB + k0);
        cpa16(st + 2 * TBYTES + sOff + 16, Bh + gOffB + k0 + 8);
        cpa16(st + 3 * TBYTES + sOff,      Bl + gOffB + k0);
        cpa16(st + 3 * TBYTES + sOff + 16, Bl + gOffB + k0 + 8);
        CP_COMMIT();
    }

    int buf = 0;
    for (int s = 0; s < nst; ++s) {
        if (s + 1 < nst) asm volatile("cp.async.wait_group 1;" ::: "memory");
        else             asm volatile("cp.async.wait_group 0;" ::: "memory");
        __syncthreads();

        if (s + 2 < nst) {
            int pb = (buf + 2) % NSTAGE;
            uint32_t st = sb + pb * STAGEB;
            int k0 = (s + 2) * 32;
            cpa16(st + sOff,               Ah + gOffA + k0);
            cpa16(st + sOff + 16,          Ah + gOffA + k0 + 8);
            cpa16(st + TBYTES + sOff,      Al + gOffA + k0);
            cpa16(st + TBYTES + sOff + 16, Al + gOffA + k0 + 8);
            cpa16(st + 2 * TBYTES + sOff,      Bh + gOffB + k0);
            cpa16(st + 2 * TBYTES + sOff + 16, Bh + gOffB + k0 + 8);
            cpa16(st + 3 * TBYTES + sOff,      Bl + gOffB + k0);
            cpa16(st + 3 * TBYTES + sOff + 16, Bl + gOffB + k0 + 8);
            CP_COMMIT();
        }

        uint32_t st = sb + buf * STAGEB;
        uint32_t aBaseH = st + (wm * 64) * TPITCH + aLaneOff;
        uint32_t aBaseL = aBaseH + TBYTES;
        uint32_t bBaseH = st + 2 * TBYTES + (wn * 32) * TPITCH + aLaneOff;
        uint32_t bBaseL = bBaseH + TBYTES;

#pragma unroll
        for (int ks = 0; ks < 2; ++ks) {
            uint32_t ko = ks * 32;
            uint32_t ahf[4][4], alf[4][4];
#pragma unroll
            for (int mi = 0; mi < 4; ++mi) {
                ldsm4(ahf[mi][0], ahf[mi][1], ahf[mi][2], ahf[mi][3],
                      aBaseH + mi * 16 * TPITCH + ko);
                ldsm4(alf[mi][0], alf[mi][1], alf[mi][2], alf[mi][3],
                      aBaseL + mi * 16 * TPITCH + ko);
            }
            uint32_t bh[2][4], bl[2][4];
#pragma unroll
            for (int bi = 0; bi < 2; ++bi) {
                ldsm4(bh[bi][0], bh[bi][1], bh[bi][2], bh[bi][3],
                      bBaseH + bi * 16 * TPITCH + ko);
                ldsm4(bl[bi][0], bl[bi][1], bl[bi][2], bl[bi][3],
                      bBaseL + bi * 16 * TPITCH + ko);
            }
#pragma unroll
            for (int mi = 0; mi < 4; ++mi) {
#pragma unroll
                for (int bi = 0; bi < 2; ++bi) {
#pragma unroll
                    for (int sub = 0; sub < 2; ++sub) {
                        int nj = bi * 2 + sub;
                        uint32_t b0h = bh[bi][sub], b1h = bh[bi][sub + 2];
                        uint32_t b0l = bl[bi][sub], b1l = bl[bi][sub + 2];
                        mma16816(acc[mi][nj], ahf[mi], b0h, b1h);
                        mma16816(acc[mi][nj], ahf[mi], b0l, b1l);
                        mma16816(acc[mi][nj], alf[mi], b0h, b1h);
                    }
                }
            }
        }
        buf = (buf + 1) % NSTAGE;
        __syncthreads();
    }

    const int g  = lane >> 2;
    const int q4 = lane & 3;
#pragma unroll
    for (int mi = 0; mi < 4; ++mi) {
#pragma unroll
        for (int nj = 0; nj < 4; ++nj) {
            int r0 = bm + wm * 64 + mi * 16 + g;
            int c0 = bn + wn * 32 + nj * 8 + q4 * 2;
            *(float2*)(C + (size_t)r0 * N + c0)       = make_float2(acc[mi][nj][0], acc[mi][nj][1]);
            *(float2*)(C + (size_t)(r0 + 8) * N + c0) = make_float2(acc[mi][nj][2], acc[mi][nj][3]);
        }
    }
}

// ---------------- per-head RMSNorm on Q -> bf16 split -----------------------
__global__ __launch_bounds__(256) void rmsnorm_q_kernel(
    const float* __restrict__ q, const float* __restrict__ w,
    __nv_bfloat16* __restrict__ qh, __nv_bfloat16* __restrict__ ql)
{
    int row  = blockIdx.x * 8 + (threadIdx.x >> 5);
    int lane = threadIdx.x & 31;
    float4 v = *(const float4*)(q + row * HD + lane * 4);
    float ss = v.x * v.x + v.y * v.y + v.z * v.z + v.w * v.w;
#pragma unroll
    for (int o = 16; o > 0; o >>= 1) ss += __shfl_xor_sync(0xffffffffu, ss, o);
    float r = rsqrtf(ss * (1.f / 128.f) + EPSF);
    float4 wv = *(const float4*)(w + lane * 4);
    float f0 = v.x * r * wv.x, f1 = v.y * r * wv.y;
    float f2 = v.z * r * wv.z, f3 = v.w * r * wv.w;
    __nv_bfloat16 h0 = __float2bfloat16(f0), h1 = __float2bfloat16(f1);
    __nv_bfloat16 h2 = __float2bfloat16(f2), h3 = __float2bfloat16(f3);
    size_t base = (size_t)row * HD + lane * 4;
    *(__nv_bfloat162*)(qh + base)     = __nv_bfloat162(h0, h1);
    *(__nv_bfloat162*)(qh + base + 2) = __nv_bfloat162(h2, h3);
    *(__nv_bfloat162*)(ql + base) = __nv_bfloat162(
        __float2bfloat16(f0 - __bfloat162float(h0)), __float2bfloat16(f1 - __bfloat162float(h1)));
    *(__nv_bfloat162*)(ql + base + 2) = __nv_bfloat162(
        __float2bfloat16(f2 - __bfloat162float(h2)), __float2bfloat16(f3 - __bfloat162float(h3)));
}

// ---------------- split packed KV -> rmsnorm K -> bf16 splits ---------------
__global__ __launch_bounds__(256) void kvsplit_kernel(
    const float* __restrict__ kv, const float* __restrict__ wk,
    __nv_bfloat16* __restrict__ kh, __nv_bfloat16* __restrict__ kl,
    __nv_bfloat16* __restrict__ vh, __nv_bfloat16* __restrict__ vl)
{
    int row  = blockIdx.x * 8 + (threadIdx.x >> 5);  // (b*CLEN + l)*NKVH + kvh
    int lane = threadIdx.x & 31;
    int kvh  = row & 3;
    int bl_  = row >> 2;
    int b    = bl_ >> 11;
    int l    = bl_ & 2047;

    const float* base = kv + (size_t)row * 256;
    float4 f0 = *(const float4*)(base + lane * 8);
    float4 f1 = *(const float4*)(base + lane * 8 + 4);
    float k0 = f0.x, k1 = f0.z, k2 = f1.x, k3 = f1.z;
    float v0 = f0.y, v1 = f0.w, v2 = f1.y, v3 = f1.w;

    float ss = k0 * k0 + k1 * k1 + k2 * k2 + k3 * k3;
#pragma unroll
    for (int o = 16; o > 0; o >>= 1) ss += __shfl_xor_sync(0xffffffffu, ss, o);
    float r = rsqrtf(ss * (1.f / 128.f) + EPSF);

    int d0 = lane * 4;
    float4 wv = *(const float4*)(wk + d0);
    float kk0 = k0 * r * wv.x, kk1 = k1 * r * wv.y;
    float kk2 = k2 * r * wv.z, kk3 = k3 * r * wv.w;

    size_t ob = ((size_t)(b * NKVH + kvh) * CLEN + l) * HD + d0;
    __nv_bfloat16 h0 = __float2bfloat16(kk0), h1 = __float2bfloat16(kk1);
    __nv_bfloat16 h2 = __float2bfloat16(kk2), h3 = __float2bfloat16(kk3);
    *(__nv_bfloat162*)(kh + ob)     = __nv_bfloat162(h0, h1);
    *(__nv_bfloat162*)(kh + ob + 2) = __nv_bfloat162(h2, h3);
    *(__nv_bfloat162*)(kl + ob) = __nv_bfloat162(
        __float2bfloat16(kk0 - __bfloat162float(h0)), __float2bfloat16(kk1 - __bfloat162float(h1)));
    *(__nv_bfloat162*)(kl + ob + 2) = __nv_bfloat162(
        __float2bfloat16(kk2 - __bfloat162float(h2)), __float2bfloat16(kk3 - __bfloat162float(h3)));

    __nv_bfloat16 g0 = __float2bfloat16(v0), g1 = __float2bfloat16(v1);
    __nv_bfloat16 g2 = __float2bfloat16(v2), g3 = __float2bfloat16(v3);
    *(__nv_bfloat162*)(vh + ob)     = __nv_bfloat162(g0, g1);
    *(__nv_bfloat162*)(vh + ob + 2) = __nv_bfloat162(g2, g3);
    *(__nv_bfloat162*)(vl + ob) = __nv_bfloat162(
        __float2bfloat16(v0 - __bfloat162float(g0)), __float2bfloat16(v1 - __bfloat162float(g1)));
    *(__nv_bfloat162*)(vl + ob + 2) = __nv_bfloat162(
        __float2bfloat16(v2 - __bfloat162float(g2)), __float2bfloat16(v3 - __bfloat162float(g3)));
}

// ---------------- HMMA flash attention: BQ=128, BK=64 ----------------------
#define QPITCH  272
#define QBYTES  (128 * QPITCH)      // 34816
#define KVTILEB (64 * QPITCH)       // 17408
#define KVSTAGE (4 * KVTILEB)       // 69632
#define ATTN_SMEM (2 * QBYTES + 2 * KVSTAGE)   // 208896

__global__ __launch_bounds__(256, 1) void attn_hmma_kernel(
    const __nv_bfloat16* __restrict__ qh, const __nv_bfloat16* __restrict__ ql,
    const __nv_bfloat16* __restrict__ kh, const __nv_bfloat16* __restrict__ kl,
    const __nv_bfloat16* __restrict__ vh, const __nv_bfloat16* __restrict__ vl,
    __nv_bfloat16* __restrict__ oh, __nv_bfloat16* __restrict__ ol)
{
    extern __shared__ char smc[];
    const uint32_t sb = smem_u32(smc);

    const int tid  = threadIdx.x;
    const int lane = tid & 31;
    const int wid  = tid >> 5;
    const int h    = blockIdx.y;
    const int b    = blockIdx.z;
    const int kvh  = h >> 2;
    const int s0   = blockIdx.x * 128;

    const __nv_bfloat16* qgh = qh + ((size_t)(b * SEQ + s0) * NH + h) * HD;
    const __nv_bfloat16* qgl = ql + ((size_t)(b * SEQ + s0) * NH + h) * HD;
    const size_t kvbase = (size_t)(b * NKVH + kvh) * CLEN * HD;

    // --- load Q tiles (resident) ---
    {
        int chunk = tid & 15, r0 = tid >> 4;
#pragma unroll
        for (int it = 0; it < 8; ++it) {
            int row = r0 + it * 16;
            uint32_t d = sb + row * QPITCH + chunk * 16;
            size_t g = (size_t)row * HIDDIM + chunk * 8;
            cpa16(d,          qgh + g);
            cpa16(d + QBYTES, qgl + g);
        }
        CP_COMMIT();
    }

    auto loadKV = [&](int blk, int stage) {
        uint32_t st = sb + 2 * QBYTES + stage * KVSTAGE;
        const __nv_bfloat16* pk = kh + kvbase + (size_t)blk * 64 * HD;
        const __nv_bfloat16* pkl = kl + kvbase + (size_t)blk * 64 * HD;
        const __nv_bfloat16* pv = vh + kvbase + (size_t)blk * 64 * HD;
        const __nv_bfloat16* pvl = vl + kvbase + (size_t)blk * 64 * HD;
        int chunk = tid & 15, r0 = tid >> 4;
#pragma unroll
        for (int it = 0; it < 4; ++it) {
            int row = r0 + it * 16;
            uint32_t d = st + row * QPITCH + chunk * 16;
            size_t g = (size_t)row * HD + chunk * 8;
            cpa16(d,               pk + g);
            cpa16(d + KVTILEB,     pkl + g);
            cpa16(d + 2 * KVTILEB, pv + g);
            cpa16(d + 3 * KVTILEB, pvl + g);
        }
        CP_COMMIT();
    };
    loadKV(0, 0);

    float m0 = -1e30f, m1 = -1e30f, l0 = 0.f, l1 = 0.f;
    float ofr[16][4];
#pragma unroll
    for (int f = 0; f < 16; ++f)
#pragma unroll
        for (int r = 0; r < 4; ++r) ofr[f][r] = 0.f;

    const uint32_t laneOff = (lane & 15) * QPITCH + (lane >> 4) * 16;
    const uint32_t qBaseH = sb + (wid * 16) * QPITCH + laneOff;
    const uint32_t qBaseL = qBaseH + QBYTES;

    for (int blk = 0; blk < 32; ++blk) {
        int stage = blk & 1;
        if (blk < 31) loadKV(blk + 1, stage ^ 1);
        if (blk < 31) asm volatile("cp.async.wait_group 1;" ::: "memory");
        else          asm volatile("cp.async.wait_group 0;" ::: "memory");
        __syncthreads();

        uint32_t st = sb + 2 * QBYTES + stage * KVSTAGE;
        uint32_t kBase = st + laneOff;
        uint32_t vBase = st + 2 * KVTILEB + laneOff;

        // ---- S = Q K^T (split: qh*kh + qh*kl + ql*kh) ----
        float sc[8][4];
#pragma unroll
        for (int j = 0; j < 8; ++j)
#pragma unroll
            for (int r = 0; r < 4; ++r) sc[j][r] = 0.f;

#pragma unroll
        for (int kc = 0; kc < 8; ++kc) {
            uint32_t qa[4], qla[4];
            ldsm4(qa[0], qa[1], qa[2], qa[3], qBaseH + kc * 32);
            ldsm4(qla[0], qla[1], qla[2], qla[3], qBaseL + kc * 32);
#pragma unroll
            for (int kg = 0; kg < 4; ++kg) {
                uint32_t kb[4], klb[4];
                ldsm4(kb[0], kb[1], kb[2], kb[3],
                      kBase + kg * 16 * QPITCH + kc * 32);
                ldsm4(klb[0], klb[1], klb[2], klb[3],
                      kBase + KVTILEB + kg * 16 * QPITCH + kc * 32);
                mma16816(sc[kg * 2],     qa,  kb[0],  kb[2]);
                mma16816(sc[kg * 2 + 1], qa,  kb[1],  kb[3]);
                mma16816(sc[kg * 2],     qa,  klb[0], klb[2]);
                mma16816(sc[kg * 2 + 1], qa,  klb[1], klb[3]);
                mma16816(sc[kg * 2],     qla, kb[0],  kb[2]);
                mma16816(sc[kg * 2 + 1], qla, kb[1],  kb[3]);
            }
        }

        // ---- online softmax ----
        float mx0 = -1e30f, mx1 = -1e30f;
#pragma unroll
        for (int j = 0; j < 8; ++j) {
            sc[j][0] *= SCALEF; sc[j][1] *= SCALEF;
            sc[j][2] *= SCALEF; sc[j][3] *= SCALEF;
            mx0 = fmaxf(mx0, fmaxf(sc[j][0], sc[j][1]));
            mx1 = fmaxf(mx1, fmaxf(sc[j][2], sc[j][3]));
        }
        mx0 = fmaxf(mx0, __shfl_xor_sync(0xffffffffu, mx0, 1));
        mx0 = fmaxf(mx0, __shfl_xor_sync(0xffffffffu, mx0, 2));
        mx1 = fmaxf(mx1, __shfl_xor_sync(0xffffffffu, mx1, 1));
        mx1 = fmaxf(mx1, __shfl_xor_sync(0xffffffffu, mx1, 2));
        float m0n = fmaxf(m0, mx0), m1n = fmaxf(m1, mx1);
        float c0 = __expf(m0 - m0n), c1 = __expf(m1 - m1n);
        m0 = m0n; m1 = m1n;

        float rs0 = 0.f, rs1 = 0.f;
#pragma unroll
        for (int j = 0; j < 8; ++j) {
            sc[j][0] = __expf(sc[j][0] - m0); rs0 += sc[j][0];
            sc[j][1] = __expf(sc[j][1] - m0); rs0 += sc[j][1];
            sc[j][2] = __expf(sc[j][2] - m1); rs1 += sc[j][2];
            sc[j][3] = __expf(sc[j][3] - m1); rs1 += sc[j][3];
        }
        rs0 += __shfl_xor_sync(0xffffffffu, rs0, 1);
        rs0 += __shfl_xor_sync(0xffffffffu, rs0, 2);
        rs1 += __shfl_xor_sync(0xffffffffu, rs1, 1);
        rs1 += __shfl_xor_sync(0xffffffffu, rs1, 2);
        l0 = l0 * c0 + rs0;
        l1 = l1 * c1 + rs1;

#pragma unroll
        for (int f = 0; f < 16; ++f) {
            ofr[f][0] *= c0; ofr[f][1] *= c0;
            ofr[f][2] *= c1; ofr[f][3] *= c1;
        }

        // ---- P fragments in registers (hi + lo split) ----
        uint32_t pha[4][4], pla[4][4];
#pragma unroll
        for (int kc = 0; kc < 4; ++kc) {
#pragma unroll
            for (int half = 0; half < 2; ++half) {   // half0: S[2kc], half1: S[2kc+1]
                float e0 = sc[2 * kc + half][0], e1 = sc[2 * kc + half][1];
                float e2 = sc[2 * kc + half][2], e3 = sc[2 * kc + half][3];
                __nv_bfloat16 h0 = __float2bfloat16(e0), h1 = __float2bfloat16(e1);
                __nv_bfloat16 h2 = __float2bfloat16(e2), h3 = __float2bfloat16(e3);
                pha[kc][half * 2]     = pack_bf2(__bfloat162float(h0), 0.f);
                // build packed regs properly below
                __nv_bfloat162 H01 = __halves2bfloat162(h0, h1);
                __nv_bfloat162 H23 = __halves2bfloat162(h2, h3);
                pha[kc][half * 2]     = *(uint32_t*)&H01;
                pha[kc][half * 2 + 1] = *(uint32_t*)&H23;
                __nv_bfloat162 L01 = __halves2bfloat162(
                    __float2bfloat16(e0 - __bfloat162float(h0)),
                    __float2bfloat16(e1 - __bfloat162float(h1)));
                __nv_bfloat162 L23 = __halves2bfloat162(
                    __float2bfloat16(e2 - __bfloat162float(h2)),
                    __float2bfloat16(e3 - __bfloat162float(h3)));
                pla[kc][half * 2]     = *(uint32_t*)&L01;
                pla[kc][half * 2 + 1] = *(uint32_t*)&L23;
            }
        }
        // A-frag order: a0=S[2kc]c01, a1=S[2kc]c23, a2=S[2kc+1]c01, a3=S[2kc+1]c23
        // (half*2 mapping above gives exactly that: half0->a0,a1 half1->a2,a3)

        // ---- O += P V (split: ph*vh + ph*vl + pl*vh) ----
#pragma unroll
        for (int dg = 0; dg < 8; ++dg) {
#pragma unroll
            for (int kc = 0; kc < 4; ++kc) {
                uint32_t vb[4], vlb[4];
                ldsm4t(vb[0], vb[1], vb[2], vb[3],
                       vBase + kc * 16 * QPITCH + dg * 32);
                ldsm4t(vlb[0], vlb[1], vlb[2], vlb[3],
                       vBase + KVTILEB + kc * 16 * QPITCH + dg * 32);
                mma16816(ofr[dg * 2],     pha[kc], vb[0],  vb[1]);
                mma16816(ofr[dg * 2 + 1], pha[kc], vb[2],  vb[3]);
                mma16816(ofr[dg * 2],     pha[kc], vlb[0], vlb[1]);
                mma16816(ofr[dg * 2 + 1], pha[kc], vlb[2], vlb[3]);
                mma16816(ofr[dg * 2],     pla[kc], vb[0],  vb[1]);
                mma16816(ofr[dg * 2 + 1], pla[kc], vb[2],  vb[3]);
            }
        }
        __syncthreads();
    }

    // ---- epilogue: normalize, split to bf16 hi/lo, store ----
    float inv0 = 1.f / l0, inv1 = 1.f / l1;
    int rowA = b * SEQ + s0 + wid * 16 + (lane >> 2);
    int colB = h * HD + (lane & 3) * 2;
#pragma unroll
    for (int f = 0; f < 16; ++f) {
        int col = colB + f * 8;
        float v0 = ofr[f][0] * inv0, v1 = ofr[f][1] * inv0;
        float v2 = ofr[f][2] * inv1, v3 = ofr[f][3] * inv1;
        __nv_bfloat16 h0 = __float2bfloat16(v0), h1 = __float2bfloat16(v1);
        __nv_bfloat16 h2 = __float2bfloat16(v2), h3 = __float2bfloat16(v3);
        *(__nv_bfloat162*)(oh + (size_t)rowA * HIDDIM + col) = __nv_bfloat162(h0, h1);
        *(__nv_bfloat162*)(oh + (size_t)(rowA + 8) * HIDDIM + col) = __nv_bfloat162(h2, h3);
        *(__nv_bfloat162*)(ol + (size_t)rowA * HIDDIM + col) = __nv_bfloat162(
            __float2bfloat16(v0 - __bfloat162float(h0)),
            __float2bfloat16(v1 - __bfloat162float(h1)));
        *(__nv_bfloat162*)(ol + (size_t)(rowA + 8) * HIDDIM + col) = __nv_bfloat162(
            __float2bfloat16(v2 - __bfloat162float(h2)),
            __float2bfloat16(v3 - __bfloat162float(h3)));
    }
}

// ---------------- launch ----------------------------------------------------
extern "C" void kernel_launch(void* const* d_in, const int* in_sizes, int n_in,
                              void* d_out, int out_size)
{
    (void)in_sizes; (void)n_in; (void)out_size;
    const float* x   = (const float*)d_in[0];
    const float* c   = (const float*)d_in[1];
    const float* wq  = (const float*)d_in[2];
    const float* wkv = (const float*)d_in[3];
    const float* wo  = (const float*)d_in[4];
    const float* nqw = (const float*)d_in[5];
    const float* nkw = (const float*)d_in[6];
    float* out = (float*)d_out;

    float *q, *kv;
    __nv_bfloat16 *qh, *qlp, *kh, *kl, *vh, *vl, *ah, *al, *bh, *bl;
    cudaGetSymbolAddress((void**)&q,   g_q);
    cudaGetSymbolAddress((void**)&kv,  g_kv);
    cudaGetSymbolAddress((void**)&qh,  g_qh);
    cudaGetSymbolAddress((void**)&qlp, g_ql);
    cudaGetSymbolAddress((void**)&kh,  g_kh);
    cudaGetSymbolAddress((void**)&kl,  g_kl);
    cudaGetSymbolAddress((void**)&vh,  g_vh);
    cudaGetSymbolAddress((void**)&vl,  g_vl);
    cudaGetSymbolAddress((void**)&ah,  g_ah);
    cudaGetSymbolAddress((void**)&al,  g_al);
    cudaGetSymbolAddress((void**)&bh,  g_bh);
    cudaGetSymbolAddress((void**)&bl,  g_bl);

    const int M = BATCH * SEQ;            // 4096
    const int K = HIDDIM;                 // 2048
    const int gemm_smem = NSTAGE * STAGEB;
    cudaFuncSetAttribute(gemm_hmma_kernel,
                         cudaFuncAttributeMaxDynamicSharedMemorySize, gemm_smem);
    cudaFuncSetAttribute(attn_hmma_kernel,
                         cudaFuncAttributeMaxDynamicSharedMemorySize, ATTN_SMEM);

    int convA_grid = (M * K) / 4 / 256;

    // 1) Q projection
    convA_kernel<<<convA_grid, 256>>>((const float4*)x, ah, al);
    convWT_kernel<<<dim3(HIDDIM / 32, K / 32), 256>>>(wq, bh, bl, K, HIDDIM);
    gemm_hmma_kernel<<<dim3(HIDDIM / 128, M / 128), 256, gemm_smem>>>(
        ah, al, bh, bl, q, M, HIDDIM, K);

    // 2) Q rmsnorm -> bf16 split
    rmsnorm_q_kernel<<<(M * NH) / 8, 256>>>(q, nqw, qh, qlp);

    // 3) KV projection
    convA_kernel<<<convA_grid, 256>>>((const float4*)c, ah, al);
    convWT_kernel<<<dim3((NKVH * HD * 2) / 32, K / 32), 256>>>(wkv, bh, bl, K, NKVH * HD * 2);
    gemm_hmma_kernel<<<dim3((NKVH * HD * 2) / 128, M / 128), 256, gemm_smem>>>(
        ah, al, bh, bl, kv, M, NKVH * HD * 2, K);

    // 4) split KV -> bf16 splits
    kvsplit_kernel<<<(BATCH * CLEN * NKVH) / 8, 256>>>(kv, nkw, kh, kl, vh, vl);

    // 5) HMMA attention -> writes bf16 split activations for out-proj
    attn_hmma_kernel<<<dim3(SEQ / 128, NH, BATCH), 256, ATTN_SMEM>>>(
        qh, qlp, kh, kl, vh, vl, ah, al);

    // 6) output projection
    convWT_kernel<<<dim3(HIDDIM / 32, K / 32), 256>>>(wo, bh, bl, K, HIDDIM);
    gemm_hmma_kernel<<<dim3(HIDDIM / 128, M / 128), 256, gemm_smem>>>(
        ah, al, bh, bl, out, M, HIDDIM, K);
}

// round 5
// speedup vs baseline: 2.3237x; 1.0071x over previous
#include <cuda_runtime.h>
#include <cuda_bf16.h>
#include <math.h>
#include <stdint.h>

#define BATCH 2
#define SEQ   2048
#define CLEN  2048
#define NH    16
#define NKVH  4
#define HD    128
#define HIDDIM 2048
#define EPSF  1e-6f
#define SCALEF 0.08838834764831845f   // 1/sqrt(128)

// ---------------- scratch (device globals) ---------------------------------
__device__ float g_q [BATCH*SEQ*HIDDIM];          // fp32 Q proj out
__device__ float g_kv[BATCH*CLEN*NKVH*HD*2];      // fp32 KV proj out

__device__ __nv_bfloat16 g_qh[BATCH*SEQ*HIDDIM];  // Q post-rmsnorm split
__device__ __nv_bfloat16 g_ql[BATCH*SEQ*HIDDIM];
__device__ __nv_bfloat16 g_kh[BATCH*NKVH*CLEN*HD];
__device__ __nv_bfloat16 g_kl[BATCH*NKVH*CLEN*HD];
__device__ __nv_bfloat16 g_vh[BATCH*NKVH*CLEN*HD];
__device__ __nv_bfloat16 g_vl[BATCH*NKVH*CLEN*HD];

__device__ __nv_bfloat16 g_ah[BATCH*SEQ*HIDDIM];  // GEMM activation hi/lo
__device__ __nv_bfloat16 g_al[BATCH*SEQ*HIDDIM];
__device__ __nv_bfloat16 g_bh[HIDDIM*HIDDIM];     // weight^T hi/lo
__device__ __nv_bfloat16 g_bl[HIDDIM*HIDDIM];

// ======================= family-common tensor helpers ======================
__device__ __forceinline__ uint32_t smem_u32(const void* p) {
    uint32_t a;
    asm("{ .reg .u64 t; cvta.to.shared.u64 t, %1; cvt.u32.u64 %0, t; }" : "=r"(a) : "l"(p));
    return a;
}
__device__ __forceinline__ void cpa16(uint32_t d, const void* g) {
    asm volatile("cp.async.cg.shared.global [%0], [%1], 16;" :: "r"(d), "l"(g) : "memory");
}
#define CP_COMMIT() asm volatile("cp.async.commit_group;" ::: "memory")

__device__ __forceinline__ void ldsm4(uint32_t& r0, uint32_t& r1, uint32_t& r2, uint32_t& r3,
                                      uint32_t a) {
    asm volatile("ldmatrix.sync.aligned.m8n8.x4.shared.b16 {%0,%1,%2,%3}, [%4];"
                 : "=r"(r0), "=r"(r1), "=r"(r2), "=r"(r3) : "r"(a));
}
__device__ __forceinline__ void ldsm4t(uint32_t& r0, uint32_t& r1, uint32_t& r2, uint32_t& r3,
                                       uint32_t a) {
    asm volatile("ldmatrix.sync.aligned.m8n8.x4.trans.shared.b16 {%0,%1,%2,%3}, [%4];"
                 : "=r"(r0), "=r"(r1), "=r"(r2), "=r"(r3) : "r"(a));
}
__device__ __forceinline__ void mma16816(float* c, const uint32_t* a, uint32_t b0, uint32_t b1) {
    asm volatile(
        "mma.sync.aligned.m16n8k16.row.col.f32.bf16.bf16.f32 "
        "{%0,%1,%2,%3}, {%4,%5,%6,%7}, {%8,%9}, {%0,%1,%2,%3};"
        : "+f"(c[0]), "+f"(c[1]), "+f"(c[2]), "+f"(c[3])
        : "r"(a[0]), "r"(a[1]), "r"(a[2]), "r"(a[3]), "r"(b0), "r"(b1));
}

// ---------------- split-bf16 conversion kernels ----------------------------
__global__ __launch_bounds__(256) void convA_kernel(
    const float4* __restrict__ in, __nv_bfloat16* __restrict__ hi,
    __nv_bfloat16* __restrict__ lo)
{
    size_t i = (size_t)blockIdx.x * 256 + threadIdx.x;
    float4 v = in[i];
    __nv_bfloat16 h0 = __float2bfloat16(v.x), h1 = __float2bfloat16(v.y);
    __nv_bfloat16 h2 = __float2bfloat16(v.z), h3 = __float2bfloat16(v.w);
    __nv_bfloat16 l0 = __float2bfloat16(v.x - __bfloat162float(h0));
    __nv_bfloat16 l1 = __float2bfloat16(v.y - __bfloat162float(h1));
    __nv_bfloat16 l2 = __float2bfloat16(v.z - __bfloat162float(h2));
    __nv_bfloat16 l3 = __float2bfloat16(v.w - __bfloat162float(h3));
    ((__nv_bfloat162*)hi)[i * 2]     = __nv_bfloat162(h0, h1);
    ((__nv_bfloat162*)hi)[i * 2 + 1] = __nv_bfloat162(h2, h3);
    ((__nv_bfloat162*)lo)[i * 2]     = __nv_bfloat162(l0, l1);
    ((__nv_bfloat162*)lo)[i * 2 + 1] = __nv_bfloat162(l2, l3);
}

__global__ __launch_bounds__(256) void convWT_kernel(
    const float* __restrict__ w, __nv_bfloat16* __restrict__ th,
    __nv_bfloat16* __restrict__ tl, int K, int N)
{
    __shared__ float s[32][33];
    int n0 = blockIdx.x * 32, k0 = blockIdx.y * 32;
    int tx = threadIdx.x & 31, ty = threadIdx.x >> 5;
#pragma unroll
    for (int i = ty; i < 32; i += 8)
        s[i][tx] = w[(size_t)(k0 + i) * N + n0 + tx];
    __syncthreads();
#pragma unroll
    for (int j = ty; j < 32; j += 8) {
        float v = s[tx][j];
        __nv_bfloat16 h = __float2bfloat16(v);
        __nv_bfloat16 l = __float2bfloat16(v - __bfloat162float(h));
        size_t idx = (size_t)(n0 + j) * K + k0 + tx;
        th[idx] = h;
        tl[idx] = l;
    }
}

// ---------------- HMMA split-bf16 GEMM v2: CTA 128x256, warp 64x64 ---------
#define TP2  80
#define A_T  (128 * TP2)             // 10240
#define B_T  (256 * TP2)             // 20480
#define STB  (2 * A_T + 2 * B_T)     // 61440
#define NST2 3                       // 184320 B smem

__global__ __launch_bounds__(256, 1) void gemm_hmma_kernel(
    const __nv_bfloat16* __restrict__ Ah, const __nv_bfloat16* __restrict__ Al,
    const __nv_bfloat16* __restrict__ Bh, const __nv_bfloat16* __restrict__ Bl,
    float* __restrict__ C, int M, int N, int K)
{
    extern __shared__ char smc[];
    const uint32_t sb = smem_u32(smc);

    const int tid  = threadIdx.x;
    const int lane = tid & 31;
    const int wid  = tid >> 5;
    const int wm   = wid & 1;          // 2 warps along M (64 each)
    const int wn   = wid >> 1;         // 4 warps along N (64 each)
    const int bm   = blockIdx.y * 128;
    const int bn   = blockIdx.x * 256;

    // loaders: A (128 rows x 32 bf16): thread -> row tid>>1, 32B half (tid&1)
    const int arow = tid >> 1;
    const int ahalf = tid & 1;
    const size_t gA = (size_t)(bm + arow) * K + ahalf * 16;
    const uint32_t sA = arow * TP2 + ahalf * 32;
    // B (256 rows x 32 bf16): thread -> row tid, full 64B
    const size_t gB = (size_t)(bn + tid) * K;
    const uint32_t sB = tid * TP2;

    const uint32_t laneOff = (lane & 15) * TP2 + (lane >> 4) * 16;

    float acc[4][8][4];
#pragma unroll
    for (int i = 0; i < 4; i++)
#pragma unroll
        for (int j = 0; j < 8; j++)
#pragma unroll
            for (int r = 0; r < 4; r++) acc[i][j][r] = 0.f;

    const int nst = K / 32;

    auto loadStage = [&](int s, int buf) {
        uint32_t st = sb + buf * STB;
        int k0 = s * 32;
        cpa16(st + sA,            Ah + gA + k0);
        cpa16(st + sA + 16,       Ah + gA + k0 + 8);
        cpa16(st + A_T + sA,      Al + gA + k0);
        cpa16(st + A_T + sA + 16, Al + gA + k0 + 8);
        uint32_t bb = st + 2 * A_T + sB;
        cpa16(bb,      Bh + gB + k0);
        cpa16(bb + 16, Bh + gB + k0 + 8);
        cpa16(bb + 32, Bh + gB + k0 + 16);
        cpa16(bb + 48, Bh + gB + k0 + 24);
        bb += B_T;
        cpa16(bb,      Bl + gB + k0);
        cpa16(bb + 16, Bl + gB + k0 + 8);
        cpa16(bb + 32, Bl + gB + k0 + 16);
        cpa16(bb + 48, Bl + gB + k0 + 24);
        CP_COMMIT();
    };

    loadStage(0, 0);
    loadStage(1, 1);

    int buf = 0;
    for (int s = 0; s < nst; ++s) {
        if (s + 1 < nst) asm volatile("cp.async.wait_group 1;" ::: "memory");
        else             asm volatile("cp.async.wait_group 0;" ::: "memory");
        __syncthreads();

        if (s + 2 < nst) loadStage(s + 2, (buf + 2) % NST2);

        uint32_t st = sb + buf * STB;
        uint32_t aBaseH = st + (wm * 64) * TP2 + laneOff;
        uint32_t aBaseL = aBaseH + A_T;
        uint32_t bBaseH = st + 2 * A_T + (wn * 64) * TP2 + laneOff;
        uint32_t bBaseL = bBaseH + B_T;

#pragma unroll
        for (int ks = 0; ks < 2; ++ks) {
            uint32_t ko = ks * 32;
            uint32_t ahf[4][4], alf[4][4];
#pragma unroll
            for (int mi = 0; mi < 4; ++mi) {
                ldsm4(ahf[mi][0], ahf[mi][1], ahf[mi][2], ahf[mi][3],
                      aBaseH + mi * 16 * TP2 + ko);
                ldsm4(alf[mi][0], alf[mi][1], alf[mi][2], alf[mi][3],
                      aBaseL + mi * 16 * TP2 + ko);
            }
#pragma unroll
            for (int bi = 0; bi < 4; ++bi) {
                uint32_t bhf[4], blf[4];
                ldsm4(bhf[0], bhf[1], bhf[2], bhf[3], bBaseH + bi * 16 * TP2 + ko);
                ldsm4(blf[0], blf[1], blf[2], blf[3], bBaseL + bi * 16 * TP2 + ko);
#pragma unroll
                for (int mi = 0; mi < 4; ++mi) {
#pragma unroll
                    for (int sub = 0; sub < 2; ++sub) {
                        int nj = bi * 2 + sub;
                        mma16816(acc[mi][nj], ahf[mi], bhf[sub], bhf[sub + 2]);
                        mma16816(acc[mi][nj], ahf[mi], blf[sub], blf[sub + 2]);
                        mma16816(acc[mi][nj], alf[mi], bhf[sub], bhf[sub + 2]);
                    }
                }
            }
        }
        buf = (buf + 1) % NST2;
        __syncthreads();
    }

    const int g  = lane >> 2;
    const int q4 = lane & 3;
#pragma unroll
    for (int mi = 0; mi < 4; ++mi) {
#pragma unroll
        for (int nj = 0; nj < 8; ++nj) {
            int r0 = bm + wm * 64 + mi * 16 + g;
            int c0 = bn + wn * 64 + nj * 8 + q4 * 2;
            *(float2*)(C + (size_t)r0 * N + c0)       = make_float2(acc[mi][nj][0], acc[mi][nj][1]);
            *(float2*)(C + (size_t)(r0 + 8) * N + c0) = make_float2(acc[mi][nj][2], acc[mi][nj][3]);
        }
    }
}

// ---------------- per-head RMSNorm on Q -> bf16 split -----------------------
__global__ __launch_bounds__(256) void rmsnorm_q_kernel(
    const float* __restrict__ q, const float* __restrict__ w,
    __nv_bfloat16* __restrict__ qh, __nv_bfloat16* __restrict__ ql)
{
    int row  = blockIdx.x * 8 + (threadIdx.x >> 5);
    int lane = threadIdx.x & 31;
    float4 v = *(const float4*)(q + row * HD + lane * 4);
    float ss = v.x * v.x + v.y * v.y + v.z * v.z + v.w * v.w;
#pragma unroll
    for (int o = 16; o > 0; o >>= 1) ss += __shfl_xor_sync(0xffffffffu, ss, o);
    float r = rsqrtf(ss * (1.f / 128.f) + EPSF);
    float4 wv = *(const float4*)(w + lane * 4);
    float f0 = v.x * r * wv.x, f1 = v.y * r * wv.y;
    float f2 = v.z * r * wv.z, f3 = v.w * r * wv.w;
    __nv_bfloat16 h0 = __float2bfloat16(f0), h1 = __float2bfloat16(f1);
    __nv_bfloat16 h2 = __float2bfloat16(f2), h3 = __float2bfloat16(f3);
    size_t base = (size_t)row * HD + lane * 4;
    *(__nv_bfloat162*)(qh + base)     = __nv_bfloat162(h0, h1);
    *(__nv_bfloat162*)(qh + base + 2) = __nv_bfloat162(h2, h3);
    *(__nv_bfloat162*)(ql + base) = __nv_bfloat162(
        __float2bfloat16(f0 - __bfloat162float(h0)), __float2bfloat16(f1 - __bfloat162float(h1)));
    *(__nv_bfloat162*)(ql + base + 2) = __nv_bfloat162(
        __float2bfloat16(f2 - __bfloat162float(h2)), __float2bfloat16(f3 - __bfloat162float(h3)));
}

// ---------------- split packed KV -> rmsnorm K -> bf16 splits ---------------
__global__ __launch_bounds__(256) void kvsplit_kernel(
    const float* __restrict__ kv, const float* __restrict__ wk,
    __nv_bfloat16* __restrict__ kh, __nv_bfloat16* __restrict__ kl,
    __nv_bfloat16* __restrict__ vh, __nv_bfloat16* __restrict__ vl)
{
    int row  = blockIdx.x * 8 + (threadIdx.x >> 5);  // (b*CLEN + l)*NKVH + kvh
    int lane = threadIdx.x & 31;
    int kvh  = row & 3;
    int bl_  = row >> 2;
    int b    = bl_ >> 11;
    int l    = bl_ & 2047;

    const float* base = kv + (size_t)row * 256;
    float4 f0 = *(const float4*)(base + lane * 8);
    float4 f1 = *(const float4*)(base + lane * 8 + 4);
    float k0 = f0.x, k1 = f0.z, k2 = f1.x, k3 = f1.z;
    float v0 = f0.y, v1 = f0.w, v2 = f1.y, v3 = f1.w;

    float ss = k0 * k0 + k1 * k1 + k2 * k2 + k3 * k3;
#pragma unroll
    for (int o = 16; o > 0; o >>= 1) ss += __shfl_xor_sync(0xffffffffu, ss, o);
    float r = rsqrtf(ss * (1.f / 128.f) + EPSF);

    int d0 = lane * 4;
    float4 wv = *(const float4*)(wk + d0);
    float kk0 = k0 * r * wv.x, kk1 = k1 * r * wv.y;
    float kk2 = k2 * r * wv.z, kk3 = k3 * r * wv.w;

    size_t ob = ((size_t)(b * NKVH + kvh) * CLEN + l) * HD + d0;
    __nv_bfloat16 h0 = __float2bfloat16(kk0), h1 = __float2bfloat16(kk1);
    __nv_bfloat16 h2 = __float2bfloat16(kk2), h3 = __float2bfloat16(kk3);
    *(__nv_bfloat162*)(kh + ob)     = __nv_bfloat162(h0, h1);
    *(__nv_bfloat162*)(kh + ob + 2) = __nv_bfloat162(h2, h3);
    *(__nv_bfloat162*)(kl + ob) = __nv_bfloat162(
        __float2bfloat16(kk0 - __bfloat162float(h0)), __float2bfloat16(kk1 - __bfloat162float(h1)));
    *(__nv_bfloat162*)(kl + ob + 2) = __nv_bfloat162(
        __float2bfloat16(kk2 - __bfloat162float(h2)), __float2bfloat16(kk3 - __bfloat162float(h3)));

    __nv_bfloat16 g0 = __float2bfloat16(v0), g1 = __float2bfloat16(v1);
    __nv_bfloat16 g2 = __float2bfloat16(v2), g3 = __float2bfloat16(v3);
    *(__nv_bfloat162*)(vh + ob)     = __nv_bfloat162(g0, g1);
    *(__nv_bfloat162*)(vh + ob + 2) = __nv_bfloat162(g2, g3);
    *(__nv_bfloat162*)(vl + ob) = __nv_bfloat162(
        __float2bfloat16(v0 - __bfloat162float(g0)), __float2bfloat16(v1 - __bfloat162float(g1)));
    *(__nv_bfloat162*)(vl + ob + 2) = __nv_bfloat162(
        __float2bfloat16(v2 - __bfloat162float(g2)), __float2bfloat16(v3 - __bfloat162float(g3)));
}

// ---------------- HMMA flash attention: BQ=128, BK=64 ----------------------
#define QPITCH  272
#define QBYTES  (128 * QPITCH)      // 34816
#define KVTILEB (64 * QPITCH)       // 17408
#define KVSTAGE (4 * KVTILEB)       // 69632
#define ATTN_SMEM (2 * QBYTES + 2 * KVSTAGE)   // 208896

__global__ __launch_bounds__(256, 1) void attn_hmma_kernel(
    const __nv_bfloat16* __restrict__ qh, const __nv_bfloat16* __restrict__ ql,
    const __nv_bfloat16* __restrict__ kh, const __nv_bfloat16* __restrict__ kl,
    const __nv_bfloat16* __restrict__ vh, const __nv_bfloat16* __restrict__ vl,
    __nv_bfloat16* __restrict__ oh, __nv_bfloat16* __restrict__ ol)
{
    extern __shared__ char smc[];
    const uint32_t sb = smem_u32(smc);

    const int tid  = threadIdx.x;
    const int lane = tid & 31;
    const int wid  = tid >> 5;
    const int h    = blockIdx.y;
    const int b    = blockIdx.z;
    const int kvh  = h >> 2;
    const int s0   = blockIdx.x * 128;

    const __nv_bfloat16* qgh = qh + ((size_t)(b * SEQ + s0) * NH + h) * HD;
    const __nv_bfloat16* qgl = ql + ((size_t)(b * SEQ + s0) * NH + h) * HD;
    const size_t kvbase = (size_t)(b * NKVH + kvh) * CLEN * HD;

    {
        int chunk = tid & 15, r0 = tid >> 4;
#pragma unroll
        for (int it = 0; it < 8; ++it) {
            int row = r0 + it * 16;
            uint32_t d = sb + row * QPITCH + chunk * 16;
            size_t g = (size_t)row * HIDDIM + chunk * 8;
            cpa16(d,          qgh + g);
            cpa16(d + QBYTES, qgl + g);
        }
        CP_COMMIT();
    }

    auto loadKV = [&](int blk, int stage) {
        uint32_t st = sb + 2 * QBYTES + stage * KVSTAGE;
        const __nv_bfloat16* pk  = kh + kvbase + (size_t)blk * 64 * HD;
        const __nv_bfloat16* pkl = kl + kvbase + (size_t)blk * 64 * HD;
        const __nv_bfloat16* pv  = vh + kvbase + (size_t)blk * 64 * HD;
        const __nv_bfloat16* pvl = vl + kvbase + (size_t)blk * 64 * HD;
        int chunk = tid & 15, r0 = tid >> 4;
#pragma unroll
        for (int it = 0; it < 4; ++it) {
            int row = r0 + it * 16;
            uint32_t d = st + row * QPITCH + chunk * 16;
            size_t g = (size_t)row * HD + chunk * 8;
            cpa16(d,               pk + g);
            cpa16(d + KVTILEB,     pkl + g);
            cpa16(d + 2 * KVTILEB, pv + g);
            cpa16(d + 3 * KVTILEB, pvl + g);
        }
        CP_COMMIT();
    };
    loadKV(0, 0);

    float m0 = -1e30f, m1 = -1e30f, l0 = 0.f, l1 = 0.f;
    float ofr[16][4];
#pragma unroll
    for (int f = 0; f < 16; ++f)
#pragma unroll
        for (int r = 0; r < 4; ++r) ofr[f][r] = 0.f;

    const uint32_t laneOff = (lane & 15) * QPITCH + (lane >> 4) * 16;
    const uint32_t qBaseH = sb + (wid * 16) * QPITCH + laneOff;
    const uint32_t qBaseL = qBaseH + QBYTES;

    for (int blk = 0; blk < 32; ++blk) {
        int stage = blk & 1;
        if (blk < 31) loadKV(blk + 1, stage ^ 1);
        if (blk < 31) asm volatile("cp.async.wait_group 1;" ::: "memory");
        else          asm volatile("cp.async.wait_group 0;" ::: "memory");
        __syncthreads();

        uint32_t st = sb + 2 * QBYTES + stage * KVSTAGE;
        uint32_t kBase = st + laneOff;
        uint32_t vBase = st + 2 * KVTILEB + laneOff;

        float sc[8][4];
#pragma unroll
        for (int j = 0; j < 8; ++j)
#pragma unroll
            for (int r = 0; r < 4; ++r) sc[j][r] = 0.f;

#pragma unroll
        for (int kc = 0; kc < 8; ++kc) {
            uint32_t qa[4], qla[4];
            ldsm4(qa[0], qa[1], qa[2], qa[3], qBaseH + kc * 32);
            ldsm4(qla[0], qla[1], qla[2], qla[3], qBaseL + kc * 32);
#pragma unroll
            for (int kg = 0; kg < 4; ++kg) {
                uint32_t kb[4], klb[4];
                ldsm4(kb[0], kb[1], kb[2], kb[3],
                      kBase + kg * 16 * QPITCH + kc * 32);
                ldsm4(klb[0], klb[1], klb[2], klb[3],
                      kBase + KVTILEB + kg * 16 * QPITCH + kc * 32);
                mma16816(sc[kg * 2],     qa,  kb[0],  kb[2]);
                mma16816(sc[kg * 2 + 1], qa,  kb[1],  kb[3]);
                mma16816(sc[kg * 2],     qa,  klb[0], klb[2]);
                mma16816(sc[kg * 2 + 1], qa,  klb[1], klb[3]);
                mma16816(sc[kg * 2],     qla, kb[0],  kb[2]);
                mma16816(sc[kg * 2 + 1], qla, kb[1],  kb[3]);
            }
        }

        float mx0 = -1e30f, mx1 = -1e30f;
#pragma unroll
        for (int j = 0; j < 8; ++j) {
            sc[j][0] *= SCALEF; sc[j][1] *= SCALEF;
            sc[j][2] *= SCALEF; sc[j][3] *= SCALEF;
            mx0 = fmaxf(mx0, fmaxf(sc[j][0], sc[j][1]));
            mx1 = fmaxf(mx1, fmaxf(sc[j][2], sc[j][3]));
        }
        mx0 = fmaxf(mx0, __shfl_xor_sync(0xffffffffu, mx0, 1));
        mx0 = fmaxf(mx0, __shfl_xor_sync(0xffffffffu, mx0, 2));
        mx1 = fmaxf(mx1, __shfl_xor_sync(0xffffffffu, mx1, 1));
        mx1 = fmaxf(mx1, __shfl_xor_sync(0xffffffffu, mx1, 2));
        float m0n = fmaxf(m0, mx0), m1n = fmaxf(m1, mx1);
        float c0 = __expf(m0 - m0n), c1 = __expf(m1 - m1n);
        m0 = m0n; m1 = m1n;

        float rs0 = 0.f, rs1 = 0.f;
#pragma unroll
        for (int j = 0; j < 8; ++j) {
            sc[j][0] = __expf(sc[j][0] - m0); rs0 += sc[j][0];
            sc[j][1] = __expf(sc[j][1] - m0); rs0 += sc[j][1];
            sc[j][2] = __expf(sc[j][2] - m1); rs1 += sc[j][2];
            sc[j][3] = __expf(sc[j][3] - m1); rs1 += sc[j][3];
        }
        rs0 += __shfl_xor_sync(0xffffffffu, rs0, 1);
        rs0 += __shfl_xor_sync(0xffffffffu, rs0, 2);
        rs1 += __shfl_xor_sync(0xffffffffu, rs1, 1);
        rs1 += __shfl_xor_sync(0xffffffffu, rs1, 2);
        l0 = l0 * c0 + rs0;
        l1 = l1 * c1 + rs1;

#pragma unroll
        for (int f = 0; f < 16; ++f) {
            ofr[f][0] *= c0; ofr[f][1] *= c0;
            ofr[f][2] *= c1; ofr[f][3] *= c1;
        }

        uint32_t pha[4][4], pla[4][4];
#pragma unroll
        for (int kc = 0; kc < 4; ++kc) {
#pragma unroll
            for (int half = 0; half < 2; ++half) {
                float e0 = sc[2 * kc + half][0], e1 = sc[2 * kc + half][1];
                float e2 = sc[2 * kc + half][2], e3 = sc[2 * kc + half][3];
                __nv_bfloat16 h0 = __float2bfloat16(e0), h1 = __float2bfloat16(e1);
                __nv_bfloat16 h2 = __float2bfloat16(e2), h3 = __float2bfloat16(e3);
                __nv_bfloat162 H01 = __halves2bfloat162(h0, h1);
                __nv_bfloat162 H23 = __halves2bfloat162(h2, h3);
                pha[kc][half * 2]     = *(uint32_t*)&H01;
                pha[kc][half * 2 + 1] = *(uint32_t*)&H23;
                __nv_bfloat162 L01 = __halves2bfloat162(
                    __float2bfloat16(e0 - __bfloat162float(h0)),
                    __float2bfloat16(e1 - __bfloat162float(h1)));
                __nv_bfloat162 L23 = __halves2bfloat162(
                    __float2bfloat16(e2 - __bfloat162float(h2)),
                    __float2bfloat16(e3 - __bfloat162float(h3)));
                pla[kc][half * 2]     = *(uint32_t*)&L01;
                pla[kc][half * 2 + 1] = *(uint32_t*)&L23;
            }
        }

#pragma unroll
        for (int dg = 0; dg < 8; ++dg) {
#pragma unroll
            for (int kc = 0; kc < 4; ++kc) {
                uint32_t vb[4], vlb[4];
                ldsm4t(vb[0], vb[1], vb[2], vb[3],
                       vBase + kc * 16 * QPITCH + dg * 32);
                ldsm4t(vlb[0], vlb[1], vlb[2], vlb[3],
                       vBase + KVTILEB + kc * 16 * QPITCH + dg * 32);
                mma16816(ofr[dg * 2],     pha[kc], vb[0],  vb[1]);
                mma16816(ofr[dg * 2 + 1], pha[kc], vb[2],  vb[3]);
                mma16816(ofr[dg * 2],     pha[kc], vlb[0], vlb[1]);
                mma16816(ofr[dg * 2 + 1], pha[kc], vlb[2], vlb[3]);
                mma16816(ofr[dg * 2],     pla[kc], vb[0],  vb[1]);
                mma16816(ofr[dg * 2 + 1], pla[kc], vb[2],  vb[3]);
            }
        }
        __syncthreads();
    }

    float inv0 = 1.f / l0, inv1 = 1.f / l1;
    int rowA = b * SEQ + s0 + wid * 16 + (lane >> 2);
    int colB = h * HD + (lane & 3) * 2;
#pragma unroll
    for (int f = 0; f < 16; ++f) {
        int col = colB + f * 8;
        float v0 = ofr[f][0] * inv0, v1 = ofr[f][1] * inv0;
        float v2 = ofr[f][2] * inv1, v3 = ofr[f][3] * inv1;
        __nv_bfloat16 h0 = __float2bfloat16(v0), h1 = __float2bfloat16(v1);
        __nv_bfloat16 h2 = __float2bfloat16(v2), h3 = __float2bfloat16(v3);
        *(__nv_bfloat162*)(oh + (size_t)rowA * HIDDIM + col) = __nv_bfloat162(h0, h1);
        *(__nv_bfloat162*)(oh + (size_t)(rowA + 8) * HIDDIM + col) = __nv_bfloat162(h2, h3);
        *(__nv_bfloat162*)(ol + (size_t)rowA * HIDDIM + col) = __nv_bfloat162(
            __float2bfloat16(v0 - __bfloat162float(h0)),
            __float2bfloat16(v1 - __bfloat162float(h1)));
        *(__nv_bfloat162*)(ol + (size_t)(rowA + 8) * HIDDIM + col) = __nv_bfloat162(
            __float2bfloat16(v2 - __bfloat162float(h2)),
            __float2bfloat16(v3 - __bfloat162float(h3)));
    }
}

// ---------------- launch ----------------------------------------------------
extern "C" void kernel_launch(void* const* d_in, const int* in_sizes, int n_in,
                              void* d_out, int out_size)
{
    (void)in_sizes; (void)n_in; (void)out_size;
    const float* x   = (const float*)d_in[0];
    const float* c   = (const float*)d_in[1];
    const float* wq  = (const float*)d_in[2];
    const float* wkv = (const float*)d_in[3];
    const float* wo  = (const float*)d_in[4];
    const float* nqw = (const float*)d_in[5];
    const float* nkw = (const float*)d_in[6];
    float* out = (float*)d_out;

    float *q, *kv;
    __nv_bfloat16 *qh, *qlp, *kh, *kl, *vh, *vl, *ah, *al, *bh, *bl;
    cudaGetSymbolAddress((void**)&q,   g_q);
    cudaGetSymbolAddress((void**)&kv,  g_kv);
    cudaGetSymbolAddress((void**)&qh,  g_qh);
    cudaGetSymbolAddress((void**)&qlp, g_ql);
    cudaGetSymbolAddress((void**)&kh,  g_kh);
    cudaGetSymbolAddress((void**)&kl,  g_kl);
    cudaGetSymbolAddress((void**)&vh,  g_vh);
    cudaGetSymbolAddress((void**)&vl,  g_vl);
    cudaGetSymbolAddress((void**)&ah,  g_ah);
    cudaGetSymbolAddress((void**)&al,  g_al);
    cudaGetSymbolAddress((void**)&bh,  g_bh);
    cudaGetSymbolAddress((void**)&bl,  g_bl);

    const int M = BATCH * SEQ;            // 4096
    const int K = HIDDIM;                 // 2048
    const int gemm_smem = NST2 * STB;     // 184320
    cudaFuncSetAttribute(gemm_hmma_kernel,
                         cudaFuncAttributeMaxDynamicSharedMemorySize, gemm_smem);
    cudaFuncSetAttribute(attn_hmma_kernel,
                         cudaFuncAttributeMaxDynamicSharedMemorySize, ATTN_SMEM);

    int convA_grid = (M * K) / 4 / 256;

    // 1) Q projection
    convA_kernel<<<convA_grid, 256>>>((const float4*)x, ah, al);
    convWT_kernel<<<dim3(HIDDIM / 32, K / 32), 256>>>(wq, bh, bl, K, HIDDIM);
    gemm_hmma_kernel<<<dim3(HIDDIM / 256, M / 128), 256, gemm_smem>>>(
        ah, al, bh, bl, q, M, HIDDIM, K);

    // 2) Q rmsnorm -> bf16 split
    rmsnorm_q_kernel<<<(M * NH) / 8, 256>>>(q, nqw, qh, qlp);

    // 3) KV projection
    convA_kernel<<<convA_grid, 256>>>((const float4*)c, ah, al);
    convWT_kernel<<<dim3((NKVH * HD * 2) / 32, K / 32), 256>>>(wkv, bh, bl, K, NKVH * HD * 2);
    gemm_hmma_kernel<<<dim3((NKVH * HD * 2) / 256, M / 128), 256, gemm_smem>>>(
        ah, al, bh, bl, kv, M, NKVH * HD * 2, K);

    // 4) split KV -> bf16 splits
    kvsplit_kernel<<<(BATCH * CLEN * NKVH) / 8, 256>>>(kv, nkw, kh, kl, vh, vl);

    // 5) HMMA attention -> writes bf16 split activations for out-proj
    attn_hmma_kernel<<<dim3(SEQ / 128, NH, BATCH), 256, ATTN_SMEM>>>(
        qh, qlp, kh, kl, vh, vl, ah, al);

    // 6) output projection
    convWT_kernel<<<dim3(HIDDIM / 32, K / 32), 256>>>(wo, bh, bl, K, HIDDIM);
    gemm_hmma_kernel<<<dim3(HIDDIM / 256, M / 128), 256, gemm_smem>>>(
        ah, al, bh, bl, out, M, HIDDIM, K);
}

// round 6
// speedup vs baseline: 3.4123x; 1.4685x over previous
#include <cuda_runtime.h>
#include <cuda_fp16.h>
#include <math.h>
#include <stdint.h>

#define BATCH 2
#define SEQ   2048
#define CLEN  2048
#define NH    16
#define NKVH  4
#define HD    128
#define HIDDIM 2048
#define EPSF  1e-6f
#define SCALEF 0.08838834764831845f   // 1/sqrt(128)

// ---------------- scratch (device globals) ---------------------------------
__device__ float g_q [BATCH*SEQ*HIDDIM];          // fp32 Q proj out
__device__ float g_kv[BATCH*CLEN*NKVH*HD*2];      // fp32 KV proj out

__device__ __half g_q16[BATCH*SEQ*HIDDIM];        // Q post-rmsnorm (fp16)
__device__ __half g_k16[BATCH*NKVH*CLEN*HD];      // K post-rmsnorm (fp16)
__device__ __half g_vh [BATCH*NKVH*CLEN*HD];      // V split hi/lo
__device__ __half g_vl [BATCH*NKVH*CLEN*HD];

__device__ __half g_a16[BATCH*SEQ*HIDDIM];        // activation buffer (x / c / attn-out)
__device__ __half g_wh [HIDDIM*HIDDIM];           // weight^T split hi/lo
__device__ __half g_wl [HIDDIM*HIDDIM];

// ======================= helpers ============================================
__device__ __forceinline__ uint32_t smem_u32(const void* p) {
    uint32_t a;
    asm("{ .reg .u64 t; cvta.to.shared.u64 t, %1; cvt.u32.u64 %0, t; }" : "=r"(a) : "l"(p));
    return a;
}
__device__ __forceinline__ void cpa16(uint32_t d, const void* g) {
    asm volatile("cp.async.cg.shared.global [%0], [%1], 16;" :: "r"(d), "l"(g) : "memory");
}
#define CP_COMMIT() asm volatile("cp.async.commit_group;" ::: "memory")

__device__ __forceinline__ void ldsm4(uint32_t& r0, uint32_t& r1, uint32_t& r2, uint32_t& r3,
                                      uint32_t a) {
    asm volatile("ldmatrix.sync.aligned.m8n8.x4.shared.b16 {%0,%1,%2,%3}, [%4];"
                 : "=r"(r0), "=r"(r1), "=r"(r2), "=r"(r3) : "r"(a));
}
__device__ __forceinline__ void ldsm4t(uint32_t& r0, uint32_t& r1, uint32_t& r2, uint32_t& r3,
                                       uint32_t a) {
    asm volatile("ldmatrix.sync.aligned.m8n8.x4.trans.shared.b16 {%0,%1,%2,%3}, [%4];"
                 : "=r"(r0), "=r"(r1), "=r"(r2), "=r"(r3) : "r"(a));
}
__device__ __forceinline__ void mma16816(float* c, const uint32_t* a, uint32_t b0, uint32_t b1) {
    asm volatile(
        "mma.sync.aligned.m16n8k16.row.col.f32.f16.f16.f32 "
        "{%0,%1,%2,%3}, {%4,%5,%6,%7}, {%8,%9}, {%0,%1,%2,%3};"
        : "+f"(c[0]), "+f"(c[1]), "+f"(c[2]), "+f"(c[3])
        : "r"(a[0]), "r"(a[1]), "r"(a[2]), "r"(a[3]), "r"(b0), "r"(b1));
}
__device__ __forceinline__ uint32_t packh2(float a, float b) {
    __half2 h = __floats2half2_rn(a, b);
    return *(uint32_t*)&h;
}

// ---------------- conversion kernels ----------------------------------------
__global__ __launch_bounds__(256) void convA16_kernel(
    const float4* __restrict__ in, __half* __restrict__ o16)
{
    size_t i = (size_t)blockIdx.x * 256 + threadIdx.x;
    float4 v = in[i];
    ((__half2*)o16)[i * 2]     = __floats2half2_rn(v.x, v.y);
    ((__half2*)o16)[i * 2 + 1] = __floats2half2_rn(v.z, v.w);
}

// weight transpose + fp16 split: W[K,N] fp32 -> Wt_h/Wt_l[N,K] fp16
__global__ __launch_bounds__(256) void convWT16_kernel(
    const float* __restrict__ w, __half* __restrict__ th,
    __half* __restrict__ tl, int K, int N)
{
    __shared__ float s[32][33];
    int n0 = blockIdx.x * 32, k0 = blockIdx.y * 32;
    int tx = threadIdx.x & 31, ty = threadIdx.x >> 5;
#pragma unroll
    for (int i = ty; i < 32; i += 8)
        s[i][tx] = w[(size_t)(k0 + i) * N + n0 + tx];
    __syncthreads();
#pragma unroll
    for (int j = ty; j < 32; j += 8) {
        float v = s[tx][j];
        __half h = __float2half_rn(v);
        __half l = __float2half_rn(v - __half2float(h));
        size_t idx = (size_t)(n0 + j) * K + k0 + tx;
        th[idx] = h;
        tl[idx] = l;
    }
}

// ---------------- fp16 GEMM: C[M,N] = A[M,K] @ (Wh+Wl)[N,K]^T  (2-pass) ----
#define TP2  80
#define A_T  (128 * TP2)             // 10240
#define B_T  (256 * TP2)             // 20480
#define STB  (A_T + 2 * B_T)         // 51200
#define NST2 3                       // 153600 B smem

__global__ __launch_bounds__(256, 1) void gemm_f16_kernel(
    const __half* __restrict__ A,
    const __half* __restrict__ Bh, const __half* __restrict__ Bl,
    float* __restrict__ C, int M, int N, int K)
{
    extern __shared__ char smc[];
    const uint32_t sb = smem_u32(smc);

    const int tid  = threadIdx.x;
    const int lane = tid & 31;
    const int wid  = tid >> 5;
    const int wm   = wid & 1;          // 2 warps along M (64 each)
    const int wn   = wid >> 1;         // 4 warps along N (64 each)
    const int bm   = blockIdx.y * 128;
    const int bn   = blockIdx.x * 256;

    const int arow = tid >> 1;
    const int ahalf = tid & 1;
    const size_t gA = (size_t)(bm + arow) * K + ahalf * 16;
    const uint32_t sA = arow * TP2 + ahalf * 32;
    const size_t gB = (size_t)(bn + tid) * K;
    const uint32_t sB = tid * TP2;

    const uint32_t laneOff = (lane & 15) * TP2 + (lane >> 4) * 16;

    float acc[4][8][4];
#pragma unroll
    for (int i = 0; i < 4; i++)
#pragma unroll
        for (int j = 0; j < 8; j++)
#pragma unroll
            for (int r = 0; r < 4; r++) acc[i][j][r] = 0.f;

    const int nst = K / 32;

    auto loadStage = [&](int s, int buf) {
        uint32_t st = sb + buf * STB;
        int k0 = s * 32;
        cpa16(st + sA,      A + gA + k0);
        cpa16(st + sA + 16, A + gA + k0 + 8);
        uint32_t bb = st + A_T + sB;
        cpa16(bb,      Bh + gB + k0);
        cpa16(bb + 16, Bh + gB + k0 + 8);
        cpa16(bb + 32, Bh + gB + k0 + 16);
        cpa16(bb + 48, Bh + gB + k0 + 24);
        bb += B_T;
        cpa16(bb,      Bl + gB + k0);
        cpa16(bb + 16, Bl + gB + k0 + 8);
        cpa16(bb + 32, Bl + gB + k0 + 16);
        cpa16(bb + 48, Bl + gB + k0 + 24);
        CP_COMMIT();
    };

    loadStage(0, 0);
    loadStage(1, 1);

    int buf = 0;
    for (int s = 0; s < nst; ++s) {
        if (s + 1 < nst) asm volatile("cp.async.wait_group 1;" ::: "memory");
        else             asm volatile("cp.async.wait_group 0;" ::: "memory");
        __syncthreads();

        if (s + 2 < nst) loadStage(s + 2, (buf + 2) % NST2);

        uint32_t st = sb + buf * STB;
        uint32_t aBase  = st + (wm * 64) * TP2 + laneOff;
        uint32_t bBaseH = st + A_T + (wn * 64) * TP2 + laneOff;
        uint32_t bBaseL = bBaseH + B_T;

#pragma unroll
        for (int ks = 0; ks < 2; ++ks) {
            uint32_t ko = ks * 32;
            uint32_t af[4][4];
#pragma unroll
            for (int mi = 0; mi < 4; ++mi)
                ldsm4(af[mi][0], af[mi][1], af[mi][2], af[mi][3],
                      aBase + mi * 16 * TP2 + ko);
#pragma unroll
            for (int bi = 0; bi < 4; ++bi) {
                uint32_t bhf[4], blf[4];
                ldsm4(bhf[0], bhf[1], bhf[2], bhf[3], bBaseH + bi * 16 * TP2 + ko);
                ldsm4(blf[0], blf[1], blf[2], blf[3], bBaseL + bi * 16 * TP2 + ko);
#pragma unroll
                for (int mi = 0; mi < 4; ++mi) {
#pragma unroll
                    for (int sub = 0; sub < 2; ++sub) {
                        int nj = bi * 2 + sub;
                        mma16816(acc[mi][nj], af[mi], bhf[sub], bhf[sub + 2]);
                        mma16816(acc[mi][nj], af[mi], blf[sub], blf[sub + 2]);
                    }
                }
            }
        }
        buf = (buf + 1) % NST2;
        __syncthreads();
    }

    const int g  = lane >> 2;
    const int q4 = lane & 3;
#pragma unroll
    for (int mi = 0; mi < 4; ++mi) {
#pragma unroll
        for (int nj = 0; nj < 8; ++nj) {
            int r0 = bm + wm * 64 + mi * 16 + g;
            int c0 = bn + wn * 64 + nj * 8 + q4 * 2;
            *(float2*)(C + (size_t)r0 * N + c0)       = make_float2(acc[mi][nj][0], acc[mi][nj][1]);
            *(float2*)(C + (size_t)(r0 + 8) * N + c0) = make_float2(acc[mi][nj][2], acc[mi][nj][3]);
        }
    }
}

// ---------------- per-head RMSNorm on Q -> fp16 ------------------------------
__global__ __launch_bounds__(256) void rmsnorm_q_kernel(
    const float* __restrict__ q, const float* __restrict__ w,
    __half* __restrict__ q16)
{
    int row  = blockIdx.x * 8 + (threadIdx.x >> 5);
    int lane = threadIdx.x & 31;
    float4 v = *(const float4*)(q + (size_t)row * HD + lane * 4);
    float ss = v.x * v.x + v.y * v.y + v.z * v.z + v.w * v.w;
#pragma unroll
    for (int o = 16; o > 0; o >>= 1) ss += __shfl_xor_sync(0xffffffffu, ss, o);
    float r = rsqrtf(ss * (1.f / 128.f) + EPSF);
    float4 wv = *(const float4*)(w + lane * 4);
    size_t base = (size_t)row * HD + lane * 4;
    *(__half2*)(q16 + base)     = __floats2half2_rn(v.x * r * wv.x, v.y * r * wv.y);
    *(__half2*)(q16 + base + 2) = __floats2half2_rn(v.z * r * wv.z, v.w * r * wv.w);
}

// ---------------- split packed KV -> rmsnorm K -> fp16 (V split hi/lo) ------
__global__ __launch_bounds__(256) void kvsplit_kernel(
    const float* __restrict__ kv, const float* __restrict__ wk,
    __half* __restrict__ k16, __half* __restrict__ vh, __half* __restrict__ vl)
{
    int row  = blockIdx.x * 8 + (threadIdx.x >> 5);  // (b*CLEN + l)*NKVH + kvh
    int lane = threadIdx.x & 31;
    int kvh  = row & 3;
    int bl_  = row >> 2;
    int b    = bl_ >> 11;
    int l    = bl_ & 2047;

    const float* base = kv + (size_t)row * 256;
    float4 f0 = *(const float4*)(base + lane * 8);
    float4 f1 = *(const float4*)(base + lane * 8 + 4);
    float k0 = f0.x, k1 = f0.z, k2 = f1.x, k3 = f1.z;
    float v0 = f0.y, v1 = f0.w, v2 = f1.y, v3 = f1.w;

    float ss = k0 * k0 + k1 * k1 + k2 * k2 + k3 * k3;
#pragma unroll
    for (int o = 16; o > 0; o >>= 1) ss += __shfl_xor_sync(0xffffffffu, ss, o);
    float r = rsqrtf(ss * (1.f / 128.f) + EPSF);

    int d0 = lane * 4;
    float4 wv = *(const float4*)(wk + d0);
    size_t ob = ((size_t)(b * NKVH + kvh) * CLEN + l) * HD + d0;

    *(__half2*)(k16 + ob)     = __floats2half2_rn(k0 * r * wv.x, k1 * r * wv.y);
    *(__half2*)(k16 + ob + 2) = __floats2half2_rn(k2 * r * wv.z, k3 * r * wv.w);

    __half h0 = __float2half_rn(v0), h1 = __float2half_rn(v1);
    __half h2 = __float2half_rn(v2), h3 = __float2half_rn(v3);
    *(__half2*)(vh + ob)     = __halves2half2(h0, h1);
    *(__half2*)(vh + ob + 2) = __halves2half2(h2, h3);
    *(__half2*)(vl + ob) = __floats2half2_rn(v0 - __half2float(h0), v1 - __half2float(h1));
    *(__half2*)(vl + ob + 2) = __floats2half2_rn(v2 - __half2float(h2), v3 - __half2float(h3));
}

// ---------------- fp16 flash attention: BQ=128, BK=64 ------------------------
// QK single-pass fp16; PV: P fp16 x (Vh + Vl) 2-pass.
#define QPITCH  272
#define QBYTES  (128 * QPITCH)      // 34816 (single Q tile)
#define KVT     (64 * QPITCH)       // 17408
#define KVSTG   (3 * KVT)           // 52224: K, Vh, Vl
#define ATTN_SMEM (QBYTES + 2 * KVSTG)   // 139264

__global__ __launch_bounds__(256, 1) void attn_f16_kernel(
    const __half* __restrict__ q16, const __half* __restrict__ k16,
    const __half* __restrict__ vh,  const __half* __restrict__ vl,
    __half* __restrict__ o16)
{
    extern __shared__ char smc[];
    const uint32_t sb = smem_u32(smc);

    const int tid  = threadIdx.x;
    const int lane = tid & 31;
    const int wid  = tid >> 5;
    const int h    = blockIdx.y;
    const int b    = blockIdx.z;
    const int kvh  = h >> 2;
    const int s0   = blockIdx.x * 128;

    const __half* qg = q16 + ((size_t)(b * SEQ + s0) * NH + h) * HD;
    const size_t kvbase = (size_t)(b * NKVH + kvh) * CLEN * HD;

    // Q resident tile
    {
        int chunk = tid & 15, r0 = tid >> 4;
#pragma unroll
        for (int it = 0; it < 8; ++it) {
            int row = r0 + it * 16;
            cpa16(sb + row * QPITCH + chunk * 16, qg + (size_t)row * HIDDIM + chunk * 8);
        }
        CP_COMMIT();
    }

    auto loadKV = [&](int blk, int stage) {
        uint32_t st = sb + QBYTES + stage * KVSTG;
        const __half* pk = k16 + kvbase + (size_t)blk * 64 * HD;
        const __half* ph = vh  + kvbase + (size_t)blk * 64 * HD;
        const __half* pl = vl  + kvbase + (size_t)blk * 64 * HD;
        int chunk = tid & 15, r0 = tid >> 4;
#pragma unroll
        for (int it = 0; it < 4; ++it) {
            int row = r0 + it * 16;
            uint32_t d = st + row * QPITCH + chunk * 16;
            size_t g = (size_t)row * HD + chunk * 8;
            cpa16(d,           pk + g);
            cpa16(d + KVT,     ph + g);
            cpa16(d + 2 * KVT, pl + g);
        }
        CP_COMMIT();
    };
    loadKV(0, 0);

    float m0 = -1e30f, m1 = -1e30f, l0 = 0.f, l1 = 0.f;
    float ofr[16][4];
#pragma unroll
    for (int f = 0; f < 16; ++f)
#pragma unroll
        for (int r = 0; r < 4; ++r) ofr[f][r] = 0.f;

    const uint32_t laneOff = (lane & 15) * QPITCH + (lane >> 4) * 16;
    const uint32_t qBase = sb + (wid * 16) * QPITCH + laneOff;

    for (int blk = 0; blk < 32; ++blk) {
        int stage = blk & 1;
        if (blk < 31) loadKV(blk + 1, stage ^ 1);
        if (blk < 31) asm volatile("cp.async.wait_group 1;" ::: "memory");
        else          asm volatile("cp.async.wait_group 0;" ::: "memory");
        __syncthreads();

        uint32_t st = sb + QBYTES + stage * KVSTG;
        uint32_t kBase = st + laneOff;
        uint32_t vBase = st + KVT + laneOff;

        // ---- S = Q K^T (single-pass fp16) ----
        float sc[8][4];
#pragma unroll
        for (int j = 0; j < 8; ++j)
#pragma unroll
            for (int r = 0; r < 4; ++r) sc[j][r] = 0.f;

#pragma unroll
        for (int kc = 0; kc < 8; ++kc) {
            uint32_t qa[4];
            ldsm4(qa[0], qa[1], qa[2], qa[3], qBase + kc * 32);
#pragma unroll
            for (int kg = 0; kg < 4; ++kg) {
                uint32_t kb[4];
                ldsm4(kb[0], kb[1], kb[2], kb[3],
                      kBase + kg * 16 * QPITCH + kc * 32);
                mma16816(sc[kg * 2],     qa, kb[0], kb[2]);
                mma16816(sc[kg * 2 + 1], qa, kb[1], kb[3]);
            }
        }

        // ---- online softmax ----
        float mx0 = -1e30f, mx1 = -1e30f;
#pragma unroll
        for (int j = 0; j < 8; ++j) {
            sc[j][0] *= SCALEF; sc[j][1] *= SCALEF;
            sc[j][2] *= SCALEF; sc[j][3] *= SCALEF;
            mx0 = fmaxf(mx0, fmaxf(sc[j][0], sc[j][1]));
            mx1 = fmaxf(mx1, fmaxf(sc[j][2], sc[j][3]));
        }
        mx0 = fmaxf(mx0, __shfl_xor_sync(0xffffffffu, mx0, 1));
        mx0 = fmaxf(mx0, __shfl_xor_sync(0xffffffffu, mx0, 2));
        mx1 = fmaxf(mx1, __shfl_xor_sync(0xffffffffu, mx1, 1));
        mx1 = fmaxf(mx1, __shfl_xor_sync(0xffffffffu, mx1, 2));
        float m0n = fmaxf(m0, mx0), m1n = fmaxf(m1, mx1);
        float c0 = __expf(m0 - m0n), c1 = __expf(m1 - m1n);
        m0 = m0n; m1 = m1n;

        float rs0 = 0.f, rs1 = 0.f;
#pragma unroll
        for (int j = 0; j < 8; ++j) {
            sc[j][0] = __expf(sc[j][0] - m0); rs0 += sc[j][0];
            sc[j][1] = __expf(sc[j][1] - m0); rs0 += sc[j][1];
            sc[j][2] = __expf(sc[j][2] - m1); rs1 += sc[j][2];
            sc[j][3] = __expf(sc[j][3] - m1); rs1 += sc[j][3];
        }
        rs0 += __shfl_xor_sync(0xffffffffu, rs0, 1);
        rs0 += __shfl_xor_sync(0xffffffffu, rs0, 2);
        rs1 += __shfl_xor_sync(0xffffffffu, rs1, 1);
        rs1 += __shfl_xor_sync(0xffffffffu, rs1, 2);
        l0 = l0 * c0 + rs0;
        l1 = l1 * c1 + rs1;

#pragma unroll
        for (int f = 0; f < 16; ++f) {
            ofr[f][0] *= c0; ofr[f][1] *= c0;
            ofr[f][2] *= c1; ofr[f][3] *= c1;
        }

        // ---- P fragments (fp16, exact-enough for [0,1] weights) ----
        uint32_t pa[4][4];
#pragma unroll
        for (int kc = 0; kc < 4; ++kc) {
#pragma unroll
            for (int half = 0; half < 2; ++half) {
                pa[kc][half * 2]     = packh2(sc[2 * kc + half][0], sc[2 * kc + half][1]);
                pa[kc][half * 2 + 1] = packh2(sc[2 * kc + half][2], sc[2 * kc + half][3]);
            }
        }

        // ---- O += P (Vh + Vl) ----
#pragma unroll
        for (int dg = 0; dg < 8; ++dg) {
#pragma unroll
            for (int kc = 0; kc < 4; ++kc) {
                uint32_t vb[4], vlb[4];
                ldsm4t(vb[0], vb[1], vb[2], vb[3],
                       vBase + kc * 16 * QPITCH + dg * 32);
                ldsm4t(vlb[0], vlb[1], vlb[2], vlb[3],
                       vBase + KVT + kc * 16 * QPITCH + dg * 32);
                mma16816(ofr[dg * 2],     pa[kc], vb[0],  vb[1]);
                mma16816(ofr[dg * 2 + 1], pa[kc], vb[2],  vb[3]);
                mma16816(ofr[dg * 2],     pa[kc], vlb[0], vlb[1]);
                mma16816(ofr[dg * 2 + 1], pa[kc], vlb[2], vlb[3]);
            }
        }
        __syncthreads();
    }

    // ---- epilogue: normalize, write fp16 activations for o-proj ----
    float inv0 = 1.f / l0, inv1 = 1.f / l1;
    int rowA = b * SEQ + s0 + wid * 16 + (lane >> 2);
    int colB = h * HD + (lane & 3) * 2;
#pragma unroll
    for (int f = 0; f < 16; ++f) {
        int col = colB + f * 8;
        *(__half2*)(o16 + (size_t)rowA * HIDDIM + col) =
            __floats2half2_rn(ofr[f][0] * inv0, ofr[f][1] * inv0);
        *(__half2*)(o16 + (size_t)(rowA + 8) * HIDDIM + col) =
            __floats2half2_rn(ofr[f][2] * inv1, ofr[f][3] * inv1);
    }
}

// ---------------- launch ----------------------------------------------------
extern "C" void kernel_launch(void* const* d_in, const int* in_sizes, int n_in,
                              void* d_out, int out_size)
{
    (void)in_sizes; (void)n_in; (void)out_size;
    const float* x   = (const float*)d_in[0];
    const float* c   = (const float*)d_in[1];
    const float* wq  = (const float*)d_in[2];
    const float* wkv = (const float*)d_in[3];
    const float* wo  = (const float*)d_in[4];
    const float* nqw = (const float*)d_in[5];
    const float* nkw = (const float*)d_in[6];
    float* out = (float*)d_out;

    float *q, *kv;
    __half *q16, *k16, *vh, *vl, *a16, *wh, *wl;
    cudaGetSymbolAddress((void**)&q,   g_q);
    cudaGetSymbolAddress((void**)&kv,  g_kv);
    cudaGetSymbolAddress((void**)&q16, g_q16);
    cudaGetSymbolAddress((void**)&k16, g_k16);
    cudaGetSymbolAddress((void**)&vh,  g_vh);
    cudaGetSymbolAddress((void**)&vl,  g_vl);
    cudaGetSymbolAddress((void**)&a16, g_a16);
    cudaGetSymbolAddress((void**)&wh,  g_wh);
    cudaGetSymbolAddress((void**)&wl,  g_wl);

    const int M = BATCH * SEQ;            // 4096
    const int K = HIDDIM;                 // 2048
    const int gemm_smem = NST2 * STB;     // 153600
    cudaFuncSetAttribute(gemm_f16_kernel,
                         cudaFuncAttributeMaxDynamicSharedMemorySize, gemm_smem);
    cudaFuncSetAttribute(attn_f16_kernel,
                         cudaFuncAttributeMaxDynamicSharedMemorySize, ATTN_SMEM);

    int convA_grid = (M * K) / 4 / 256;

    // 1) Q projection: q = x @ wq  (A fp16 single, W split fp16 2-pass)
    convA16_kernel<<<convA_grid, 256>>>((const float4*)x, a16);
    convWT16_kernel<<<dim3(HIDDIM / 32, K / 32), 256>>>(wq, wh, wl, K, HIDDIM);
    gemm_f16_kernel<<<dim3(HIDDIM / 256, M / 128), 256, gemm_smem>>>(
        a16, wh, wl, q, M, HIDDIM, K);

    // 2) Q rmsnorm -> fp16
    rmsnorm_q_kernel<<<(M * NH) / 8, 256>>>(q, nqw, q16);

    // 3) KV projection
    convA16_kernel<<<convA_grid, 256>>>((const float4*)c, a16);
    convWT16_kernel<<<dim3((NKVH * HD * 2) / 32, K / 32), 256>>>(wkv, wh, wl, K, NKVH * HD * 2);
    gemm_f16_kernel<<<dim3((NKVH * HD * 2) / 256, M / 128), 256, gemm_smem>>>(
        a16, wh, wl, kv, M, NKVH * HD * 2, K);

    // 4) split KV -> fp16 (K single, V hi/lo)
    kvsplit_kernel<<<(BATCH * CLEN * NKVH) / 8, 256>>>(kv, nkw, k16, vh, vl);

    // 5) fp16 attention -> fp16 activations
    attn_f16_kernel<<<dim3(SEQ / 128, NH, BATCH), 256, ATTN_SMEM>>>(
        q16, k16, vh, vl, a16);

    // 6) output projection
    convWT16_kernel<<<dim3(HIDDIM / 32, K / 32), 256>>>(wo, wh, wl, K, HIDDIM);
    gemm_f16_kernel<<<dim3(HIDDIM / 256, M / 128), 256, gemm_smem>>>(
        a16, wh, wl, out, M, HIDDIM, K);
}

// round 7
// speedup vs baseline: 3.9388x; 1.1543x over previous
#include <cuda_runtime.h>
#include <cuda_fp16.h>
#include <math.h>
#include <stdint.h>

#define BATCH 2
#define SEQ   2048
#define CLEN  2048
#define NH    16
#define NKVH  4
#define HD    128
#define HIDDIM 2048
#define EPSF  1e-6f
#define SCALEF 0.08838834764831845f   // 1/sqrt(128)

// ---------------- scratch (device globals) ---------------------------------
__device__ float g_q [BATCH*SEQ*HIDDIM];          // fp32 Q proj out
__device__ float g_kv[BATCH*CLEN*NKVH*HD*2];      // fp32 KV proj out

__device__ __half g_q16[BATCH*SEQ*HIDDIM];        // Q post-rmsnorm (fp16)
__device__ __half g_k16[BATCH*NKVH*CLEN*HD];      // K post-rmsnorm (fp16)
__device__ __half g_v16[BATCH*NKVH*CLEN*HD];      // V (fp16 single)

__device__ __half g_a16[BATCH*SEQ*HIDDIM];        // activation buffer (x / c / attn-out)
__device__ __half g_wh [HIDDIM*HIDDIM];           // weight^T split hi/lo
__device__ __half g_wl [HIDDIM*HIDDIM];

// ======================= helpers ============================================
__device__ __forceinline__ uint32_t smem_u32(const void* p) {
    uint32_t a;
    asm("{ .reg .u64 t; cvta.to.shared.u64 t, %1; cvt.u32.u64 %0, t; }" : "=r"(a) : "l"(p));
    return a;
}
__device__ __forceinline__ void cpa16(uint32_t d, const void* g) {
    asm volatile("cp.async.cg.shared.global [%0], [%1], 16;" :: "r"(d), "l"(g) : "memory");
}
#define CP_COMMIT() asm volatile("cp.async.commit_group;" ::: "memory")

__device__ __forceinline__ void ldsm4(uint32_t& r0, uint32_t& r1, uint32_t& r2, uint32_t& r3,
                                      uint32_t a) {
    asm volatile("ldmatrix.sync.aligned.m8n8.x4.shared.b16 {%0,%1,%2,%3}, [%4];"
                 : "=r"(r0), "=r"(r1), "=r"(r2), "=r"(r3) : "r"(a));
}
__device__ __forceinline__ void ldsm4t(uint32_t& r0, uint32_t& r1, uint32_t& r2, uint32_t& r3,
                                       uint32_t a) {
    asm volatile("ldmatrix.sync.aligned.m8n8.x4.trans.shared.b16 {%0,%1,%2,%3}, [%4];"
                 : "=r"(r0), "=r"(r1), "=r"(r2), "=r"(r3) : "r"(a));
}
__device__ __forceinline__ void mma16816(float* c, const uint32_t* a, uint32_t b0, uint32_t b1) {
    asm volatile(
        "mma.sync.aligned.m16n8k16.row.col.f32.f16.f16.f32 "
        "{%0,%1,%2,%3}, {%4,%5,%6,%7}, {%8,%9}, {%0,%1,%2,%3};"
        : "+f"(c[0]), "+f"(c[1]), "+f"(c[2]), "+f"(c[3])
        : "r"(a[0]), "r"(a[1]), "r"(a[2]), "r"(a[3]), "r"(b0), "r"(b1));
}
__device__ __forceinline__ uint32_t packh2(float a, float b) {
    __half2 h = __floats2half2_rn(a, b);
    return *(uint32_t*)&h;
}

// ---------------- conversion kernels ----------------------------------------
__global__ __launch_bounds__(256) void convA16_kernel(
    const float4* __restrict__ in, __half* __restrict__ o16)
{
    size_t i = (size_t)blockIdx.x * 256 + threadIdx.x;
    float4 v = in[i];
    ((__half2*)o16)[i * 2]     = __floats2half2_rn(v.x, v.y);
    ((__half2*)o16)[i * 2 + 1] = __floats2half2_rn(v.z, v.w);
}

// weight transpose + fp16 split: W[K,N] fp32 -> Wt_h/Wt_l[N,K] fp16
__global__ __launch_bounds__(256) void convWT16_kernel(
    const float* __restrict__ w, __half* __restrict__ th,
    __half* __restrict__ tl, int K, int N)
{
    __shared__ float s[32][33];
    int n0 = blockIdx.x * 32, k0 = blockIdx.y * 32;
    int tx = threadIdx.x & 31, ty = threadIdx.x >> 5;
#pragma unroll
    for (int i = ty; i < 32; i += 8)
        s[i][tx] = w[(size_t)(k0 + i) * N + n0 + tx];
    __syncthreads();
#pragma unroll
    for (int j = ty; j < 32; j += 8) {
        float v = s[tx][j];
        __half h = __float2half_rn(v);
        __half l = __float2half_rn(v - __half2float(h));
        size_t idx = (size_t)(n0 + j) * K + k0 + tx;
        th[idx] = h;
        tl[idx] = l;
    }
}

// weight transpose single fp16 (for KV projection)
__global__ __launch_bounds__(256) void convWT16s_kernel(
    const float* __restrict__ w, __half* __restrict__ th, int K, int N)
{
    __shared__ float s[32][33];
    int n0 = blockIdx.x * 32, k0 = blockIdx.y * 32;
    int tx = threadIdx.x & 31, ty = threadIdx.x >> 5;
#pragma unroll
    for (int i = ty; i < 32; i += 8)
        s[i][tx] = w[(size_t)(k0 + i) * N + n0 + tx];
    __syncthreads();
#pragma unroll
    for (int j = ty; j < 32; j += 8)
        th[(size_t)(n0 + j) * K + k0 + tx] = __float2half_rn(s[tx][j]);
}

// ---------------- fp16 GEMM 2-pass: C = A @ (Wh+Wl)^T ----------------------
#define TP2  80
#define A_T  (128 * TP2)             // 10240
#define B_T  (256 * TP2)             // 20480
#define STB  (A_T + 2 * B_T)         // 51200
#define NST2 3                       // 153600 B smem

__global__ __launch_bounds__(256, 1) void gemm_f16_kernel(
    const __half* __restrict__ A,
    const __half* __restrict__ Bh, const __half* __restrict__ Bl,
    float* __restrict__ C, int M, int N, int K)
{
    extern __shared__ char smc[];
    const uint32_t sb = smem_u32(smc);

    const int tid  = threadIdx.x;
    const int lane = tid & 31;
    const int wid  = tid >> 5;
    const int wm   = wid & 1;
    const int wn   = wid >> 1;
    const int bm   = blockIdx.y * 128;
    const int bn   = blockIdx.x * 256;

    const int arow = tid >> 1;
    const int ahalf = tid & 1;
    const size_t gA = (size_t)(bm + arow) * K + ahalf * 16;
    const uint32_t sA = arow * TP2 + ahalf * 32;
    const size_t gB = (size_t)(bn + tid) * K;
    const uint32_t sB = tid * TP2;

    const uint32_t laneOff = (lane & 15) * TP2 + (lane >> 4) * 16;

    float acc[4][8][4];
#pragma unroll
    for (int i = 0; i < 4; i++)
#pragma unroll
        for (int j = 0; j < 8; j++)
#pragma unroll
            for (int r = 0; r < 4; r++) acc[i][j][r] = 0.f;

    const int nst = K / 32;

    auto loadStage = [&](int s, int buf) {
        uint32_t st = sb + buf * STB;
        int k0 = s * 32;
        cpa16(st + sA,      A + gA + k0);
        cpa16(st + sA + 16, A + gA + k0 + 8);
        uint32_t bb = st + A_T + sB;
        cpa16(bb,      Bh + gB + k0);
        cpa16(bb + 16, Bh + gB + k0 + 8);
        cpa16(bb + 32, Bh + gB + k0 + 16);
        cpa16(bb + 48, Bh + gB + k0 + 24);
        bb += B_T;
        cpa16(bb,      Bl + gB + k0);
        cpa16(bb + 16, Bl + gB + k0 + 8);
        cpa16(bb + 32, Bl + gB + k0 + 16);
        cpa16(bb + 48, Bl + gB + k0 + 24);
        CP_COMMIT();
    };

    loadStage(0, 0);
    loadStage(1, 1);

    int buf = 0;
    for (int s = 0; s < nst; ++s) {
        if (s + 1 < nst) asm volatile("cp.async.wait_group 1;" ::: "memory");
        else             asm volatile("cp.async.wait_group 0;" ::: "memory");
        __syncthreads();

        if (s + 2 < nst) loadStage(s + 2, (buf + 2) % NST2);

        uint32_t st = sb + buf * STB;
        uint32_t aBase  = st + (wm * 64) * TP2 + laneOff;
        uint32_t bBaseH = st + A_T + (wn * 64) * TP2 + laneOff;
        uint32_t bBaseL = bBaseH + B_T;

#pragma unroll
        for (int ks = 0; ks < 2; ++ks) {
            uint32_t ko = ks * 32;
            uint32_t af[4][4];
#pragma unroll
            for (int mi = 0; mi < 4; ++mi)
                ldsm4(af[mi][0], af[mi][1], af[mi][2], af[mi][3],
                      aBase + mi * 16 * TP2 + ko);
#pragma unroll
            for (int bi = 0; bi < 4; ++bi) {
                uint32_t bhf[4], blf[4];
                ldsm4(bhf[0], bhf[1], bhf[2], bhf[3], bBaseH + bi * 16 * TP2 + ko);
                ldsm4(blf[0], blf[1], blf[2], blf[3], bBaseL + bi * 16 * TP2 + ko);
#pragma unroll
                for (int mi = 0; mi < 4; ++mi) {
#pragma unroll
                    for (int sub = 0; sub < 2; ++sub) {
                        int nj = bi * 2 + sub;
                        mma16816(acc[mi][nj], af[mi], bhf[sub], bhf[sub + 2]);
                        mma16816(acc[mi][nj], af[mi], blf[sub], blf[sub + 2]);
                    }
                }
            }
        }
        buf = (buf + 1) % NST2;
        __syncthreads();
    }

    const int g  = lane >> 2;
    const int q4 = lane & 3;
#pragma unroll
    for (int mi = 0; mi < 4; ++mi) {
#pragma unroll
        for (int nj = 0; nj < 8; ++nj) {
            int r0 = bm + wm * 64 + mi * 16 + g;
            int c0 = bn + wn * 64 + nj * 8 + q4 * 2;
            *(float2*)(C + (size_t)r0 * N + c0)       = make_float2(acc[mi][nj][0], acc[mi][nj][1]);
            *(float2*)(C + (size_t)(r0 + 8) * N + c0) = make_float2(acc[mi][nj][2], acc[mi][nj][3]);
        }
    }
}

// ---------------- fp16 GEMM 1-pass: C = A @ Wh^T (KV projection) ------------
#define STB1 (A_T + B_T)             // 30720
#define NST1 3                       // 92160 B smem

__global__ __launch_bounds__(256, 1) void gemm_f16_1p_kernel(
    const __half* __restrict__ A, const __half* __restrict__ Bh,
    float* __restrict__ C, int M, int N, int K)
{
    extern __shared__ char smc[];
    const uint32_t sb = smem_u32(smc);

    const int tid  = threadIdx.x;
    const int lane = tid & 31;
    const int wid  = tid >> 5;
    const int wm   = wid & 1;
    const int wn   = wid >> 1;
    const int bm   = blockIdx.y * 128;
    const int bn   = blockIdx.x * 256;

    const int arow = tid >> 1;
    const int ahalf = tid & 1;
    const size_t gA = (size_t)(bm + arow) * K + ahalf * 16;
    const uint32_t sA = arow * TP2 + ahalf * 32;
    const size_t gB = (size_t)(bn + tid) * K;
    const uint32_t sB = tid * TP2;

    const uint32_t laneOff = (lane & 15) * TP2 + (lane >> 4) * 16;

    float acc[4][8][4];
#pragma unroll
    for (int i = 0; i < 4; i++)
#pragma unroll
        for (int j = 0; j < 8; j++)
#pragma unroll
            for (int r = 0; r < 4; r++) acc[i][j][r] = 0.f;

    const int nst = K / 32;

    auto loadStage = [&](int s, int buf) {
        uint32_t st = sb + buf * STB1;
        int k0 = s * 32;
        cpa16(st + sA,      A + gA + k0);
        cpa16(st + sA + 16, A + gA + k0 + 8);
        uint32_t bb = st + A_T + sB;
        cpa16(bb,      Bh + gB + k0);
        cpa16(bb + 16, Bh + gB + k0 + 8);
        cpa16(bb + 32, Bh + gB + k0 + 16);
        cpa16(bb + 48, Bh + gB + k0 + 24);
        CP_COMMIT();
    };

    loadStage(0, 0);
    loadStage(1, 1);

    int buf = 0;
    for (int s = 0; s < nst; ++s) {
        if (s + 1 < nst) asm volatile("cp.async.wait_group 1;" ::: "memory");
        else             asm volatile("cp.async.wait_group 0;" ::: "memory");
        __syncthreads();

        if (s + 2 < nst) loadStage(s + 2, (buf + 2) % NST1);

        uint32_t st = sb + buf * STB1;
        uint32_t aBase  = st + (wm * 64) * TP2 + laneOff;
        uint32_t bBase  = st + A_T + (wn * 64) * TP2 + laneOff;

#pragma unroll
        for (int ks = 0; ks < 2; ++ks) {
            uint32_t ko = ks * 32;
            uint32_t af[4][4];
#pragma unroll
            for (int mi = 0; mi < 4; ++mi)
                ldsm4(af[mi][0], af[mi][1], af[mi][2], af[mi][3],
                      aBase + mi * 16 * TP2 + ko);
#pragma unroll
            for (int bi = 0; bi < 4; ++bi) {
                uint32_t bf[4];
                ldsm4(bf[0], bf[1], bf[2], bf[3], bBase + bi * 16 * TP2 + ko);
#pragma unroll
                for (int mi = 0; mi < 4; ++mi) {
#pragma unroll
                    for (int sub = 0; sub < 2; ++sub)
                        mma16816(acc[mi][bi * 2 + sub], af[mi], bf[sub], bf[sub + 2]);
                }
            }
        }
        buf = (buf + 1) % NST1;
        __syncthreads();
    }

    const int g  = lane >> 2;
    const int q4 = lane & 3;
#pragma unroll
    for (int mi = 0; mi < 4; ++mi) {
#pragma unroll
        for (int nj = 0; nj < 8; ++nj) {
            int r0 = bm + wm * 64 + mi * 16 + g;
            int c0 = bn + wn * 64 + nj * 8 + q4 * 2;
            *(float2*)(C + (size_t)r0 * N + c0)       = make_float2(acc[mi][nj][0], acc[mi][nj][1]);
            *(float2*)(C + (size_t)(r0 + 8) * N + c0) = make_float2(acc[mi][nj][2], acc[mi][nj][3]);
        }
    }
}

// ---------------- per-head RMSNorm on Q -> fp16 ------------------------------
__global__ __launch_bounds__(256) void rmsnorm_q_kernel(
    const float* __restrict__ q, const float* __restrict__ w,
    __half* __restrict__ q16)
{
    int row  = blockIdx.x * 8 + (threadIdx.x >> 5);
    int lane = threadIdx.x & 31;
    float4 v = *(const float4*)(q + (size_t)row * HD + lane * 4);
    float ss = v.x * v.x + v.y * v.y + v.z * v.z + v.w * v.w;
#pragma unroll
    for (int o = 16; o > 0; o >>= 1) ss += __shfl_xor_sync(0xffffffffu, ss, o);
    float r = rsqrtf(ss * (1.f / 128.f) + EPSF);
    float4 wv = *(const float4*)(w + lane * 4);
    size_t base = (size_t)row * HD + lane * 4;
    *(__half2*)(q16 + base)     = __floats2half2_rn(v.x * r * wv.x, v.y * r * wv.y);
    *(__half2*)(q16 + base + 2) = __floats2half2_rn(v.z * r * wv.z, v.w * r * wv.w);
}

// ---------------- split packed KV -> rmsnorm K -> fp16 ----------------------
__global__ __launch_bounds__(256) void kvsplit_kernel(
    const float* __restrict__ kv, const float* __restrict__ wk,
    __half* __restrict__ k16, __half* __restrict__ v16)
{
    int row  = blockIdx.x * 8 + (threadIdx.x >> 5);  // (b*CLEN + l)*NKVH + kvh
    int lane = threadIdx.x & 31;
    int kvh  = row & 3;
    int bl_  = row >> 2;
    int b    = bl_ >> 11;
    int l    = bl_ & 2047;

    const float* base = kv + (size_t)row * 256;
    float4 f0 = *(const float4*)(base + lane * 8);
    float4 f1 = *(const float4*)(base + lane * 8 + 4);
    float k0 = f0.x, k1 = f0.z, k2 = f1.x, k3 = f1.z;
    float v0 = f0.y, v1 = f0.w, v2 = f1.y, v3 = f1.w;

    float ss = k0 * k0 + k1 * k1 + k2 * k2 + k3 * k3;
#pragma unroll
    for (int o = 16; o > 0; o >>= 1) ss += __shfl_xor_sync(0xffffffffu, ss, o);
    float r = rsqrtf(ss * (1.f / 128.f) + EPSF);

    int d0 = lane * 4;
    float4 wv = *(const float4*)(wk + d0);
    size_t ob = ((size_t)(b * NKVH + kvh) * CLEN + l) * HD + d0;

    *(__half2*)(k16 + ob)     = __floats2half2_rn(k0 * r * wv.x, k1 * r * wv.y);
    *(__half2*)(k16 + ob + 2) = __floats2half2_rn(k2 * r * wv.z, k3 * r * wv.w);
    *(__half2*)(v16 + ob)     = __floats2half2_rn(v0, v1);
    *(__half2*)(v16 + ob + 2) = __floats2half2_rn(v2, v3);
}

// ---------------- fp16 flash attention: BQ=128, BK=64, V single-pass --------
#define QPITCH  272
#define QBYTES  (128 * QPITCH)      // 34816
#define KVT     (64 * QPITCH)       // 17408
#define KVSTG   (2 * KVT)           // 34816: K, V
#define ATTN_SMEM (QBYTES + 2 * KVSTG)   // 104448

__global__ __launch_bounds__(256, 1) void attn_f16_kernel(
    const __half* __restrict__ q16, const __half* __restrict__ k16,
    const __half* __restrict__ v16, __half* __restrict__ o16)
{
    extern __shared__ char smc[];
    const uint32_t sb = smem_u32(smc);

    const int tid  = threadIdx.x;
    const int lane = tid & 31;
    const int wid  = tid >> 5;
    const int h    = blockIdx.y;
    const int b    = blockIdx.z;
    const int kvh  = h >> 2;
    const int s0   = blockIdx.x * 128;

    const __half* qg = q16 + ((size_t)(b * SEQ + s0) * NH + h) * HD;
    const size_t kvbase = (size_t)(b * NKVH + kvh) * CLEN * HD;

    {
        int chunk = tid & 15, r0 = tid >> 4;
#pragma unroll
        for (int it = 0; it < 8; ++it) {
            int row = r0 + it * 16;
            cpa16(sb + row * QPITCH + chunk * 16, qg + (size_t)row * HIDDIM + chunk * 8);
        }
        CP_COMMIT();
    }

    auto loadKV = [&](int blk, int stage) {
        uint32_t st = sb + QBYTES + stage * KVSTG;
        const __half* pk = k16 + kvbase + (size_t)blk * 64 * HD;
        const __half* pv = v16 + kvbase + (size_t)blk * 64 * HD;
        int chunk = tid & 15, r0 = tid >> 4;
#pragma unroll
        for (int it = 0; it < 4; ++it) {
            int row = r0 + it * 16;
            uint32_t d = st + row * QPITCH + chunk * 16;
            size_t g = (size_t)row * HD + chunk * 8;
            cpa16(d,       pk + g);
            cpa16(d + KVT, pv + g);
        }
        CP_COMMIT();
    };
    loadKV(0, 0);

    float m0 = -1e30f, m1 = -1e30f, l0 = 0.f, l1 = 0.f;
    float ofr[16][4];
#pragma unroll
    for (int f = 0; f < 16; ++f)
#pragma unroll
        for (int r = 0; r < 4; ++r) ofr[f][r] = 0.f;

    const uint32_t laneOff = (lane & 15) * QPITCH + (lane >> 4) * 16;
    const uint32_t qBase = sb + (wid * 16) * QPITCH + laneOff;

    for (int blk = 0; blk < 32; ++blk) {
        int stage = blk & 1;
        if (blk < 31) loadKV(blk + 1, stage ^ 1);
        if (blk < 31) asm volatile("cp.async.wait_group 1;" ::: "memory");
        else          asm volatile("cp.async.wait_group 0;" ::: "memory");
        __syncthreads();

        uint32_t st = sb + QBYTES + stage * KVSTG;
        uint32_t kBase = st + laneOff;
        uint32_t vBase = st + KVT + laneOff;

        // ---- S = Q K^T ----
        float sc[8][4];
#pragma unroll
        for (int j = 0; j < 8; ++j)
#pragma unroll
            for (int r = 0; r < 4; ++r) sc[j][r] = 0.f;

#pragma unroll
        for (int kc = 0; kc < 8; ++kc) {
            uint32_t qa[4];
            ldsm4(qa[0], qa[1], qa[2], qa[3], qBase + kc * 32);
#pragma unroll
            for (int kg = 0; kg < 4; ++kg) {
                uint32_t kb[4];
                ldsm4(kb[0], kb[1], kb[2], kb[3],
                      kBase + kg * 16 * QPITCH + kc * 32);
                mma16816(sc[kg * 2],     qa, kb[0], kb[2]);
                mma16816(sc[kg * 2 + 1], qa, kb[1], kb[3]);
            }
        }

        // ---- online softmax ----
        float mx0 = -1e30f, mx1 = -1e30f;
#pragma unroll
        for (int j = 0; j < 8; ++j) {
            sc[j][0] *= SCALEF; sc[j][1] *= SCALEF;
            sc[j][2] *= SCALEF; sc[j][3] *= SCALEF;
            mx0 = fmaxf(mx0, fmaxf(sc[j][0], sc[j][1]));
            mx1 = fmaxf(mx1, fmaxf(sc[j][2], sc[j][3]));
        }
        mx0 = fmaxf(mx0, __shfl_xor_sync(0xffffffffu, mx0, 1));
        mx0 = fmaxf(mx0, __shfl_xor_sync(0xffffffffu, mx0, 2));
        mx1 = fmaxf(mx1, __shfl_xor_sync(0xffffffffu, mx1, 1));
        mx1 = fmaxf(mx1, __shfl_xor_sync(0xffffffffu, mx1, 2));
        float m0n = fmaxf(m0, mx0), m1n = fmaxf(m1, mx1);
        float c0 = __expf(m0 - m0n), c1 = __expf(m1 - m1n);
        m0 = m0n; m1 = m1n;

        float rs0 = 0.f, rs1 = 0.f;
#pragma unroll
        for (int j = 0; j < 8; ++j) {
            sc[j][0] = __expf(sc[j][0] - m0); rs0 += sc[j][0];
            sc[j][1] = __expf(sc[j][1] - m0); rs0 += sc[j][1];
            sc[j][2] = __expf(sc[j][2] - m1); rs1 += sc[j][2];
            sc[j][3] = __expf(sc[j][3] - m1); rs1 += sc[j][3];
        }
        rs0 += __shfl_xor_sync(0xffffffffu, rs0, 1);
        rs0 += __shfl_xor_sync(0xffffffffu, rs0, 2);
        rs1 += __shfl_xor_sync(0xffffffffu, rs1, 1);
        rs1 += __shfl_xor_sync(0xffffffffu, rs1, 2);
        l0 = l0 * c0 + rs0;
        l1 = l1 * c1 + rs1;

#pragma unroll
        for (int f = 0; f < 16; ++f) {
            ofr[f][0] *= c0; ofr[f][1] *= c0;
            ofr[f][2] *= c1; ofr[f][3] *= c1;
        }

        // ---- P fragments ----
        uint32_t pa[4][4];
#pragma unroll
        for (int kc = 0; kc < 4; ++kc) {
#pragma unroll
            for (int half = 0; half < 2; ++half) {
                pa[kc][half * 2]     = packh2(sc[2 * kc + half][0], sc[2 * kc + half][1]);
                pa[kc][half * 2 + 1] = packh2(sc[2 * kc + half][2], sc[2 * kc + half][3]);
            }
        }

        // ---- O += P V ----
#pragma unroll
        for (int dg = 0; dg < 8; ++dg) {
#pragma unroll
            for (int kc = 0; kc < 4; ++kc) {
                uint32_t vb[4];
                ldsm4t(vb[0], vb[1], vb[2], vb[3],
                       vBase + kc * 16 * QPITCH + dg * 32);
                mma16816(ofr[dg * 2],     pa[kc], vb[0], vb[1]);
                mma16816(ofr[dg * 2 + 1], pa[kc], vb[2], vb[3]);
            }
        }
        __syncthreads();
    }

    float inv0 = 1.f / l0, inv1 = 1.f / l1;
    int rowA = b * SEQ + s0 + wid * 16 + (lane >> 2);
    int colB = h * HD + (lane & 3) * 2;
#pragma unroll
    for (int f = 0; f < 16; ++f) {
        int col = colB + f * 8;
        *(__half2*)(o16 + (size_t)rowA * HIDDIM + col) =
            __floats2half2_rn(ofr[f][0] * inv0, ofr[f][1] * inv0);
        *(__half2*)(o16 + (size_t)(rowA + 8) * HIDDIM + col) =
            __floats2half2_rn(ofr[f][2] * inv1, ofr[f][3] * inv1);
    }
}

// ---------------- launch ----------------------------------------------------
extern "C" void kernel_launch(void* const* d_in, const int* in_sizes, int n_in,
                              void* d_out, int out_size)
{
    (void)in_sizes; (void)n_in; (void)out_size;
    const float* x   = (const float*)d_in[0];
    const float* c   = (const float*)d_in[1];
    const float* wq  = (const float*)d_in[2];
    const float* wkv = (const float*)d_in[3];
    const float* wo  = (const float*)d_in[4];
    const float* nqw = (const float*)d_in[5];
    const float* nkw = (const float*)d_in[6];
    float* out = (float*)d_out;

    float *q, *kv;
    __half *q16, *k16, *v16, *a16, *wh, *wl;
    cudaGetSymbolAddress((void**)&q,   g_q);
    cudaGetSymbolAddress((void**)&kv,  g_kv);
    cudaGetSymbolAddress((void**)&q16, g_q16);
    cudaGetSymbolAddress((void**)&k16, g_k16);
    cudaGetSymbolAddress((void**)&v16, g_v16);
    cudaGetSymbolAddress((void**)&a16, g_a16);
    cudaGetSymbolAddress((void**)&wh,  g_wh);
    cudaGetSymbolAddress((void**)&wl,  g_wl);

    const int M = BATCH * SEQ;            // 4096
    const int K = HIDDIM;                 // 2048
    const int gemm_smem  = NST2 * STB;    // 153600
    const int gemm1_smem = NST1 * STB1;   // 92160
    cudaFuncSetAttribute(gemm_f16_kernel,
                         cudaFuncAttributeMaxDynamicSharedMemorySize, gemm_smem);
    cudaFuncSetAttribute(gemm_f16_1p_kernel,
                         cudaFuncAttributeMaxDynamicSharedMemorySize, gemm1_smem);
    cudaFuncSetAttribute(attn_f16_kernel,
                         cudaFuncAttributeMaxDynamicSharedMemorySize, ATTN_SMEM);

    int convA_grid = (M * K) / 4 / 256;

    // 1) Q projection: q = x @ wq  (A fp16 single, W split fp16 2-pass)
    convA16_kernel<<<convA_grid, 256>>>((const float4*)x, a16);
    convWT16_kernel<<<dim3(HIDDIM / 32, K / 32), 256>>>(wq, wh, wl, K, HIDDIM);
    gemm_f16_kernel<<<dim3(HIDDIM / 256, M / 128), 256, gemm_smem>>>(
        a16, wh, wl, q, M, HIDDIM, K);

    // 2) Q rmsnorm -> fp16
    rmsnorm_q_kernel<<<(M * NH) / 8, 256>>>(q, nqw, q16);

    // 3) KV projection (single-pass weights)
    convA16_kernel<<<convA_grid, 256>>>((const float4*)c, a16);
    convWT16s_kernel<<<dim3((NKVH * HD * 2) / 32, K / 32), 256>>>(wkv, wh, K, NKVH * HD * 2);
    gemm_f16_1p_kernel<<<dim3((NKVH * HD * 2) / 256, M / 128), 256, gemm1_smem>>>(
        a16, wh, kv, M, NKVH * HD * 2, K);

    // 4) split KV -> fp16
    kvsplit_kernel<<<(BATCH * CLEN * NKVH) / 8, 256>>>(kv, nkw, k16, v16);

    // 5) fp16 attention (V single-pass) -> fp16 activations
    attn_f16_kernel<<<dim3(SEQ / 128, NH, BATCH), 256, ATTN_SMEM>>>(
        q16, k16, v16, a16);

    // 6) output projection (W 2-pass)
    convWT16_kernel<<<dim3(HIDDIM / 32, K / 32), 256>>>(wo, wh, wl, K, HIDDIM);
    gemm_f16_kernel<<<dim3(HIDDIM / 256, M / 128), 256, gemm_smem>>>(
        a16, wh, wl, out, M, HIDDIM, K);
}

// round 8
// speedup vs baseline: 5.3751x; 1.3646x over previous
#include <cuda_runtime.h>
#include <cuda_fp16.h>
#include <math.h>
#include <stdint.h>

#define BATCH 2
#define SEQ   2048
#define CLEN  2048
#define NH    16
#define NKVH  4
#define HD    128
#define HIDDIM 2048
#define EPSF  1e-6f
#define SCALEF 0.08838834764831845f   // 1/sqrt(128)

// ---------------- scratch (device globals) ---------------------------------
__device__ float g_q [BATCH*SEQ*HIDDIM];          // fp32 Q proj out
__device__ float g_kv[BATCH*CLEN*NKVH*HD*2];      // fp32 KV proj out

__device__ __half g_q16[BATCH*SEQ*HIDDIM];        // Q post-rmsnorm (fp16)
__device__ __half g_k16[BATCH*NKVH*CLEN*HD];      // K post-rmsnorm (fp16)
__device__ __half g_v16[BATCH*NKVH*CLEN*HD];      // V (fp16)

__device__ __half g_a16[BATCH*SEQ*HIDDIM];        // activation buffer (x / c / attn-out)
__device__ __half g_wh [HIDDIM*HIDDIM];           // weight^T fp16

// ======================= helpers ============================================
__device__ __forceinline__ uint32_t smem_u32(const void* p) {
    uint32_t a;
    asm("{ .reg .u64 t; cvta.to.shared.u64 t, %1; cvt.u32.u64 %0, t; }" : "=r"(a) : "l"(p));
    return a;
}
__device__ __forceinline__ void cpa16(uint32_t d, const void* g) {
    asm volatile("cp.async.cg.shared.global [%0], [%1], 16;" :: "r"(d), "l"(g) : "memory");
}
#define CP_COMMIT() asm volatile("cp.async.commit_group;" ::: "memory")

__device__ __forceinline__ void ldsm4(uint32_t& r0, uint32_t& r1, uint32_t& r2, uint32_t& r3,
                                      uint32_t a) {
    asm volatile("ldmatrix.sync.aligned.m8n8.x4.shared.b16 {%0,%1,%2,%3}, [%4];"
                 : "=r"(r0), "=r"(r1), "=r"(r2), "=r"(r3) : "r"(a));
}
__device__ __forceinline__ void ldsm4t(uint32_t& r0, uint32_t& r1, uint32_t& r2, uint32_t& r3,
                                       uint32_t a) {
    asm volatile("ldmatrix.sync.aligned.m8n8.x4.trans.shared.b16 {%0,%1,%2,%3}, [%4];"
                 : "=r"(r0), "=r"(r1), "=r"(r2), "=r"(r3) : "r"(a));
}
__device__ __forceinline__ void mma16816(float* c, const uint32_t* a, uint32_t b0, uint32_t b1) {
    asm volatile(
        "mma.sync.aligned.m16n8k16.row.col.f32.f16.f16.f32 "
        "{%0,%1,%2,%3}, {%4,%5,%6,%7}, {%8,%9}, {%0,%1,%2,%3};"
        : "+f"(c[0]), "+f"(c[1]), "+f"(c[2]), "+f"(c[3])
        : "r"(a[0]), "r"(a[1]), "r"(a[2]), "r"(a[3]), "r"(b0), "r"(b1));
}
__device__ __forceinline__ uint32_t packh2(float a, float b) {
    __half2 h = __floats2half2_rn(a, b);
    return *(uint32_t*)&h;
}

// ---------------- conversion kernels ----------------------------------------
__global__ __launch_bounds__(256) void convA16_kernel(
    const float4* __restrict__ in, __half* __restrict__ o16)
{
    size_t i = (size_t)blockIdx.x * 256 + threadIdx.x;
    float4 v = in[i];
    ((__half2*)o16)[i * 2]     = __floats2half2_rn(v.x, v.y);
    ((__half2*)o16)[i * 2 + 1] = __floats2half2_rn(v.z, v.w);
}

// weight transpose -> fp16: W[K,N] fp32 -> Wt[N,K] fp16
__global__ __launch_bounds__(256) void convWT16s_kernel(
    const float* __restrict__ w, __half* __restrict__ th, int K, int N)
{
    __shared__ float s[32][33];
    int n0 = blockIdx.x * 32, k0 = blockIdx.y * 32;
    int tx = threadIdx.x & 31, ty = threadIdx.x >> 5;
#pragma unroll
    for (int i = ty; i < 32; i += 8)
        s[i][tx] = w[(size_t)(k0 + i) * N + n0 + tx];
    __syncthreads();
#pragma unroll
    for (int j = ty; j < 32; j += 8)
        th[(size_t)(n0 + j) * K + k0 + tx] = __float2half_rn(s[tx][j]);
}

// ---------------- fp16 GEMM 1-pass: C[M,N] = A[M,K] @ Wt[N,K]^T ------------
#define TP2  80
#define A_T  (128 * TP2)             // 10240
#define B_T  (256 * TP2)             // 20480
#define STB1 (A_T + B_T)             // 30720
#define NST1 3                       // 92160 B smem

__global__ __launch_bounds__(256, 1) void gemm_f16_1p_kernel(
    const __half* __restrict__ A, const __half* __restrict__ Bh,
    float* __restrict__ C, int M, int N, int K)
{
    extern __shared__ char smc[];
    const uint32_t sb = smem_u32(smc);

    const int tid  = threadIdx.x;
    const int lane = tid & 31;
    const int wid  = tid >> 5;
    const int wm   = wid & 1;
    const int wn   = wid >> 1;
    const int bm   = blockIdx.y * 128;
    const int bn   = blockIdx.x * 256;

    const int arow = tid >> 1;
    const int ahalf = tid & 1;
    const size_t gA = (size_t)(bm + arow) * K + ahalf * 16;
    const uint32_t sA = arow * TP2 + ahalf * 32;
    const size_t gB = (size_t)(bn + tid) * K;
    const uint32_t sB = tid * TP2;

    const uint32_t laneOff = (lane & 15) * TP2 + (lane >> 4) * 16;

    float acc[4][8][4];
#pragma unroll
    for (int i = 0; i < 4; i++)
#pragma unroll
        for (int j = 0; j < 8; j++)
#pragma unroll
            for (int r = 0; r < 4; r++) acc[i][j][r] = 0.f;

    const int nst = K / 32;

    auto loadStage = [&](int s, int buf) {
        uint32_t st = sb + buf * STB1;
        int k0 = s * 32;
        cpa16(st + sA,      A + gA + k0);
        cpa16(st + sA + 16, A + gA + k0 + 8);
        uint32_t bb = st + A_T + sB;
        cpa16(bb,      Bh + gB + k0);
        cpa16(bb + 16, Bh + gB + k0 + 8);
        cpa16(bb + 32, Bh + gB + k0 + 16);
        cpa16(bb + 48, Bh + gB + k0 + 24);
        CP_COMMIT();
    };

    loadStage(0, 0);
    loadStage(1, 1);

    int buf = 0;
    for (int s = 0; s < nst; ++s) {
        if (s + 1 < nst) asm volatile("cp.async.wait_group 1;" ::: "memory");
        else             asm volatile("cp.async.wait_group 0;" ::: "memory");
        __syncthreads();

        if (s + 2 < nst) loadStage(s + 2, (buf + 2) % NST1);

        uint32_t st = sb + buf * STB1;
        uint32_t aBase  = st + (wm * 64) * TP2 + laneOff;
        uint32_t bBase  = st + A_T + (wn * 64) * TP2 + laneOff;

#pragma unroll
        for (int ks = 0; ks < 2; ++ks) {
            uint32_t ko = ks * 32;
            uint32_t af[4][4];
#pragma unroll
            for (int mi = 0; mi < 4; ++mi)
                ldsm4(af[mi][0], af[mi][1], af[mi][2], af[mi][3],
                      aBase + mi * 16 * TP2 + ko);
#pragma unroll
            for (int bi = 0; bi < 4; ++bi) {
                uint32_t bf[4];
                ldsm4(bf[0], bf[1], bf[2], bf[3], bBase + bi * 16 * TP2 + ko);
#pragma unroll
                for (int mi = 0; mi < 4; ++mi) {
#pragma unroll
                    for (int sub = 0; sub < 2; ++sub)
                        mma16816(acc[mi][bi * 2 + sub], af[mi], bf[sub], bf[sub + 2]);
                }
            }
        }
        buf = (buf + 1) % NST1;
        __syncthreads();
    }

    const int g  = lane >> 2;
    const int q4 = lane & 3;
#pragma unroll
    for (int mi = 0; mi < 4; ++mi) {
#pragma unroll
        for (int nj = 0; nj < 8; ++nj) {
            int r0 = bm + wm * 64 + mi * 16 + g;
            int c0 = bn + wn * 64 + nj * 8 + q4 * 2;
            *(float2*)(C + (size_t)r0 * N + c0)       = make_float2(acc[mi][nj][0], acc[mi][nj][1]);
            *(float2*)(C + (size_t)(r0 + 8) * N + c0) = make_float2(acc[mi][nj][2], acc[mi][nj][3]);
        }
    }
}

// ---------------- per-head RMSNorm on Q -> fp16 ------------------------------
__global__ __launch_bounds__(256) void rmsnorm_q_kernel(
    const float* __restrict__ q, const float* __restrict__ w,
    __half* __restrict__ q16)
{
    int row  = blockIdx.x * 8 + (threadIdx.x >> 5);
    int lane = threadIdx.x & 31;
    float4 v = *(const float4*)(q + (size_t)row * HD + lane * 4);
    float ss = v.x * v.x + v.y * v.y + v.z * v.z + v.w * v.w;
#pragma unroll
    for (int o = 16; o > 0; o >>= 1) ss += __shfl_xor_sync(0xffffffffu, ss, o);
    float r = rsqrtf(ss * (1.f / 128.f) + EPSF);
    float4 wv = *(const float4*)(w + lane * 4);
    size_t base = (size_t)row * HD + lane * 4;
    *(__half2*)(q16 + base)     = __floats2half2_rn(v.x * r * wv.x, v.y * r * wv.y);
    *(__half2*)(q16 + base + 2) = __floats2half2_rn(v.z * r * wv.z, v.w * r * wv.w);
}

// ---------------- split packed KV -> rmsnorm K -> fp16 ----------------------
__global__ __launch_bounds__(256) void kvsplit_kernel(
    const float* __restrict__ kv, const float* __restrict__ wk,
    __half* __restrict__ k16, __half* __restrict__ v16)
{
    int row  = blockIdx.x * 8 + (threadIdx.x >> 5);  // (b*CLEN + l)*NKVH + kvh
    int lane = threadIdx.x & 31;
    int kvh  = row & 3;
    int bl_  = row >> 2;
    int b    = bl_ >> 11;
    int l    = bl_ & 2047;

    const float* base = kv + (size_t)row * 256;
    float4 f0 = *(const float4*)(base + lane * 8);
    float4 f1 = *(const float4*)(base + lane * 8 + 4);
    float k0 = f0.x, k1 = f0.z, k2 = f1.x, k3 = f1.z;
    float v0 = f0.y, v1 = f0.w, v2 = f1.y, v3 = f1.w;

    float ss = k0 * k0 + k1 * k1 + k2 * k2 + k3 * k3;
#pragma unroll
    for (int o = 16; o > 0; o >>= 1) ss += __shfl_xor_sync(0xffffffffu, ss, o);
    float r = rsqrtf(ss * (1.f / 128.f) + EPSF);

    int d0 = lane * 4;
    float4 wv = *(const float4*)(wk + d0);
    size_t ob = ((size_t)(b * NKVH + kvh) * CLEN + l) * HD + d0;

    *(__half2*)(k16 + ob)     = __floats2half2_rn(k0 * r * wv.x, k1 * r * wv.y);
    *(__half2*)(k16 + ob + 2) = __floats2half2_rn(k2 * r * wv.z, k3 * r * wv.w);
    *(__half2*)(v16 + ob)     = __floats2half2_rn(v0, v1);
    *(__half2*)(v16 + ob + 2) = __floats2half2_rn(v2, v3);
}

// ---------------- fp16 flash attention: BQ=128, BK=64 ------------------------
#define QPITCH  272
#define QBYTES  (128 * QPITCH)      // 34816
#define KVT     (64 * QPITCH)       // 17408
#define KVSTG   (2 * KVT)           // 34816: K, V
#define ATTN_SMEM (QBYTES + 2 * KVSTG)   // 104448

__global__ __launch_bounds__(256, 1) void attn_f16_kernel(
    const __half* __restrict__ q16, const __half* __restrict__ k16,
    const __half* __restrict__ v16, __half* __restrict__ o16)
{
    extern __shared__ char smc[];
    const uint32_t sb = smem_u32(smc);

    const int tid  = threadIdx.x;
    const int lane = tid & 31;
    const int wid  = tid >> 5;
    const int h    = blockIdx.y;
    const int b    = blockIdx.z;
    const int kvh  = h >> 2;
    const int s0   = blockIdx.x * 128;

    const __half* qg = q16 + ((size_t)(b * SEQ + s0) * NH + h) * HD;
    const size_t kvbase = (size_t)(b * NKVH + kvh) * CLEN * HD;

    {
        int chunk = tid & 15, r0 = tid >> 4;
#pragma unroll
        for (int it = 0; it < 8; ++it) {
            int row = r0 + it * 16;
            cpa16(sb + row * QPITCH + chunk * 16, qg + (size_t)row * HIDDIM + chunk * 8);
        }
        CP_COMMIT();
    }

    auto loadKV = [&](int blk, int stage) {
        uint32_t st = sb + QBYTES + stage * KVSTG;
        const __half* pk = k16 + kvbase + (size_t)blk * 64 * HD;
        const __half* pv = v16 + kvbase + (size_t)blk * 64 * HD;
        int chunk = tid & 15, r0 = tid >> 4;
#pragma unroll
        for (int it = 0; it < 4; ++it) {
            int row = r0 + it * 16;
            uint32_t d = st + row * QPITCH + chunk * 16;
            size_t g = (size_t)row * HD + chunk * 8;
            cpa16(d,       pk + g);
            cpa16(d + KVT, pv + g);
        }
        CP_COMMIT();
    };
    loadKV(0, 0);

    float m0 = -1e30f, m1 = -1e30f, l0 = 0.f, l1 = 0.f;
    float ofr[16][4];
#pragma unroll
    for (int f = 0; f < 16; ++f)
#pragma unroll
        for (int r = 0; r < 4; ++r) ofr[f][r] = 0.f;

    const uint32_t laneOff = (lane & 15) * QPITCH + (lane >> 4) * 16;
    const uint32_t qBase = sb + (wid * 16) * QPITCH + laneOff;

    for (int blk = 0; blk < 32; ++blk) {
        int stage = blk & 1;
        if (blk < 31) loadKV(blk + 1, stage ^ 1);
        if (blk < 31) asm volatile("cp.async.wait_group 1;" ::: "memory");
        else          asm volatile("cp.async.wait_group 0;" ::: "memory");
        __syncthreads();

        uint32_t st = sb + QBYTES + stage * KVSTG;
        uint32_t kBase = st + laneOff;
        uint32_t vBase = st + KVT + laneOff;

        // ---- S = Q K^T ----
        float sc[8][4];
#pragma unroll
        for (int j = 0; j < 8; ++j)
#pragma unroll
            for (int r = 0; r < 4; ++r) sc[j][r] = 0.f;

#pragma unroll
        for (int kc = 0; kc < 8; ++kc) {
            uint32_t qa[4];
            ldsm4(qa[0], qa[1], qa[2], qa[3], qBase + kc * 32);
#pragma unroll
            for (int kg = 0; kg < 4; ++kg) {
                uint32_t kb[4];
                ldsm4(kb[0], kb[1], kb[2], kb[3],
                      kBase + kg * 16 * QPITCH + kc * 32);
                mma16816(sc[kg * 2],     qa, kb[0], kb[2]);
                mma16816(sc[kg * 2 + 1], qa, kb[1], kb[3]);
            }
        }

        // ---- online softmax ----
        float mx0 = -1e30f, mx1 = -1e30f;
#pragma unroll
        for (int j = 0; j < 8; ++j) {
            sc[j][0] *= SCALEF; sc[j][1] *= SCALEF;
            sc[j][2] *= SCALEF; sc[j][3] *= SCALEF;
            mx0 = fmaxf(mx0, fmaxf(sc[j][0], sc[j][1]));
            mx1 = fmaxf(mx1, fmaxf(sc[j][2], sc[j][3]));
        }
        mx0 = fmaxf(mx0, __shfl_xor_sync(0xffffffffu, mx0, 1));
        mx0 = fmaxf(mx0, __shfl_xor_sync(0xffffffffu, mx0, 2));
        mx1 = fmaxf(mx1, __shfl_xor_sync(0xffffffffu, mx1, 1));
        mx1 = fmaxf(mx1, __shfl_xor_sync(0xffffffffu, mx1, 2));
        float m0n = fmaxf(m0, mx0), m1n = fmaxf(m1, mx1);
        float c0 = __expf(m0 - m0n), c1 = __expf(m1 - m1n);
        m0 = m0n; m1 = m1n;

        float rs0 = 0.f, rs1 = 0.f;
#pragma unroll
        for (int j = 0; j < 8; ++j) {
            sc[j][0] = __expf(sc[j][0] - m0); rs0 += sc[j][0];
            sc[j][1] = __expf(sc[j][1] - m0); rs0 += sc[j][1];
            sc[j][2] = __expf(sc[j][2] - m1); rs1 += sc[j][2];
            sc[j][3] = __expf(sc[j][3] - m1); rs1 += sc[j][3];
        }
        rs0 += __shfl_xor_sync(0xffffffffu, rs0, 1);
        rs0 += __shfl_xor_sync(0xffffffffu, rs0, 2);
        rs1 += __shfl_xor_sync(0xffffffffu, rs1, 1);
        rs1 += __shfl_xor_sync(0xffffffffu, rs1, 2);
        l0 = l0 * c0 + rs0;
        l1 = l1 * c1 + rs1;

#pragma unroll
        for (int f = 0; f < 16; ++f) {
            ofr[f][0] *= c0; ofr[f][1] *= c0;
            ofr[f][2] *= c1; ofr[f][3] *= c1;
        }

        // ---- P fragments ----
        uint32_t pa[4][4];
#pragma unroll
        for (int kc = 0; kc < 4; ++kc) {
#pragma unroll
            for (int half = 0; half < 2; ++half) {
                pa[kc][half * 2]     = packh2(sc[2 * kc + half][0], sc[2 * kc + half][1]);
                pa[kc][half * 2 + 1] = packh2(sc[2 * kc + half][2], sc[2 * kc + half][3]);
            }
        }

        // ---- O += P V ----
#pragma unroll
        for (int dg = 0; dg < 8; ++dg) {
#pragma unroll
            for (int kc = 0; kc < 4; ++kc) {
                uint32_t vb[4];
                ldsm4t(vb[0], vb[1], vb[2], vb[3],
                       vBase + kc * 16 * QPITCH + dg * 32);
                mma16816(ofr[dg * 2],     pa[kc], vb[0], vb[1]);
                mma16816(ofr[dg * 2 + 1], pa[kc], vb[2], vb[3]);
            }
        }
        __syncthreads();
    }

    float inv0 = 1.f / l0, inv1 = 1.f / l1;
    int rowA = b * SEQ + s0 + wid * 16 + (lane >> 2);
    int colB = h * HD + (lane & 3) * 2;
#pragma unroll
    for (int f = 0; f < 16; ++f) {
        int col = colB + f * 8;
        *(__half2*)(o16 + (size_t)rowA * HIDDIM + col) =
            __floats2half2_rn(ofr[f][0] * inv0, ofr[f][1] * inv0);
        *(__half2*)(o16 + (size_t)(rowA + 8) * HIDDIM + col) =
            __floats2half2_rn(ofr[f][2] * inv1, ofr[f][3] * inv1);
    }
}

// ---------------- launch ----------------------------------------------------
extern "C" void kernel_launch(void* const* d_in, const int* in_sizes, int n_in,
                              void* d_out, int out_size)
{
    (void)in_sizes; (void)n_in; (void)out_size;
    const float* x   = (const float*)d_in[0];
    const float* c   = (const float*)d_in[1];
    const float* wq  = (const float*)d_in[2];
    const float* wkv = (const float*)d_in[3];
    const float* wo  = (const float*)d_in[4];
    const float* nqw = (const float*)d_in[5];
    const float* nkw = (const float*)d_in[6];
    float* out = (float*)d_out;

    float *q, *kv;
    __half *q16, *k16, *v16, *a16, *wh;
    cudaGetSymbolAddress((void**)&q,   g_q);
    cudaGetSymbolAddress((void**)&kv,  g_kv);
    cudaGetSymbolAddress((void**)&q16, g_q16);
    cudaGetSymbolAddress((void**)&k16, g_k16);
    cudaGetSymbolAddress((void**)&v16, g_v16);
    cudaGetSymbolAddress((void**)&a16, g_a16);
    cudaGetSymbolAddress((void**)&wh,  g_wh);

    const int M = BATCH * SEQ;            // 4096
    const int K = HIDDIM;                 // 2048
    const int gemm1_smem = NST1 * STB1;   // 92160
    cudaFuncSetAttribute(gemm_f16_1p_kernel,
                         cudaFuncAttributeMaxDynamicSharedMemorySize, gemm1_smem);
    cudaFuncSetAttribute(attn_f16_kernel,
                         cudaFuncAttributeMaxDynamicSharedMemorySize, ATTN_SMEM);

    int convA_grid = (M * K) / 4 / 256;

    // 1) Q projection: q = x @ wq  (single-pass fp16)
    convA16_kernel<<<convA_grid, 256>>>((const float4*)x, a16);
    convWT16s_kernel<<<dim3(HIDDIM / 32, K / 32), 256>>>(wq, wh, K, HIDDIM);
    gemm_f16_1p_kernel<<<dim3(HIDDIM / 256, M / 128), 256, gemm1_smem>>>(
        a16, wh, q, M, HIDDIM, K);

    // 2) Q rmsnorm -> fp16
    rmsnorm_q_kernel<<<(M * NH) / 8, 256>>>(q, nqw, q16);

    // 3) KV projection (single-pass fp16)
    convA16_kernel<<<convA_grid, 256>>>((const float4*)c, a16);
    convWT16s_kernel<<<dim3((NKVH * HD * 2) / 32, K / 32), 256>>>(wkv, wh, K, NKVH * HD * 2);
    gemm_f16_1p_kernel<<<dim3((NKVH * HD * 2) / 256, M / 128), 256, gemm1_smem>>>(
        a16, wh, kv, M, NKVH * HD * 2, K);

    // 4) split KV -> fp16
    kvsplit_kernel<<<(BATCH * CLEN * NKVH) / 8, 256>>>(kv, nkw, k16, v16);

    // 5) fp16 attention -> fp16 activations
    attn_f16_kernel<<<dim3(SEQ / 128, NH, BATCH), 256, ATTN_SMEM>>>(
        q16, k16, v16, a16);

    // 6) output projection (single-pass fp16)
    convWT16s_kernel<<<dim3(HIDDIM / 32, K / 32), 256>>>(wo, wh, K, HIDDIM);
    gemm_f16_1p_kernel<<<dim3(HIDDIM / 256, M / 128), 256, gemm1_smem>>>(
        a16, wh, out, M, HIDDIM, K);
}

// round 9
// speedup vs baseline: 5.4523x; 1.0144x over previous
#include <cuda_runtime.h>
#include <cuda_fp16.h>
#include <math.h>
#include <stdint.h>

#define BATCH 2
#define SEQ   2048
#define CLEN  2048
#define NH    16
#define NKVH  4
#define HD    128
#define HIDDIM 2048
#define EPSF  1e-6f
#define SCALEF 0.08838834764831845f   // 1/sqrt(128)

// ---------------- scratch (device globals) ---------------------------------
__device__ __half g_x16[BATCH*SEQ*HIDDIM];        // x fp16 / attn output fp16
__device__ __half g_c16[BATCH*SEQ*HIDDIM];        // c fp16
__device__ __half g_q16[BATCH*SEQ*HIDDIM];        // Q post-rmsnorm (fp16)
__device__ __half g_k16[BATCH*NKVH*CLEN*HD];      // K post-rmsnorm (fp16)
__device__ __half g_v16[BATCH*NKVH*CLEN*HD];      // V (fp16)
__device__ __half g_wh [HIDDIM*HIDDIM];           // weight^T fp16

// ======================= helpers ============================================
__device__ __forceinline__ uint32_t smem_u32(const void* p) {
    uint32_t a;
    asm("{ .reg .u64 t; cvta.to.shared.u64 t, %1; cvt.u32.u64 %0, t; }" : "=r"(a) : "l"(p));
    return a;
}
__device__ __forceinline__ void cpa16(uint32_t d, const void* g) {
    asm volatile("cp.async.cg.shared.global [%0], [%1], 16;" :: "r"(d), "l"(g) : "memory");
}
#define CP_COMMIT() asm volatile("cp.async.commit_group;" ::: "memory")

__device__ __forceinline__ void ldsm4(uint32_t& r0, uint32_t& r1, uint32_t& r2, uint32_t& r3,
                                      uint32_t a) {
    asm volatile("ldmatrix.sync.aligned.m8n8.x4.shared.b16 {%0,%1,%2,%3}, [%4];"
                 : "=r"(r0), "=r"(r1), "=r"(r2), "=r"(r3) : "r"(a));
}
__device__ __forceinline__ void ldsm4t(uint32_t& r0, uint32_t& r1, uint32_t& r2, uint32_t& r3,
                                       uint32_t a) {
    asm volatile("ldmatrix.sync.aligned.m8n8.x4.trans.shared.b16 {%0,%1,%2,%3}, [%4];"
                 : "=r"(r0), "=r"(r1), "=r"(r2), "=r"(r3) : "r"(a));
}
__device__ __forceinline__ void mma16816(float* c, const uint32_t* a, uint32_t b0, uint32_t b1) {
    asm volatile(
        "mma.sync.aligned.m16n8k16.row.col.f32.f16.f16.f32 "
        "{%0,%1,%2,%3}, {%4,%5,%6,%7}, {%8,%9}, {%0,%1,%2,%3};"
        : "+f"(c[0]), "+f"(c[1]), "+f"(c[2]), "+f"(c[3])
        : "r"(a[0]), "r"(a[1]), "r"(a[2]), "r"(a[3]), "r"(b0), "r"(b1));
}
__device__ __forceinline__ uint32_t packh2(float a, float b) {
    __half2 h = __floats2half2_rn(a, b);
    return *(uint32_t*)&h;
}

// ---------------- conversion kernels ----------------------------------------
// dual-source fp32 -> fp16 (x and c in one launch)
__global__ __launch_bounds__(256) void convA16_dual_kernel(
    const float4* __restrict__ x, const float4* __restrict__ c,
    __half* __restrict__ xo, __half* __restrict__ co, size_t nf4)
{
    size_t i = (size_t)blockIdx.x * 256 + threadIdx.x;
    const float4* s;
    __half* d;
    size_t j;
    if (i < nf4) { s = x; d = xo; j = i; }
    else         { s = c; d = co; j = i - nf4; }
    float4 v = s[j];
    ((__half2*)d)[j * 2]     = __floats2half2_rn(v.x, v.y);
    ((__half2*)d)[j * 2 + 1] = __floats2half2_rn(v.z, v.w);
}

// weight transpose -> fp16: W[K,N] fp32 -> Wt[N,K] fp16
__global__ __launch_bounds__(256) void convWT16s_kernel(
    const float* __restrict__ w, __half* __restrict__ th, int K, int N)
{
    __shared__ float s[32][33];
    int n0 = blockIdx.x * 32, k0 = blockIdx.y * 32;
    int tx = threadIdx.x & 31, ty = threadIdx.x >> 5;
#pragma unroll
    for (int i = ty; i < 32; i += 8)
        s[i][tx] = w[(size_t)(k0 + i) * N + n0 + tx];
    __syncthreads();
#pragma unroll
    for (int j = ty; j < 32; j += 8)
        th[(size_t)(n0 + j) * K + k0 + tx] = __float2half_rn(s[tx][j]);
}

// ============ shared GEMM mainloop macro pieces =============================
#define TP2  80
#define A_T  (128 * TP2)             // 10240
#define B_T  (256 * TP2)             // 20480
#define STB1 (A_T + B_T)             // 30720
#define NST1 3                       // 92160 B smem

// Mainloop producing acc[4][8][4] for a 128x256 tile (declares locals used by epilogues)
#define GEMM_MAINLOOP(APTR, BPTR, KDIM)                                          \
    extern __shared__ char smc[];                                                \
    const uint32_t sb = smem_u32(smc);                                           \
    const int tid  = threadIdx.x;                                                \
    const int lane = tid & 31;                                                   \
    const int wid  = tid >> 5;                                                   \
    const int wm   = wid & 1;                                                    \
    const int wn   = wid >> 1;                                                   \
    const int bm   = blockIdx.y * 128;                                           \
    const int bn   = blockIdx.x * 256;                                           \
    const int arow = tid >> 1;                                                   \
    const int ahalf = tid & 1;                                                   \
    const size_t gA = (size_t)(bm + arow) * (KDIM) + ahalf * 16;                 \
    const uint32_t sA = arow * TP2 + ahalf * 32;                                 \
    const size_t gB = (size_t)(bn + tid) * (KDIM);                               \
    const uint32_t sB = tid * TP2;                                               \
    const uint32_t laneOff = (lane & 15) * TP2 + (lane >> 4) * 16;               \
    float acc[4][8][4];                                                          \
    _Pragma("unroll")                                                            \
    for (int i = 0; i < 4; i++)                                                  \
        _Pragma("unroll")                                                        \
        for (int j = 0; j < 8; j++)                                              \
            _Pragma("unroll")                                                    \
            for (int r = 0; r < 4; r++) acc[i][j][r] = 0.f;                      \
    const int nst = (KDIM) / 32;                                                 \
    auto loadStage = [&](int s, int buf) {                                       \
        uint32_t st = sb + buf * STB1;                                           \
        int k0 = s * 32;                                                         \
        cpa16(st + sA,      (APTR) + gA + k0);                                   \
        cpa16(st + sA + 16, (APTR) + gA + k0 + 8);                               \
        uint32_t bb = st + A_T + sB;                                             \
        cpa16(bb,      (BPTR) + gB + k0);                                        \
        cpa16(bb + 16, (BPTR) + gB + k0 + 8);                                    \
        cpa16(bb + 32, (BPTR) + gB + k0 + 16);                                   \
        cpa16(bb + 48, (BPTR) + gB + k0 + 24);                                   \
        CP_COMMIT();                                                             \
    };                                                                           \
    loadStage(0, 0);                                                             \
    loadStage(1, 1);                                                             \
    int buf = 0;                                                                 \
    for (int s = 0; s < nst; ++s) {                                              \
        if (s + 1 < nst) asm volatile("cp.async.wait_group 1;" ::: "memory");    \
        else             asm volatile("cp.async.wait_group 0;" ::: "memory");    \
        __syncthreads();                                                         \
        if (s + 2 < nst) loadStage(s + 2, (buf + 2) % NST1);                     \
        uint32_t st = sb + buf * STB1;                                           \
        uint32_t aBase  = st + (wm * 64) * TP2 + laneOff;                        \
        uint32_t bBase  = st + A_T + (wn * 64) * TP2 + laneOff;                  \
        _Pragma("unroll")                                                        \
        for (int ks = 0; ks < 2; ++ks) {                                         \
            uint32_t ko = ks * 32;                                               \
            uint32_t af[4][4];                                                   \
            _Pragma("unroll")                                                    \
            for (int mi = 0; mi < 4; ++mi)                                       \
                ldsm4(af[mi][0], af[mi][1], af[mi][2], af[mi][3],                \
                      aBase + mi * 16 * TP2 + ko);                               \
            _Pragma("unroll")                                                    \
            for (int bi = 0; bi < 4; ++bi) {                                     \
                uint32_t bf[4];                                                  \
                ldsm4(bf[0], bf[1], bf[2], bf[3], bBase + bi * 16 * TP2 + ko);   \
                _Pragma("unroll")                                                \
                for (int mi = 0; mi < 4; ++mi) {                                 \
                    _Pragma("unroll")                                            \
                    for (int sub = 0; sub < 2; ++sub)                            \
                        mma16816(acc[mi][bi * 2 + sub], af[mi], bf[sub], bf[sub + 2]); \
                }                                                                \
            }                                                                    \
        }                                                                        \
        buf = (buf + 1) % NST1;                                                  \
        __syncthreads();                                                         \
    }

// ---------------- plain GEMM (O-projection, fp32 out) ----------------------
__global__ __launch_bounds__(256, 1) void gemm_f16_1p_kernel(
    const __half* __restrict__ A, const __half* __restrict__ Bh,
    float* __restrict__ C, int M, int N, int K)
{
    GEMM_MAINLOOP(A, Bh, K)
    const int g  = lane >> 2;
    const int q4 = lane & 3;
#pragma unroll
    for (int mi = 0; mi < 4; ++mi) {
#pragma unroll
        for (int nj = 0; nj < 8; ++nj) {
            int r0 = bm + wm * 64 + mi * 16 + g;
            int c0 = bn + wn * 64 + nj * 8 + q4 * 2;
            *(float2*)(C + (size_t)r0 * N + c0)       = make_float2(acc[mi][nj][0], acc[mi][nj][1]);
            *(float2*)(C + (size_t)(r0 + 8) * N + c0) = make_float2(acc[mi][nj][2], acc[mi][nj][3]);
        }
    }
}

// ---------------- Q-proj GEMM with fused per-head RMSNorm -> fp16 ----------
__global__ __launch_bounds__(256, 1) void gemm_q_fused_kernel(
    const __half* __restrict__ A, const __half* __restrict__ Bh,
    const float* __restrict__ nqw, __half* __restrict__ q16, int M, int N, int K)
{
    GEMM_MAINLOOP(A, Bh, K)
    // per-row sum of squares over this tile's 128-wide head segments
    float* red = (float*)smc;   // 8 warps x 64 rows
    const int g  = lane >> 2;
    const int q4 = lane & 3;
#pragma unroll
    for (int mi = 0; mi < 4; ++mi) {
        float s0 = 0.f, s1 = 0.f;
#pragma unroll
        for (int nj = 0; nj < 8; ++nj) {
            s0 += acc[mi][nj][0] * acc[mi][nj][0] + acc[mi][nj][1] * acc[mi][nj][1];
            s1 += acc[mi][nj][2] * acc[mi][nj][2] + acc[mi][nj][3] * acc[mi][nj][3];
        }
        s0 += __shfl_xor_sync(0xffffffffu, s0, 1);
        s0 += __shfl_xor_sync(0xffffffffu, s0, 2);
        s1 += __shfl_xor_sync(0xffffffffu, s1, 1);
        s1 += __shfl_xor_sync(0xffffffffu, s1, 2);
        if (q4 == 0) {
            red[wid * 64 + mi * 16 + g]     = s0;
            red[wid * 64 + mi * 16 + g + 8] = s1;
        }
    }
    __syncthreads();

    const int dbase = ((wid >> 1) & 1) * 64;   // (wn & 1) * 64
#pragma unroll
    for (int mi = 0; mi < 4; ++mi) {
        int rl = mi * 16 + g;
        float ss0 = red[wid * 64 + rl]     + red[(wid ^ 2) * 64 + rl];
        float ss1 = red[wid * 64 + rl + 8] + red[(wid ^ 2) * 64 + rl + 8];
        float r0 = rsqrtf(ss0 * (1.f / 128.f) + EPSF);
        float r1 = rsqrtf(ss1 * (1.f / 128.f) + EPSF);
        int row0 = bm + wm * 64 + rl;
#pragma unroll
        for (int nj = 0; nj < 8; ++nj) {
            int d = dbase + nj * 8 + q4 * 2;
            float w0 = nqw[d], w1 = nqw[d + 1];
            size_t c0 = (size_t)row0 * N + bn + wn * 64 + nj * 8 + q4 * 2;
            *(__half2*)(q16 + c0) =
                __floats2half2_rn(acc[mi][nj][0] * r0 * w0, acc[mi][nj][1] * r0 * w1);
            *(__half2*)(q16 + c0 + (size_t)8 * N) =
                __floats2half2_rn(acc[mi][nj][2] * r1 * w0, acc[mi][nj][3] * r1 * w1);
        }
    }
}

// ---------------- KV-proj GEMM with fused split + K-RMSNorm -> fp16 --------
// N tile of 256 == one kvh group; even cols = K, odd cols = V.
__global__ __launch_bounds__(256, 1) void gemm_kv_fused_kernel(
    const __half* __restrict__ A, const __half* __restrict__ Bh,
    const float* __restrict__ nkw, __half* __restrict__ k16,
    __half* __restrict__ v16, int M, int N, int K)
{
    GEMM_MAINLOOP(A, Bh, K)
    float* red = (float*)smc;
    const int g  = lane >> 2;
    const int q4 = lane & 3;
#pragma unroll
    for (int mi = 0; mi < 4; ++mi) {
        float s0 = 0.f, s1 = 0.f;
#pragma unroll
        for (int nj = 0; nj < 8; ++nj) {
            s0 += acc[mi][nj][0] * acc[mi][nj][0];
            s1 += acc[mi][nj][2] * acc[mi][nj][2];
        }
        s0 += __shfl_xor_sync(0xffffffffu, s0, 1);
        s0 += __shfl_xor_sync(0xffffffffu, s0, 2);
        s1 += __shfl_xor_sync(0xffffffffu, s1, 1);
        s1 += __shfl_xor_sync(0xffffffffu, s1, 2);
        if (q4 == 0) {
            red[wid * 64 + mi * 16 + g]     = s0;
            red[wid * 64 + mi * 16 + g + 8] = s1;
        }
    }
    __syncthreads();

    const int kvh = blockIdx.x;
#pragma unroll
    for (int mi = 0; mi < 4; ++mi) {
        int rl = mi * 16 + g;
        float ss0 = red[wm * 64 + rl] + red[(2 + wm) * 64 + rl]
                  + red[(4 + wm) * 64 + rl] + red[(6 + wm) * 64 + rl];
        float ss1 = red[wm * 64 + rl + 8] + red[(2 + wm) * 64 + rl + 8]
                  + red[(4 + wm) * 64 + rl + 8] + red[(6 + wm) * 64 + rl + 8];
        float r0 = rsqrtf(ss0 * (1.f / 128.f) + EPSF);
        float r1 = rsqrtf(ss1 * (1.f / 128.f) + EPSF);
        int m0 = bm + wm * 64 + rl;
        int b0 = m0 >> 11, l0 = m0 & 2047;
        size_t base0 = ((size_t)(b0 * NKVH + kvh) * CLEN + l0) * HD;
        size_t base1 = base0 + 8 * HD;   // row + 8, same batch
#pragma unroll
        for (int nj = 0; nj < 8; ++nj) {
            int d = wn * 32 + nj * 4 + q4;
            float wk = nkw[d];
            k16[base0 + d] = __float2half_rn(acc[mi][nj][0] * r0 * wk);
            v16[base0 + d] = __float2half_rn(acc[mi][nj][1]);
            k16[base1 + d] = __float2half_rn(acc[mi][nj][2] * r1 * wk);
            v16[base1 + d] = __float2half_rn(acc[mi][nj][3]);
        }
    }
}

// ---------------- fp16 flash attention: BQ=128, BK=64 ------------------------
#define QPITCH  272
#define QBYTES  (128 * QPITCH)      // 34816
#define KVT     (64 * QPITCH)       // 17408
#define KVSTG   (2 * KVT)           // 34816: K, V
#define ATTN_SMEM (QBYTES + 2 * KVSTG)   // 104448

__global__ __launch_bounds__(256, 1) void attn_f16_kernel(
    const __half* __restrict__ q16, const __half* __restrict__ k16,
    const __half* __restrict__ v16, __half* __restrict__ o16)
{
    extern __shared__ char smc[];
    const uint32_t sb = smem_u32(smc);

    const int tid  = threadIdx.x;
    const int lane = tid & 31;
    const int wid  = tid >> 5;
    const int h    = blockIdx.y;
    const int b    = blockIdx.z;
    const int kvh  = h >> 2;
    const int s0   = blockIdx.x * 128;

    const __half* qg = q16 + ((size_t)(b * SEQ + s0) * NH + h) * HD;
    const size_t kvbase = (size_t)(b * NKVH + kvh) * CLEN * HD;

    {
        int chunk = tid & 15, r0 = tid >> 4;
#pragma unroll
        for (int it = 0; it < 8; ++it) {
            int row = r0 + it * 16;
            cpa16(sb + row * QPITCH + chunk * 16, qg + (size_t)row * HIDDIM + chunk * 8);
        }
        CP_COMMIT();
    }

    auto loadKV = [&](int blk, int stage) {
        uint32_t st = sb + QBYTES + stage * KVSTG;
        const __half* pk = k16 + kvbase + (size_t)blk * 64 * HD;
        const __half* pv = v16 + kvbase + (size_t)blk * 64 * HD;
        int chunk = tid & 15, r0 = tid >> 4;
#pragma unroll
        for (int it = 0; it < 4; ++it) {
            int row = r0 + it * 16;
            uint32_t d = st + row * QPITCH + chunk * 16;
            size_t g = (size_t)row * HD + chunk * 8;
            cpa16(d,       pk + g);
            cpa16(d + KVT, pv + g);
        }
        CP_COMMIT();
    };
    loadKV(0, 0);

    float m0 = -1e30f, m1 = -1e30f, l0 = 0.f, l1 = 0.f;
    float ofr[16][4];
#pragma unroll
    for (int f = 0; f < 16; ++f)
#pragma unroll
        for (int r = 0; r < 4; ++r) ofr[f][r] = 0.f;

    const uint32_t laneOff = (lane & 15) * QPITCH + (lane >> 4) * 16;
    const uint32_t qBase = sb + (wid * 16) * QPITCH + laneOff;

    for (int blk = 0; blk < 32; ++blk) {
        int stage = blk & 1;
        if (blk < 31) loadKV(blk + 1, stage ^ 1);
        if (blk < 31) asm volatile("cp.async.wait_group 1;" ::: "memory");
        else          asm volatile("cp.async.wait_group 0;" ::: "memory");
        __syncthreads();

        uint32_t st = sb + QBYTES + stage * KVSTG;
        uint32_t kBase = st + laneOff;
        uint32_t vBase = st + KVT + laneOff;

        // ---- S = Q K^T ----
        float sc[8][4];
#pragma unroll
        for (int j = 0; j < 8; ++j)
#pragma unroll
            for (int r = 0; r < 4; ++r) sc[j][r] = 0.f;

#pragma unroll
        for (int kc = 0; kc < 8; ++kc) {
            uint32_t qa[4];
            ldsm4(qa[0], qa[1], qa[2], qa[3], qBase + kc * 32);
#pragma unroll
            for (int kg = 0; kg < 4; ++kg) {
                uint32_t kb[4];
                ldsm4(kb[0], kb[1], kb[2], kb[3],
                      kBase + kg * 16 * QPITCH + kc * 32);
                mma16816(sc[kg * 2],     qa, kb[0], kb[2]);
                mma16816(sc[kg * 2 + 1], qa, kb[1], kb[3]);
            }
        }

        // ---- online softmax ----
        float mx0 = -1e30f, mx1 = -1e30f;
#pragma unroll
        for (int j = 0; j < 8; ++j) {
            sc[j][0] *= SCALEF; sc[j][1] *= SCALEF;
            sc[j][2] *= SCALEF; sc[j][3] *= SCALEF;
            mx0 = fmaxf(mx0, fmaxf(sc[j][0], sc[j][1]));
            mx1 = fmaxf(mx1, fmaxf(sc[j][2], sc[j][3]));
        }
        mx0 = fmaxf(mx0, __shfl_xor_sync(0xffffffffu, mx0, 1));
        mx0 = fmaxf(mx0, __shfl_xor_sync(0xffffffffu, mx0, 2));
        mx1 = fmaxf(mx1, __shfl_xor_sync(0xffffffffu, mx1, 1));
        mx1 = fmaxf(mx1, __shfl_xor_sync(0xffffffffu, mx1, 2));
        float m0n = fmaxf(m0, mx0), m1n = fmaxf(m1, mx1);
        float c0 = __expf(m0 - m0n), c1 = __expf(m1 - m1n);
        m0 = m0n; m1 = m1n;

        float rs0 = 0.f, rs1 = 0.f;
#pragma unroll
        for (int j = 0; j < 8; ++j) {
            sc[j][0] = __expf(sc[j][0] - m0); rs0 += sc[j][0];
            sc[j][1] = __expf(sc[j][1] - m0); rs0 += sc[j][1];
            sc[j][2] = __expf(sc[j][2] - m1); rs1 += sc[j][2];
            sc[j][3] = __expf(sc[j][3] - m1); rs1 += sc[j][3];
        }
        rs0 += __shfl_xor_sync(0xffffffffu, rs0, 1);
        rs0 += __shfl_xor_sync(0xffffffffu, rs0, 2);
        rs1 += __shfl_xor_sync(0xffffffffu, rs1, 1);
        rs1 += __shfl_xor_sync(0xffffffffu, rs1, 2);
        l0 = l0 * c0 + rs0;
        l1 = l1 * c1 + rs1;

#pragma unroll
        for (int f = 0; f < 16; ++f) {
            ofr[f][0] *= c0; ofr[f][1] *= c0;
            ofr[f][2] *= c1; ofr[f][3] *= c1;
        }

        // ---- P fragments ----
        uint32_t pa[4][4];
#pragma unroll
        for (int kc = 0; kc < 4; ++kc) {
#pragma unroll
            for (int half = 0; half < 2; ++half) {
                pa[kc][half * 2]     = packh2(sc[2 * kc + half][0], sc[2 * kc + half][1]);
                pa[kc][half * 2 + 1] = packh2(sc[2 * kc + half][2], sc[2 * kc + half][3]);
            }
        }

        // ---- O += P V ----
#pragma unroll
        for (int dg = 0; dg < 8; ++dg) {
#pragma unroll
            for (int kc = 0; kc < 4; ++kc) {
                uint32_t vb[4];
                ldsm4t(vb[0], vb[1], vb[2], vb[3],
                       vBase + kc * 16 * QPITCH + dg * 32);
                mma16816(ofr[dg * 2],     pa[kc], vb[0], vb[1]);
                mma16816(ofr[dg * 2 + 1], pa[kc], vb[2], vb[3]);
            }
        }
        __syncthreads();
    }

    float inv0 = 1.f / l0, inv1 = 1.f / l1;
    int rowA = b * SEQ + s0 + wid * 16 + (lane >> 2);
    int colB = h * HD + (lane & 3) * 2;
#pragma unroll
    for (int f = 0; f < 16; ++f) {
        int col = colB + f * 8;
        *(__half2*)(o16 + (size_t)rowA * HIDDIM + col) =
            __floats2half2_rn(ofr[f][0] * inv0, ofr[f][1] * inv0);
        *(__half2*)(o16 + (size_t)(rowA + 8) * HIDDIM + col) =
            __floats2half2_rn(ofr[f][2] * inv1, ofr[f][3] * inv1);
    }
}

// ---------------- launch ----------------------------------------------------
extern "C" void kernel_launch(void* const* d_in, const int* in_sizes, int n_in,
                              void* d_out, int out_size)
{
    (void)in_sizes; (void)n_in; (void)out_size;
    const float* x   = (const float*)d_in[0];
    const float* c   = (const float*)d_in[1];
    const float* wq  = (const float*)d_in[2];
    const float* wkv = (const float*)d_in[3];
    const float* wo  = (const float*)d_in[4];
    const float* nqw = (const float*)d_in[5];
    const float* nkw = (const float*)d_in[6];
    float* out = (float*)d_out;

    __half *x16, *c16, *q16, *k16, *v16, *wh;
    cudaGetSymbolAddress((void**)&x16, g_x16);
    cudaGetSymbolAddress((void**)&c16, g_c16);
    cudaGetSymbolAddress((void**)&q16, g_q16);
    cudaGetSymbolAddress((void**)&k16, g_k16);
    cudaGetSymbolAddress((void**)&v16, g_v16);
    cudaGetSymbolAddress((void**)&wh,  g_wh);

    const int M = BATCH * SEQ;            // 4096
    const int K = HIDDIM;                 // 2048
    const int gemm_smem = NST1 * STB1;    // 92160
    cudaFuncSetAttribute(gemm_f16_1p_kernel,
                         cudaFuncAttributeMaxDynamicSharedMemorySize, gemm_smem);
    cudaFuncSetAttribute(gemm_q_fused_kernel,
                         cudaFuncAttributeMaxDynamicSharedMemorySize, gemm_smem);
    cudaFuncSetAttribute(gemm_kv_fused_kernel,
                         cudaFuncAttributeMaxDynamicSharedMemorySize, gemm_smem);
    cudaFuncSetAttribute(attn_f16_kernel,
                         cudaFuncAttributeMaxDynamicSharedMemorySize, ATTN_SMEM);

    size_t nf4 = (size_t)M * K / 4;       // 2M float4 per tensor

    // 0) convert x and c to fp16 in one launch
    convA16_dual_kernel<<<(unsigned)(2 * nf4 / 256), 256>>>(
        (const float4*)x, (const float4*)c, x16, c16, nf4);

    // 1) Q projection + fused per-head rmsnorm -> q16
    convWT16s_kernel<<<dim3(HIDDIM / 32, K / 32), 256>>>(wq, wh, K, HIDDIM);
    gemm_q_fused_kernel<<<dim3(HIDDIM / 256, M / 128), 256, gemm_smem>>>(
        x16, wh, nqw, q16, M, HIDDIM, K);

    // 2) KV projection + fused split/K-rmsnorm -> k16, v16
    convWT16s_kernel<<<dim3((NKVH * HD * 2) / 32, K / 32), 256>>>(wkv, wh, K, NKVH * HD * 2);
    gemm_kv_fused_kernel<<<dim3((NKVH * HD * 2) / 256, M / 128), 256, gemm_smem>>>(
        c16, wh, nkw, k16, v16, M, NKVH * HD * 2, K);

    // 3) fp16 attention -> fp16 activations (reuse x16)
    attn_f16_kernel<<<dim3(SEQ / 128, NH, BATCH), 256, ATTN_SMEM>>>(
        q16, k16, v16, x16);

    // 4) output projection -> fp32 out
    convWT16s_kernel<<<dim3(HIDDIM / 32, K / 32), 256>>>(wo, wh, K, HIDDIM);
    gemm_f16_1p_kernel<<<dim3(HIDDIM / 256, M / 128), 256, gemm_smem>>>(
        x16, wh, out, M, HIDDIM, K);
}

// round 10
// speedup vs baseline: 5.7609x; 1.0566x over previous
#include <cuda_runtime.h>
#include <cuda_fp16.h>
#include <math.h>
#include <stdint.h>

#define BATCH 2
#define SEQ   2048
#define CLEN  2048
#define NH    16
#define NKVH  4
#define HD    128
#define HIDDIM 2048
#define EPSF  1e-6f
// 1/sqrt(128) * log2(e), folded into q16 so softmax uses raw ex2
#define QSCL  (0.08838834764831845f * 1.4426950408889634f)

// ---------------- scratch (device globals) ---------------------------------
__device__ __half g_x16[BATCH*SEQ*HIDDIM];        // x fp16 / attn output fp16
__device__ __half g_c16[BATCH*SEQ*HIDDIM];        // c fp16
__device__ __half g_q16[BATCH*SEQ*HIDDIM];        // Q post-rmsnorm (fp16, scaled)
__device__ __half g_k16[BATCH*NKVH*CLEN*HD];      // K post-rmsnorm (fp16)
__device__ __half g_v16[BATCH*NKVH*CLEN*HD];      // V (fp16)
__device__ __half g_wh [HIDDIM*HIDDIM];           // weight^T fp16

// ======================= helpers ============================================
__device__ __forceinline__ uint32_t smem_u32(const void* p) {
    uint32_t a;
    asm("{ .reg .u64 t; cvta.to.shared.u64 t, %1; cvt.u32.u64 %0, t; }" : "=r"(a) : "l"(p));
    return a;
}
__device__ __forceinline__ void cpa16(uint32_t d, const void* g) {
    asm volatile("cp.async.cg.shared.global [%0], [%1], 16;" :: "r"(d), "l"(g) : "memory");
}
#define CP_COMMIT() asm volatile("cp.async.commit_group;" ::: "memory")

__device__ __forceinline__ void ldsm4(uint32_t& r0, uint32_t& r1, uint32_t& r2, uint32_t& r3,
                                      uint32_t a) {
    asm volatile("ldmatrix.sync.aligned.m8n8.x4.shared.b16 {%0,%1,%2,%3}, [%4];"
                 : "=r"(r0), "=r"(r1), "=r"(r2), "=r"(r3) : "r"(a));
}
__device__ __forceinline__ void ldsm4t(uint32_t& r0, uint32_t& r1, uint32_t& r2, uint32_t& r3,
                                       uint32_t a) {
    asm volatile("ldmatrix.sync.aligned.m8n8.x4.trans.shared.b16 {%0,%1,%2,%3}, [%4];"
                 : "=r"(r0), "=r"(r1), "=r"(r2), "=r"(r3) : "r"(a));
}
__device__ __forceinline__ void mma16816(float* c, const uint32_t* a, uint32_t b0, uint32_t b1) {
    asm volatile(
        "mma.sync.aligned.m16n8k16.row.col.f32.f16.f16.f32 "
        "{%0,%1,%2,%3}, {%4,%5,%6,%7}, {%8,%9}, {%0,%1,%2,%3};"
        : "+f"(c[0]), "+f"(c[1]), "+f"(c[2]), "+f"(c[3])
        : "r"(a[0]), "r"(a[1]), "r"(a[2]), "r"(a[3]), "r"(b0), "r"(b1));
}
__device__ __forceinline__ uint32_t packh2(float a, float b) {
    __half2 h = __floats2half2_rn(a, b);
    return *(uint32_t*)&h;
}
__device__ __forceinline__ float ex2f(float x) {
    float y;
    asm("ex2.approx.f32 %0, %1;" : "=f"(y) : "f"(x));
    return y;
}

// ---------------- conversion kernels ----------------------------------------
__global__ __launch_bounds__(256) void convA16_dual_kernel(
    const float4* __restrict__ x, const float4* __restrict__ c,
    __half* __restrict__ xo, __half* __restrict__ co, size_t nf4)
{
    size_t i = (size_t)blockIdx.x * 256 + threadIdx.x;
    const float4* s;
    __half* d;
    size_t j;
    if (i < nf4) { s = x; d = xo; j = i; }
    else         { s = c; d = co; j = i - nf4; }
    float4 v = s[j];
    ((__half2*)d)[j * 2]     = __floats2half2_rn(v.x, v.y);
    ((__half2*)d)[j * 2 + 1] = __floats2half2_rn(v.z, v.w);
}

__global__ __launch_bounds__(256) void convWT16s_kernel(
    const float* __restrict__ w, __half* __restrict__ th, int K, int N)
{
    __shared__ float s[32][33];
    int n0 = blockIdx.x * 32, k0 = blockIdx.y * 32;
    int tx = threadIdx.x & 31, ty = threadIdx.x >> 5;
#pragma unroll
    for (int i = ty; i < 32; i += 8)
        s[i][tx] = w[(size_t)(k0 + i) * N + n0 + tx];
    __syncthreads();
#pragma unroll
    for (int j = ty; j < 32; j += 8)
        th[(size_t)(n0 + j) * K + k0 + tx] = __float2half_rn(s[tx][j]);
}

// ============ GEMM mainloop macros ==========================================
#define TP2  80
#define A_T  (128 * TP2)             // 10240
#define B_T  (256 * TP2)             // 20480
#define STB1 (A_T + B_T)             // 30720   (128x256 tile)
#define NST1 3
#define B1_T (128 * TP2)             // 10240
#define STB128 (A_T + B1_T)          // 20480   (128x128 tile)

// 128x256 tile mainloop (occ 1) — used by KV-proj fused kernel
#define GEMM_MAINLOOP(APTR, BPTR, KDIM)                                          \
    extern __shared__ char smc[];                                                \
    const uint32_t sb = smem_u32(smc);                                           \
    const int tid  = threadIdx.x;                                                \
    const int lane = tid & 31;                                                   \
    const int wid  = tid >> 5;                                                   \
    const int wm   = wid & 1;                                                    \
    const int wn   = wid >> 1;                                                   \
    const int bm   = blockIdx.y * 128;                                           \
    const int bn   = blockIdx.x * 256;                                           \
    const int arow = tid >> 1;                                                   \
    const int ahalf = tid & 1;                                                   \
    const size_t gA = (size_t)(bm + arow) * (KDIM) + ahalf * 16;                 \
    const uint32_t sA = arow * TP2 + ahalf * 32;                                 \
    const size_t gB = (size_t)(bn + tid) * (KDIM);                               \
    const uint32_t sB = tid * TP2;                                               \
    const uint32_t laneOff = (lane & 15) * TP2 + (lane >> 4) * 16;               \
    float acc[4][8][4];                                                          \
    _Pragma("unroll")                                                            \
    for (int i = 0; i < 4; i++)                                                  \
        _Pragma("unroll")                                                        \
        for (int j = 0; j < 8; j++)                                              \
            _Pragma("unroll")                                                    \
            for (int r = 0; r < 4; r++) acc[i][j][r] = 0.f;                      \
    const int nst = (KDIM) / 32;                                                 \
    auto loadStage = [&](int s, int buf) {                                       \
        uint32_t st = sb + buf * STB1;                                           \
        int k0 = s * 32;                                                         \
        cpa16(st + sA,      (APTR) + gA + k0);                                   \
        cpa16(st + sA + 16, (APTR) + gA + k0 + 8);                               \
        uint32_t bb = st + A_T + sB;                                             \
        cpa16(bb,      (BPTR) + gB + k0);                                        \
        cpa16(bb + 16, (BPTR) + gB + k0 + 8);                                    \
        cpa16(bb + 32, (BPTR) + gB + k0 + 16);                                   \
        cpa16(bb + 48, (BPTR) + gB + k0 + 24);                                   \
        CP_COMMIT();                                                             \
    };                                                                           \
    loadStage(0, 0);                                                             \
    loadStage(1, 1);                                                             \
    int buf = 0;                                                                 \
    for (int s = 0; s < nst; ++s) {                                              \
        if (s + 1 < nst) asm volatile("cp.async.wait_group 1;" ::: "memory");    \
        else             asm volatile("cp.async.wait_group 0;" ::: "memory");    \
        __syncthreads();                                                         \
        if (s + 2 < nst) loadStage(s + 2, (buf + 2) % NST1);                     \
        uint32_t st = sb + buf * STB1;                                           \
        uint32_t aBase  = st + (wm * 64) * TP2 + laneOff;                        \
        uint32_t bBase  = st + A_T + (wn * 64) * TP2 + laneOff;                  \
        _Pragma("unroll")                                                        \
        for (int ks = 0; ks < 2; ++ks) {                                         \
            uint32_t ko = ks * 32;                                               \
            uint32_t af[4][4];                                                   \
            _Pragma("unroll")                                                    \
            for (int mi = 0; mi < 4; ++mi)                                       \
                ldsm4(af[mi][0], af[mi][1], af[mi][2], af[mi][3],                \
                      aBase + mi * 16 * TP2 + ko);                               \
            _Pragma("unroll")                                                    \
            for (int bi = 0; bi < 4; ++bi) {                                     \
                uint32_t bf[4];                                                  \
                ldsm4(bf[0], bf[1], bf[2], bf[3], bBase + bi * 16 * TP2 + ko);   \
                _Pragma("unroll")                                                \
                for (int mi = 0; mi < 4; ++mi) {                                 \
                    _Pragma("unroll")                                            \
                    for (int sub = 0; sub < 2; ++sub)                            \
                        mma16816(acc[mi][bi * 2 + sub], af[mi], bf[sub], bf[sub + 2]); \
                }                                                                \
            }                                                                    \
        }                                                                        \
        buf = (buf + 1) % NST1;                                                  \
        __syncthreads();                                                         \
    }

// 128x128 tile mainloop (occ 2) — used by Q-proj and O-proj
#define GEMM_MAINLOOP128(APTR, BPTR, KDIM)                                       \
    extern __shared__ char smc[];                                                \
    const uint32_t sb = smem_u32(smc);                                           \
    const int tid  = threadIdx.x;                                                \
    const int lane = tid & 31;                                                   \
    const int wid  = tid >> 5;                                                   \
    const int wm   = wid & 1;                                                    \
    const int wn   = wid >> 1;                                                   \
    const int bm   = blockIdx.y * 128;                                           \
    const int bn   = blockIdx.x * 128;                                           \
    const int arow = tid >> 1;                                                   \
    const int ahalf = tid & 1;                                                   \
    const size_t gA = (size_t)(bm + arow) * (KDIM) + ahalf * 16;                 \
    const size_t gB = (size_t)(bn + arow) * (KDIM) + ahalf * 16;                 \
    const uint32_t sA = arow * TP2 + ahalf * 32;                                 \
    const uint32_t laneOff = (lane & 15) * TP2 + (lane >> 4) * 16;               \
    float acc[4][4][4];                                                          \
    _Pragma("unroll")                                                            \
    for (int i = 0; i < 4; i++)                                                  \
        _Pragma("unroll")                                                        \
        for (int j = 0; j < 4; j++)                                              \
            _Pragma("unroll")                                                    \
            for (int r = 0; r < 4; r++) acc[i][j][r] = 0.f;                      \
    const int nst = (KDIM) / 32;                                                 \
    auto loadStage = [&](int s, int buf) {                                       \
        uint32_t st = sb + buf * STB128;                                         \
        int k0 = s * 32;                                                         \
        cpa16(st + sA,            (APTR) + gA + k0);                             \
        cpa16(st + sA + 16,       (APTR) + gA + k0 + 8);                         \
        cpa16(st + A_T + sA,      (BPTR) + gB + k0);                             \
        cpa16(st + A_T + sA + 16, (BPTR) + gB + k0 + 8);                         \
        CP_COMMIT();                                                             \
    };                                                                           \
    loadStage(0, 0);                                                             \
    loadStage(1, 1);                                                             \
    int buf = 0;                                                                 \
    for (int s = 0; s < nst; ++s) {                                              \
        if (s + 1 < nst) asm volatile("cp.async.wait_group 1;" ::: "memory");    \
        else             asm volatile("cp.async.wait_group 0;" ::: "memory");    \
        __syncthreads();                                                         \
        if (s + 2 < nst) loadStage(s + 2, (buf + 2) % 3);                        \
        uint32_t st = sb + buf * STB128;                                         \
        uint32_t aBase  = st + (wm * 64) * TP2 + laneOff;                        \
        uint32_t bBase  = st + A_T + (wn * 32) * TP2 + laneOff;                  \
        _Pragma("unroll")                                                        \
        for (int ks = 0; ks < 2; ++ks) {                                         \
            uint32_t ko = ks * 32;                                               \
            uint32_t af[4][4];                                                   \
            _Pragma("unroll")                                                    \
            for (int mi = 0; mi < 4; ++mi)                                       \
                ldsm4(af[mi][0], af[mi][1], af[mi][2], af[mi][3],                \
                      aBase + mi * 16 * TP2 + ko);                               \
            _Pragma("unroll")                                                    \
            for (int bi = 0; bi < 2; ++bi) {                                     \
                uint32_t bf[4];                                                  \
                ldsm4(bf[0], bf[1], bf[2], bf[3], bBase + bi * 16 * TP2 + ko);   \
                _Pragma("unroll")                                                \
                for (int mi = 0; mi < 4; ++mi) {                                 \
                    _Pragma("unroll")                                            \
                    for (int sub = 0; sub < 2; ++sub)                            \
                        mma16816(acc[mi][bi * 2 + sub], af[mi], bf[sub], bf[sub + 2]); \
                }                                                                \
            }                                                                    \
        }                                                                        \
        buf = (buf + 1) % 3;                                                     \
        __syncthreads();                                                         \
    }

// ---------------- O-projection GEMM (128x128, occ 2, fp32 out) -------------
__global__ __launch_bounds__(256, 2) void gemm_o_kernel(
    const __half* __restrict__ A, const __half* __restrict__ Bh,
    float* __restrict__ C, int M, int N, int K)
{
    GEMM_MAINLOOP128(A, Bh, K)
    const int g  = lane >> 2;
    const int q4 = lane & 3;
#pragma unroll
    for (int mi = 0; mi < 4; ++mi) {
#pragma unroll
        for (int nj = 0; nj < 4; ++nj) {
            int r0 = bm + wm * 64 + mi * 16 + g;
            int c0 = bn + wn * 32 + nj * 8 + q4 * 2;
            *(float2*)(C + (size_t)r0 * N + c0)       = make_float2(acc[mi][nj][0], acc[mi][nj][1]);
            *(float2*)(C + (size_t)(r0 + 8) * N + c0) = make_float2(acc[mi][nj][2], acc[mi][nj][3]);
        }
    }
}

// ---------------- Q-proj GEMM (128x128, occ 2) + fused RMSNorm + scale -----
// One tile = one head (128 cols): reduce across the 4 N-warps.
__global__ __launch_bounds__(256, 2) void gemm_q_fused_kernel(
    const __half* __restrict__ A, const __half* __restrict__ Bh,
    const float* __restrict__ nqw, __half* __restrict__ q16, int M, int N, int K)
{
    GEMM_MAINLOOP128(A, Bh, K)
    float* red = (float*)smc;   // 8 warps x 64 rows
    const int g  = lane >> 2;
    const int q4 = lane & 3;
#pragma unroll
    for (int mi = 0; mi < 4; ++mi) {
        float s0 = 0.f, s1 = 0.f;
#pragma unroll
        for (int nj = 0; nj < 4; ++nj) {
            s0 += acc[mi][nj][0] * acc[mi][nj][0] + acc[mi][nj][1] * acc[mi][nj][1];
            s1 += acc[mi][nj][2] * acc[mi][nj][2] + acc[mi][nj][3] * acc[mi][nj][3];
        }
        s0 += __shfl_xor_sync(0xffffffffu, s0, 1);
        s0 += __shfl_xor_sync(0xffffffffu, s0, 2);
        s1 += __shfl_xor_sync(0xffffffffu, s1, 1);
        s1 += __shfl_xor_sync(0xffffffffu, s1, 2);
        if (q4 == 0) {
            red[wid * 64 + mi * 16 + g]     = s0;
            red[wid * 64 + mi * 16 + g + 8] = s1;
        }
    }
    __syncthreads();

#pragma unroll
    for (int mi = 0; mi < 4; ++mi) {
        int rl = mi * 16 + g;
        float ss0 = red[wm * 64 + rl] + red[(2 + wm) * 64 + rl]
                  + red[(4 + wm) * 64 + rl] + red[(6 + wm) * 64 + rl];
        float ss1 = red[wm * 64 + rl + 8] + red[(2 + wm) * 64 + rl + 8]
                  + red[(4 + wm) * 64 + rl + 8] + red[(6 + wm) * 64 + rl + 8];
        float r0 = rsqrtf(ss0 * (1.f / 128.f) + EPSF) * QSCL;
        float r1 = rsqrtf(ss1 * (1.f / 128.f) + EPSF) * QSCL;
        int row0 = bm + wm * 64 + rl;
#pragma unroll
        for (int nj = 0; nj < 4; ++nj) {
            int d = wn * 32 + nj * 8 + q4 * 2;
            float w0 = nqw[d], w1 = nqw[d + 1];
            size_t c0 = (size_t)row0 * N + bn + d;
            *(__half2*)(q16 + c0) =
                __floats2half2_rn(acc[mi][nj][0] * r0 * w0, acc[mi][nj][1] * r0 * w1);
            *(__half2*)(q16 + c0 + (size_t)8 * N) =
                __floats2half2_rn(acc[mi][nj][2] * r1 * w0, acc[mi][nj][3] * r1 * w1);
        }
    }
}

// ---------------- KV-proj GEMM (128x256, occ 1) + fused split/K-norm -------
__global__ __launch_bounds__(256, 1) void gemm_kv_fused_kernel(
    const __half* __restrict__ A, const __half* __restrict__ Bh,
    const float* __restrict__ nkw, __half* __restrict__ k16,
    __half* __restrict__ v16, int M, int N, int K)
{
    GEMM_MAINLOOP(A, Bh, K)
    float* red = (float*)smc;
    const int g  = lane >> 2;
    const int q4 = lane & 3;
#pragma unroll
    for (int mi = 0; mi < 4; ++mi) {
        float s0 = 0.f, s1 = 0.f;
#pragma unroll
        for (int nj = 0; nj < 8; ++nj) {
            s0 += acc[mi][nj][0] * acc[mi][nj][0];
            s1 += acc[mi][nj][2] * acc[mi][nj][2];
        }
        s0 += __shfl_xor_sync(0xffffffffu, s0, 1);
        s0 += __shfl_xor_sync(0xffffffffu, s0, 2);
        s1 += __shfl_xor_sync(0xffffffffu, s1, 1);
        s1 += __shfl_xor_sync(0xffffffffu, s1, 2);
        if (q4 == 0) {
            red[wid * 64 + mi * 16 + g]     = s0;
            red[wid * 64 + mi * 16 + g + 8] = s1;
        }
    }
    __syncthreads();

    const int kvh = blockIdx.x;
#pragma unroll
    for (int mi = 0; mi < 4; ++mi) {
        int rl = mi * 16 + g;
        float ss0 = red[wm * 64 + rl] + red[(2 + wm) * 64 + rl]
                  + red[(4 + wm) * 64 + rl] + red[(6 + wm) * 64 + rl];
        float ss1 = red[wm * 64 + rl + 8] + red[(2 + wm) * 64 + rl + 8]
                  + red[(4 + wm) * 64 + rl + 8] + red[(6 + wm) * 64 + rl + 8];
        float r0 = rsqrtf(ss0 * (1.f / 128.f) + EPSF);
        float r1 = rsqrtf(ss1 * (1.f / 128.f) + EPSF);
        int m0 = bm + wm * 64 + rl;
        int b0 = m0 >> 11, l0 = m0 & 2047;
        size_t base0 = ((size_t)(b0 * NKVH + kvh) * CLEN + l0) * HD;
        size_t base1 = base0 + 8 * HD;
#pragma unroll
        for (int nj = 0; nj < 8; ++nj) {
            int d = wn * 32 + nj * 4 + q4;
            float wk = nkw[d];
            k16[base0 + d] = __float2half_rn(acc[mi][nj][0] * r0 * wk);
            v16[base0 + d] = __float2half_rn(acc[mi][nj][1]);
            k16[base1 + d] = __float2half_rn(acc[mi][nj][2] * r1 * wk);
            v16[base1 + d] = __float2half_rn(acc[mi][nj][3]);
        }
    }
}

// ---------------- fp16 flash attention: BQ=128, BK=64, pipelined QK --------
#define QPITCH  272
#define QBYTES  (128 * QPITCH)      // 34816
#define KVT     (64 * QPITCH)       // 17408
#define KVSTG   (2 * KVT)           // 34816: K, V
#define NKVS    3
#define ATTN_SMEM (QBYTES + NKVS * KVSTG)   // 139264

__global__ __launch_bounds__(256, 1) void attn_f16_kernel(
    const __half* __restrict__ q16, const __half* __restrict__ k16,
    const __half* __restrict__ v16, __half* __restrict__ o16)
{
    extern __shared__ char smc[];
    const uint32_t sb = smem_u32(smc);

    const int tid  = threadIdx.x;
    const int lane = tid & 31;
    const int wid  = tid >> 5;
    const int h    = blockIdx.y;
    const int b    = blockIdx.z;
    const int kvh  = h >> 2;
    const int s0   = blockIdx.x * 128;

    const __half* qg = q16 + ((size_t)(b * SEQ + s0) * NH + h) * HD;
    const size_t kvbase = (size_t)(b * NKVH + kvh) * CLEN * HD;

    // Q resident tile (group 0)
    {
        int chunk = tid & 15, r0 = tid >> 4;
#pragma unroll
        for (int it = 0; it < 8; ++it) {
            int row = r0 + it * 16;
            cpa16(sb + row * QPITCH + chunk * 16, qg + (size_t)row * HIDDIM + chunk * 8);
        }
        CP_COMMIT();
    }

    auto loadKV = [&](int blk, int stage) {
        uint32_t st = sb + QBYTES + stage * KVSTG;
        const __half* pk = k16 + kvbase + (size_t)blk * 64 * HD;
        const __half* pv = v16 + kvbase + (size_t)blk * 64 * HD;
        int chunk = tid & 15, r0 = tid >> 4;
#pragma unroll
        for (int it = 0; it < 4; ++it) {
            int row = r0 + it * 16;
            uint32_t d = st + row * QPITCH + chunk * 16;
            size_t g = (size_t)row * HD + chunk * 8;
            cpa16(d,       pk + g);
            cpa16(d + KVT, pv + g);
        }
        CP_COMMIT();
    };
    loadKV(0, 0);   // group 1
    loadKV(1, 1);   // group 2

    float m0 = -1e30f, m1 = -1e30f, l0 = 0.f, l1 = 0.f;
    float ofr[16][4];
#pragma unroll
    for (int f = 0; f < 16; ++f)
#pragma unroll
        for (int r = 0; r < 4; ++r) ofr[f][r] = 0.f;

    const uint32_t laneOff = (lane & 15) * QPITCH + (lane >> 4) * 16;
    const uint32_t qBase = sb + (wid * 16) * QPITCH + laneOff;

    float scA[8][4], scB[8][4];

// S(blk) = Q K^T into SC from K stage STG (scores pre-scaled via q16)
#define QK_BLOCK(SC, STG) do {                                                   \
    uint32_t kB_ = sb + QBYTES + (STG) * KVSTG + laneOff;                        \
    _Pragma("unroll")                                                            \
    for (int j = 0; j < 8; ++j) {                                                \
        SC[j][0] = 0.f; SC[j][1] = 0.f; SC[j][2] = 0.f; SC[j][3] = 0.f;          \
    }                                                                            \
    _Pragma("unroll")                                                            \
    for (int kc = 0; kc < 8; ++kc) {                                             \
        uint32_t qa[4];                                                          \
        ldsm4(qa[0], qa[1], qa[2], qa[3], qBase + kc * 32);                      \
        _Pragma("unroll")                                                        \
        for (int kg = 0; kg < 4; ++kg) {                                         \
            uint32_t kb[4];                                                      \
            ldsm4(kb[0], kb[1], kb[2], kb[3], kB_ + kg * 16 * QPITCH + kc * 32); \
            mma16816(SC[kg * 2],     qa, kb[0], kb[2]);                          \
            mma16816(SC[kg * 2 + 1], qa, kb[1], kb[3]);                          \
        }                                                                        \
    }                                                                            \
} while (0)

// online softmax + PV for block BLK using scores SC (base-2 exp)
#define SOFTPV(SC, BLK) do {                                                     \
    float mx0 = -1e30f, mx1 = -1e30f;                                            \
    _Pragma("unroll")                                                            \
    for (int j = 0; j < 8; ++j) {                                                \
        mx0 = fmaxf(mx0, fmaxf(SC[j][0], SC[j][1]));                             \
        mx1 = fmaxf(mx1, fmaxf(SC[j][2], SC[j][3]));                             \
    }                                                                            \
    mx0 = fmaxf(mx0, __shfl_xor_sync(0xffffffffu, mx0, 1));                      \
    mx0 = fmaxf(mx0, __shfl_xor_sync(0xffffffffu, mx0, 2));                      \
    mx1 = fmaxf(mx1, __shfl_xor_sync(0xffffffffu, mx1, 1));                      \
    mx1 = fmaxf(mx1, __shfl_xor_sync(0xffffffffu, mx1, 2));                      \
    float m0n = fmaxf(m0, mx0), m1n = fmaxf(m1, mx1);                            \
    float c0 = ex2f(m0 - m0n), c1 = ex2f(m1 - m1n);                              \
    m0 = m0n; m1 = m1n;                                                          \
    float rs0 = 0.f, rs1 = 0.f;                                                  \
    _Pragma("unroll")                                                            \
    for (int j = 0; j < 8; ++j) {                                                \
        SC[j][0] = ex2f(SC[j][0] - m0); rs0 += SC[j][0];                         \
        SC[j][1] = ex2f(SC[j][1] - m0); rs0 += SC[j][1];                         \
        SC[j][2] = ex2f(SC[j][2] - m1); rs1 += SC[j][2];                         \
        SC[j][3] = ex2f(SC[j][3] - m1); rs1 += SC[j][3];                         \
    }                                                                            \
    rs0 += __shfl_xor_sync(0xffffffffu, rs0, 1);                                 \
    rs0 += __shfl_xor_sync(0xffffffffu, rs0, 2);                                 \
    rs1 += __shfl_xor_sync(0xffffffffu, rs1, 1);                                 \
    rs1 += __shfl_xor_sync(0xffffffffu, rs1, 2);                                 \
    l0 = l0 * c0 + rs0;                                                          \
    l1 = l1 * c1 + rs1;                                                          \
    _Pragma("unroll")                                                            \
    for (int f = 0; f < 16; ++f) {                                               \
        ofr[f][0] *= c0; ofr[f][1] *= c0;                                        \
        ofr[f][2] *= c1; ofr[f][3] *= c1;                                        \
    }                                                                            \
    uint32_t pa[4][4];                                                           \
    _Pragma("unroll")                                                            \
    for (int kc = 0; kc < 4; ++kc) {                                             \
        _Pragma("unroll")                                                        \
        for (int hf = 0; hf < 2; ++hf) {                                         \
            pa[kc][hf * 2]     = packh2(SC[2 * kc + hf][0], SC[2 * kc + hf][1]); \
            pa[kc][hf * 2 + 1] = packh2(SC[2 * kc + hf][2], SC[2 * kc + hf][3]); \
        }                                                                        \
    }                                                                            \
    uint32_t vB_ = sb + QBYTES + ((BLK) % 3) * KVSTG + KVT + laneOff;            \
    _Pragma("unroll")                                                            \
    for (int dg = 0; dg < 8; ++dg) {                                             \
        _Pragma("unroll")                                                        \
        for (int kc = 0; kc < 4; ++kc) {                                         \
            uint32_t vb[4];                                                      \
            ldsm4t(vb[0], vb[1], vb[2], vb[3], vB_ + kc * 16 * QPITCH + dg * 32);\
            mma16816(ofr[dg * 2],     pa[kc], vb[0], vb[1]);                     \
            mma16816(ofr[dg * 2 + 1], pa[kc], vb[2], vb[3]);                     \
        }                                                                        \
    }                                                                            \
} while (0)

    asm volatile("cp.async.wait_group 1;" ::: "memory");   // Q + K0 done
    __syncthreads();
    QK_BLOCK(scA, 0);

    for (int blk = 0; blk < 32; blk += 2) {
        // even block: scores in scA, prefetch scB
        if (blk < 30) {
            loadKV(blk + 2, (blk + 2) % 3);
            asm volatile("cp.async.wait_group 1;" ::: "memory");
        } else {
            asm volatile("cp.async.wait_group 0;" ::: "memory");
        }
        __syncthreads();
        if (blk < 31) QK_BLOCK(scB, (blk + 1) % 3);
        SOFTPV(scA, blk);
        __syncthreads();

        // odd block
        int bo = blk + 1;
        if (bo < 30) {
            loadKV(bo + 2, (bo + 2) % 3);
            asm volatile("cp.async.wait_group 1;" ::: "memory");
        } else if (bo == 30) {
            asm volatile("cp.async.wait_group 0;" ::: "memory");
        }
        __syncthreads();
        if (bo < 31) QK_BLOCK(scA, (bo + 1) % 3);
        SOFTPV(scB, bo);
        __syncthreads();
    }

    float inv0 = 1.f / l0, inv1 = 1.f / l1;
    int rowA = b * SEQ + s0 + wid * 16 + (lane >> 2);
    int colB = h * HD + (lane & 3) * 2;
#pragma unroll
    for (int f = 0; f < 16; ++f) {
        int col = colB + f * 8;
        *(__half2*)(o16 + (size_t)rowA * HIDDIM + col) =
            __floats2half2_rn(ofr[f][0] * inv0, ofr[f][1] * inv0);
        *(__half2*)(o16 + (size_t)(rowA + 8) * HIDDIM + col) =
            __floats2half2_rn(ofr[f][2] * inv1, ofr[f][3] * inv1);
    }
}

// ---------------- launch ----------------------------------------------------
extern "C" void kernel_launch(void* const* d_in, const int* in_sizes, int n_in,
                              void* d_out, int out_size)
{
    (void)in_sizes; (void)n_in; (void)out_size;
    const float* x   = (const float*)d_in[0];
    const float* c   = (const float*)d_in[1];
    const float* wq  = (const float*)d_in[2];
    const float* wkv = (const float*)d_in[3];
    const float* wo  = (const float*)d_in[4];
    const float* nqw = (const float*)d_in[5];
    const float* nkw = (const float*)d_in[6];
    float* out = (float*)d_out;

    __half *x16, *c16, *q16, *k16, *v16, *wh;
    cudaGetSymbolAddress((void**)&x16, g_x16);
    cudaGetSymbolAddress((void**)&c16, g_c16);
    cudaGetSymbolAddress((void**)&q16, g_q16);
    cudaGetSymbolAddress((void**)&k16, g_k16);
    cudaGetSymbolAddress((void**)&v16, g_v16);
    cudaGetSymbolAddress((void**)&wh,  g_wh);

    const int M = BATCH * SEQ;            // 4096
    const int K = HIDDIM;                 // 2048
    const int gemm256_smem = NST1 * STB1; // 92160
    const int gemm128_smem = 3 * STB128;  // 61440
    cudaFuncSetAttribute(gemm_q_fused_kernel,
                         cudaFuncAttributeMaxDynamicSharedMemorySize, gemm128_smem);
    cudaFuncSetAttribute(gemm_o_kernel,
                         cudaFuncAttributeMaxDynamicSharedMemorySize, gemm128_smem);
    cudaFuncSetAttribute(gemm_kv_fused_kernel,
                         cudaFuncAttributeMaxDynamicSharedMemorySize, gemm256_smem);
    cudaFuncSetAttribute(attn_f16_kernel,
                         cudaFuncAttributeMaxDynamicSharedMemorySize, ATTN_SMEM);

    size_t nf4 = (size_t)M * K / 4;

    // 0) convert x and c to fp16
    convA16_dual_kernel<<<(unsigned)(2 * nf4 / 256), 256>>>(
        (const float4*)x, (const float4*)c, x16, c16, nf4);

    // 1) Q projection + fused rmsnorm + softmax-scale fold (128x128, occ 2)
    convWT16s_kernel<<<dim3(HIDDIM / 32, K / 32), 256>>>(wq, wh, K, HIDDIM);
    gemm_q_fused_kernel<<<dim3(HIDDIM / 128, M / 128), 256, gemm128_smem>>>(
        x16, wh, nqw, q16, M, HIDDIM, K);

    // 2) KV projection + fused split/K-rmsnorm (128x256, occ 1)
    convWT16s_kernel<<<dim3((NKVH * HD * 2) / 32, K / 32), 256>>>(wkv, wh, K, NKVH * HD * 2);
    gemm_kv_fused_kernel<<<dim3((NKVH * HD * 2) / 256, M / 128), 256, gemm256_smem>>>(
        c16, wh, nkw, k16, v16, M, NKVH * HD * 2, K);

    // 3) pipelined fp16 attention -> fp16 activations (reuse x16)
    attn_f16_kernel<<<dim3(SEQ / 128, NH, BATCH), 256, ATTN_SMEM>>>(
        q16, k16, v16, x16);

    // 4) output projection (128x128, occ 2) -> fp32 out
    convWT16s_kernel<<<dim3(HIDDIM / 32, K / 32), 256>>>(wo, wh, K, HIDDIM);
    gemm_o_kernel<<<dim3(HIDDIM / 128, M / 128), 256, gemm128_smem>>>(
        x16, wh, out, M, HIDDIM, K);
}

// round 11
// speedup vs baseline: 5.8075x; 1.0081x over previous
#include <cuda_runtime.h>
#include <cuda_fp16.h>
#include <math.h>
#include <stdint.h>

#define BATCH 2
#define SEQ   2048
#define CLEN  2048
#define NH    16
#define NKVH  4
#define HD    128
#define HIDDIM 2048
#define EPSF  1e-6f
// 1/sqrt(128) * log2(e), folded into q16 so softmax uses raw ex2
#define QSCL  (0.08838834764831845f * 1.4426950408889634f)

// ---------------- scratch (device globals) ---------------------------------
__device__ __half g_x16[BATCH*SEQ*HIDDIM];        // x fp16 / attn output fp16
__device__ __half g_c16[BATCH*SEQ*HIDDIM];        // c fp16
__device__ __half g_q16[BATCH*SEQ*HIDDIM];        // Q post-rmsnorm (fp16, scaled)
__device__ __half g_k16[BATCH*NKVH*CLEN*HD];      // K post-rmsnorm (fp16)
__device__ __half g_v16[BATCH*NKVH*CLEN*HD];      // V (fp16)
__device__ __half g_wqT [HIDDIM*HIDDIM];          // wq^T fp16
__device__ __half g_wkvT[HIDDIM*NKVH*HD*2];       // wkv^T fp16
__device__ __half g_woT [HIDDIM*HIDDIM];          // wo^T fp16

// ======================= helpers ============================================
__device__ __forceinline__ uint32_t smem_u32(const void* p) {
    uint32_t a;
    asm("{ .reg .u64 t; cvta.to.shared.u64 t, %1; cvt.u32.u64 %0, t; }" : "=r"(a) : "l"(p));
    return a;
}
__device__ __forceinline__ void cpa16(uint32_t d, const void* g) {
    asm volatile("cp.async.cg.shared.global [%0], [%1], 16;" :: "r"(d), "l"(g) : "memory");
}
#define CP_COMMIT() asm volatile("cp.async.commit_group;" ::: "memory")

__device__ __forceinline__ void ldsm4(uint32_t& r0, uint32_t& r1, uint32_t& r2, uint32_t& r3,
                                      uint32_t a) {
    asm volatile("ldmatrix.sync.aligned.m8n8.x4.shared.b16 {%0,%1,%2,%3}, [%4];"
                 : "=r"(r0), "=r"(r1), "=r"(r2), "=r"(r3) : "r"(a));
}
__device__ __forceinline__ void ldsm4t(uint32_t& r0, uint32_t& r1, uint32_t& r2, uint32_t& r3,
                                       uint32_t a) {
    asm volatile("ldmatrix.sync.aligned.m8n8.x4.trans.shared.b16 {%0,%1,%2,%3}, [%4];"
                 : "=r"(r0), "=r"(r1), "=r"(r2), "=r"(r3) : "r"(a));
}
__device__ __forceinline__ void mma16816(float* c, const uint32_t* a, uint32_t b0, uint32_t b1) {
    asm volatile(
        "mma.sync.aligned.m16n8k16.row.col.f32.f16.f16.f32 "
        "{%0,%1,%2,%3}, {%4,%5,%6,%7}, {%8,%9}, {%0,%1,%2,%3};"
        : "+f"(c[0]), "+f"(c[1]), "+f"(c[2]), "+f"(c[3])
        : "r"(a[0]), "r"(a[1]), "r"(a[2]), "r"(a[3]), "r"(b0), "r"(b1));
}
__device__ __forceinline__ uint32_t packh2(float a, float b) {
    __half2 h = __floats2half2_rn(a, b);
    return *(uint32_t*)&h;
}
__device__ __forceinline__ float ex2f(float x) {
    float y;
    asm("ex2.approx.f32 %0, %1;" : "=f"(y) : "f"(x));
    return y;
}

// ---------------- fused prep kernel: all conversions in one launch ----------
// blocks [0, 16384): x/c fp32->fp16 (8192 each)
// blocks [16384, 20480): wq transpose  (64x64 tiles of 32)
// blocks [20480, 22528): wkv transpose (32x64 tiles)
// blocks [22528, 26624): wo transpose  (64x64 tiles)
#define NF4 ((size_t)BATCH * SEQ * HIDDIM / 4)    // 2M float4 per activation

__global__ __launch_bounds__(256) void prep_kernel(
    const float4* __restrict__ x, const float4* __restrict__ c,
    const float* __restrict__ wq, const float* __restrict__ wkv,
    const float* __restrict__ wo,
    __half* __restrict__ x16, __half* __restrict__ c16,
    __half* __restrict__ wqT, __half* __restrict__ wkvT, __half* __restrict__ woT)
{
    __shared__ float s[32][33];
    int bid = blockIdx.x;

    if (bid < 16384) {
        size_t i = (size_t)bid * 256 + threadIdx.x;
        const float4* src; __half* dst; size_t j;
        if (i < NF4) { src = x; dst = x16; j = i; }
        else         { src = c; dst = c16; j = i - NF4; }
        float4 v = src[j];
        ((__half2*)dst)[j * 2]     = __floats2half2_rn(v.x, v.y);
        ((__half2*)dst)[j * 2 + 1] = __floats2half2_rn(v.z, v.w);
        return;
    }
    bid -= 16384;

    const float* w; __half* o; int N;
    if (bid < 4096)      {              w = wq;  o = wqT;  N = HIDDIM; }
    else if (bid < 6144) { bid -= 4096; w = wkv; o = wkvT; N = NKVH * HD * 2; }
    else                 { bid -= 6144; w = wo;  o = woT;  N = HIDDIM; }

    const int K = HIDDIM;
    int nb = N / 32;
    int n0 = (bid % nb) * 32, k0 = (bid / nb) * 32;
    int tx = threadIdx.x & 31, ty = threadIdx.x >> 5;
#pragma unroll
    for (int i = ty; i < 32; i += 8)
        s[i][tx] = w[(size_t)(k0 + i) * N + n0 + tx];
    __syncthreads();
#pragma unroll
    for (int j = ty; j < 32; j += 8)
        o[(size_t)(n0 + j) * K + k0 + tx] = __float2half_rn(s[tx][j]);
}

// ============ GEMM mainloop macros ==========================================
#define TP2  80
#define A_T  (128 * TP2)             // 10240
#define B_T  (256 * TP2)             // 20480
#define STB1 (A_T + B_T)             // 30720   (128x256 tile)
#define NST1 3
#define B1_T (128 * TP2)             // 10240
#define STB128 (A_T + B1_T)          // 20480   (128x128 tile)

// 128x256 tile mainloop (occ 1) — used by KV-proj fused kernel
#define GEMM_MAINLOOP(APTR, BPTR, KDIM)                                          \
    extern __shared__ char smc[];                                                \
    const uint32_t sb = smem_u32(smc);                                           \
    const int tid  = threadIdx.x;                                                \
    const int lane = tid & 31;                                                   \
    const int wid  = tid >> 5;                                                   \
    const int wm   = wid & 1;                                                    \
    const int wn   = wid >> 1;                                                   \
    const int bm   = blockIdx.y * 128;                                           \
    const int bn   = blockIdx.x * 256;                                           \
    const int arow = tid >> 1;                                                   \
    const int ahalf = tid & 1;                                                   \
    const size_t gA = (size_t)(bm + arow) * (KDIM) + ahalf * 16;                 \
    const uint32_t sA = arow * TP2 + ahalf * 32;                                 \
    const size_t gB = (size_t)(bn + tid) * (KDIM);                               \
    const uint32_t sB = tid * TP2;                                               \
    const uint32_t laneOff = (lane & 15) * TP2 + (lane >> 4) * 16;               \
    float acc[4][8][4];                                                          \
    _Pragma("unroll")                                                            \
    for (int i = 0; i < 4; i++)                                                  \
        _Pragma("unroll")                                                        \
        for (int j = 0; j < 8; j++)                                              \
            _Pragma("unroll")                                                    \
            for (int r = 0; r < 4; r++) acc[i][j][r] = 0.f;                      \
    const int nst = (KDIM) / 32;                                                 \
    auto loadStage = [&](int s, int buf) {                                       \
        uint32_t st = sb + buf * STB1;                                           \
        int k0 = s * 32;                                                         \
        cpa16(st + sA,      (APTR) + gA + k0);                                   \
        cpa16(st + sA + 16, (APTR) + gA + k0 + 8);                               \
        uint32_t bb = st + A_T + sB;                                             \
        cpa16(bb,      (BPTR) + gB + k0);                                        \
        cpa16(bb + 16, (BPTR) + gB + k0 + 8);                                    \
        cpa16(bb + 32, (BPTR) + gB + k0 + 16);                                   \
        cpa16(bb + 48, (BPTR) + gB + k0 + 24);                                   \
        CP_COMMIT();                                                             \
    };                                                                           \
    loadStage(0, 0);                                                             \
    loadStage(1, 1);                                                             \
    int buf = 0;                                                                 \
    for (int s = 0; s < nst; ++s) {                                              \
        if (s + 1 < nst) asm volatile("cp.async.wait_group 1;" ::: "memory");    \
        else             asm volatile("cp.async.wait_group 0;" ::: "memory");    \
        __syncthreads();                                                         \
        if (s + 2 < nst) loadStage(s + 2, (buf + 2) % NST1);                     \
        uint32_t st = sb + buf * STB1;                                           \
        uint32_t aBase  = st + (wm * 64) * TP2 + laneOff;                        \
        uint32_t bBase  = st + A_T + (wn * 64) * TP2 + laneOff;                  \
        _Pragma("unroll")                                                        \
        for (int ks = 0; ks < 2; ++ks) {                                         \
            uint32_t ko = ks * 32;                                               \
            uint32_t af[4][4];                                                   \
            _Pragma("unroll")                                                    \
            for (int mi = 0; mi < 4; ++mi)                                       \
                ldsm4(af[mi][0], af[mi][1], af[mi][2], af[mi][3],                \
                      aBase + mi * 16 * TP2 + ko);                               \
            _Pragma("unroll")                                                    \
            for (int bi = 0; bi < 4; ++bi) {                                     \
                uint32_t bf[4];                                                  \
                ldsm4(bf[0], bf[1], bf[2], bf[3], bBase + bi * 16 * TP2 + ko);   \
                _Pragma("unroll")                                                \
                for (int mi = 0; mi < 4; ++mi) {                                 \
                    _Pragma("unroll")                                            \
                    for (int sub = 0; sub < 2; ++sub)                            \
                        mma16816(acc[mi][bi * 2 + sub], af[mi], bf[sub], bf[sub + 2]); \
                }                                                                \
            }                                                                    \
        }                                                                        \
        buf = (buf + 1) % NST1;                                                  \
        __syncthreads();                                                         \
    }

// 128x128 tile mainloop (occ 2) — used by Q-proj and O-proj
#define GEMM_MAINLOOP128(APTR, BPTR, KDIM)                                       \
    extern __shared__ char smc[];                                                \
    const uint32_t sb = smem_u32(smc);                                           \
    const int tid  = threadIdx.x;                                                \
    const int lane = tid & 31;                                                   \
    const int wid  = tid >> 5;                                                   \
    const int wm   = wid & 1;                                                    \
    const int wn   = wid >> 1;                                                   \
    const int bm   = blockIdx.y * 128;                                           \
    const int bn   = blockIdx.x * 128;                                           \
    const int arow = tid >> 1;                                                   \
    const int ahalf = tid & 1;                                                   \
    const size_t gA = (size_t)(bm + arow) * (KDIM) + ahalf * 16;                 \
    const size_t gB = (size_t)(bn + arow) * (KDIM) + ahalf * 16;                 \
    const uint32_t sA = arow * TP2 + ahalf * 32;                                 \
    const uint32_t laneOff = (lane & 15) * TP2 + (lane >> 4) * 16;               \
    float acc[4][4][4];                                                          \
    _Pragma("unroll")                                                            \
    for (int i = 0; i < 4; i++)                                                  \
        _Pragma("unroll")                                                        \
        for (int j = 0; j < 4; j++)                                              \
            _Pragma("unroll")                                                    \
            for (int r = 0; r < 4; r++) acc[i][j][r] = 0.f;                      \
    const int nst = (KDIM) / 32;                                                 \
    auto loadStage = [&](int s, int buf) {                                       \
        uint32_t st = sb + buf * STB128;                                         \
        int k0 = s * 32;                                                         \
        cpa16(st + sA,            (APTR) + gA + k0);                             \
        cpa16(st + sA + 16,       (APTR) + gA + k0 + 8);                         \
        cpa16(st + A_T + sA,      (BPTR) + gB + k0);                             \
        cpa16(st + A_T + sA + 16, (BPTR) + gB + k0 + 8);                         \
        CP_COMMIT();                                                             \
    };                                                                           \
    loadStage(0, 0);                                                             \
    loadStage(1, 1);                                                             \
    int buf = 0;                                                                 \
    for (int s = 0; s < nst; ++s) {                                              \
        if (s + 1 < nst) asm volatile("cp.async.wait_group 1;" ::: "memory");    \
        else             asm volatile("cp.async.wait_group 0;" ::: "memory");    \
        __syncthreads();                                                         \
        if (s + 2 < nst) loadStage(s + 2, (buf + 2) % 3);                        \
        uint32_t st = sb + buf * STB128;                                         \
        uint32_t aBase  = st + (wm * 64) * TP2 + laneOff;                        \
        uint32_t bBase  = st + A_T + (wn * 32) * TP2 + laneOff;                  \
        _Pragma("unroll")                                                        \
        for (int ks = 0; ks < 2; ++ks) {                                         \
            uint32_t ko = ks * 32;                                               \
            uint32_t af[4][4];                                                   \
            _Pragma("unroll")                                                    \
            for (int mi = 0; mi < 4; ++mi)                                       \
                ldsm4(af[mi][0], af[mi][1], af[mi][2], af[mi][3],                \
                      aBase + mi * 16 * TP2 + ko);                               \
            _Pragma("unroll")                                                    \
            for (int bi = 0; bi < 2; ++bi) {                                     \
                uint32_t bf[4];                                                  \
                ldsm4(bf[0], bf[1], bf[2], bf[3], bBase + bi * 16 * TP2 + ko);   \
                _Pragma("unroll")                                                \
                for (int mi = 0; mi < 4; ++mi) {                                 \
                    _Pragma("unroll")                                            \
                    for (int sub = 0; sub < 2; ++sub)                            \
                        mma16816(acc[mi][bi * 2 + sub], af[mi], bf[sub], bf[sub + 2]); \
                }                                                                \
            }                                                                    \
        }                                                                        \
        buf = (buf + 1) % 3;                                                     \
        __syncthreads();                                                         \
    }

// ---------------- O-projection GEMM (128x128, occ 2, fp32 out) -------------
__global__ __launch_bounds__(256, 2) void gemm_o_kernel(
    const __half* __restrict__ A, const __half* __restrict__ Bh,
    float* __restrict__ C, int M, int N, int K)
{
    GEMM_MAINLOOP128(A, Bh, K)
    const int g  = lane >> 2;
    const int q4 = lane & 3;
#pragma unroll
    for (int mi = 0; mi < 4; ++mi) {
#pragma unroll
        for (int nj = 0; nj < 4; ++nj) {
            int r0 = bm + wm * 64 + mi * 16 + g;
            int c0 = bn + wn * 32 + nj * 8 + q4 * 2;
            *(float2*)(C + (size_t)r0 * N + c0)       = make_float2(acc[mi][nj][0], acc[mi][nj][1]);
            *(float2*)(C + (size_t)(r0 + 8) * N + c0) = make_float2(acc[mi][nj][2], acc[mi][nj][3]);
        }
    }
}

// ---------------- Q-proj GEMM (128x128, occ 2) + fused RMSNorm + scale -----
__global__ __launch_bounds__(256, 2) void gemm_q_fused_kernel(
    const __half* __restrict__ A, const __half* __restrict__ Bh,
    const float* __restrict__ nqw, __half* __restrict__ q16, int M, int N, int K)
{
    GEMM_MAINLOOP128(A, Bh, K)
    float* red = (float*)smc;   // 8 warps x 64 rows
    const int g  = lane >> 2;
    const int q4 = lane & 3;
#pragma unroll
    for (int mi = 0; mi < 4; ++mi) {
        float s0 = 0.f, s1 = 0.f;
#pragma unroll
        for (int nj = 0; nj < 4; ++nj) {
            s0 += acc[mi][nj][0] * acc[mi][nj][0] + acc[mi][nj][1] * acc[mi][nj][1];
            s1 += acc[mi][nj][2] * acc[mi][nj][2] + acc[mi][nj][3] * acc[mi][nj][3];
        }
        s0 += __shfl_xor_sync(0xffffffffu, s0, 1);
        s0 += __shfl_xor_sync(0xffffffffu, s0, 2);
        s1 += __shfl_xor_sync(0xffffffffu, s1, 1);
        s1 += __shfl_xor_sync(0xffffffffu, s1, 2);
        if (q4 == 0) {
            red[wid * 64 + mi * 16 + g]     = s0;
            red[wid * 64 + mi * 16 + g + 8] = s1;
        }
    }
    __syncthreads();

#pragma unroll
    for (int mi = 0; mi < 4; ++mi) {
        int rl = mi * 16 + g;
        float ss0 = red[wm * 64 + rl] + red[(2 + wm) * 64 + rl]
                  + red[(4 + wm) * 64 + rl] + red[(6 + wm) * 64 + rl];
        float ss1 = red[wm * 64 + rl + 8] + red[(2 + wm) * 64 + rl + 8]
                  + red[(4 + wm) * 64 + rl + 8] + red[(6 + wm) * 64 + rl + 8];
        float r0 = rsqrtf(ss0 * (1.f / 128.f) + EPSF) * QSCL;
        float r1 = rsqrtf(ss1 * (1.f / 128.f) + EPSF) * QSCL;
        int row0 = bm + wm * 64 + rl;
#pragma unroll
        for (int nj = 0; nj < 4; ++nj) {
            int d = wn * 32 + nj * 8 + q4 * 2;
            float w0 = nqw[d], w1 = nqw[d + 1];
            size_t c0 = (size_t)row0 * N + bn + d;
            *(__half2*)(q16 + c0) =
                __floats2half2_rn(acc[mi][nj][0] * r0 * w0, acc[mi][nj][1] * r0 * w1);
            *(__half2*)(q16 + c0 + (size_t)8 * N) =
                __floats2half2_rn(acc[mi][nj][2] * r1 * w0, acc[mi][nj][3] * r1 * w1);
        }
    }
}

// ---------------- KV-proj GEMM (128x256, occ 1) + fused split/K-norm -------
__global__ __launch_bounds__(256, 1) void gemm_kv_fused_kernel(
    const __half* __restrict__ A, const __half* __restrict__ Bh,
    const float* __restrict__ nkw, __half* __restrict__ k16,
    __half* __restrict__ v16, int M, int N, int K)
{
    GEMM_MAINLOOP(A, Bh, K)
    float* red = (float*)smc;
    const int g  = lane >> 2;
    const int q4 = lane & 3;
#pragma unroll
    for (int mi = 0; mi < 4; ++mi) {
        float s0 = 0.f, s1 = 0.f;
#pragma unroll
        for (int nj = 0; nj < 8; ++nj) {
            s0 += acc[mi][nj][0] * acc[mi][nj][0];
            s1 += acc[mi][nj][2] * acc[mi][nj][2];
        }
        s0 += __shfl_xor_sync(0xffffffffu, s0, 1);
        s0 += __shfl_xor_sync(0xffffffffu, s0, 2);
        s1 += __shfl_xor_sync(0xffffffffu, s1, 1);
        s1 += __shfl_xor_sync(0xffffffffu, s1, 2);
        if (q4 == 0) {
            red[wid * 64 + mi * 16 + g]     = s0;
            red[wid * 64 + mi * 16 + g + 8] = s1;
        }
    }
    __syncthreads();

    const int kvh = blockIdx.x;
#pragma unroll
    for (int mi = 0; mi < 4; ++mi) {
        int rl = mi * 16 + g;
        float ss0 = red[wm * 64 + rl] + red[(2 + wm) * 64 + rl]
                  + red[(4 + wm) * 64 + rl] + red[(6 + wm) * 64 + rl];
        float ss1 = red[wm * 64 + rl + 8] + red[(2 + wm) * 64 + rl + 8]
                  + red[(4 + wm) * 64 + rl + 8] + red[(6 + wm) * 64 + rl + 8];
        float r0 = rsqrtf(ss0 * (1.f / 128.f) + EPSF);
        float r1 = rsqrtf(ss1 * (1.f / 128.f) + EPSF);
        int m0 = bm + wm * 64 + rl;
        int b0 = m0 >> 11, l0 = m0 & 2047;
        size_t base0 = ((size_t)(b0 * NKVH + kvh) * CLEN + l0) * HD;
        size_t base1 = base0 + 8 * HD;
#pragma unroll
        for (int nj = 0; nj < 8; ++nj) {
            int d = wn * 32 + nj * 4 + q4;
            float wk = nkw[d];
            k16[base0 + d] = __float2half_rn(acc[mi][nj][0] * r0 * wk);
            v16[base0 + d] = __float2half_rn(acc[mi][nj][1]);
            k16[base1 + d] = __float2half_rn(acc[mi][nj][2] * r1 * wk);
            v16[base1 + d] = __float2half_rn(acc[mi][nj][3]);
        }
    }
}

// ---------------- fp16 flash attention: BQ=128, BK=64, pipelined QK --------
#define QPITCH  272
#define QBYTES  (128 * QPITCH)      // 34816
#define KVT     (64 * QPITCH)       // 17408
#define KVSTG   (2 * KVT)           // 34816: K, V
#define NKVS    3
#define ATTN_SMEM (QBYTES + NKVS * KVSTG)   // 139264

__global__ __launch_bounds__(256, 1) void attn_f16_kernel(
    const __half* __restrict__ q16, const __half* __restrict__ k16,
    const __half* __restrict__ v16, __half* __restrict__ o16)
{
    extern __shared__ char smc[];
    const uint32_t sb = smem_u32(smc);

    const int tid  = threadIdx.x;
    const int lane = tid & 31;
    const int wid  = tid >> 5;
    const int h    = blockIdx.y;
    const int b    = blockIdx.z;
    const int kvh  = h >> 2;
    const int s0   = blockIdx.x * 128;

    const __half* qg = q16 + ((size_t)(b * SEQ + s0) * NH + h) * HD;
    const size_t kvbase = (size_t)(b * NKVH + kvh) * CLEN * HD;

    {
        int chunk = tid & 15, r0 = tid >> 4;
#pragma unroll
        for (int it = 0; it < 8; ++it) {
            int row = r0 + it * 16;
            cpa16(sb + row * QPITCH + chunk * 16, qg + (size_t)row * HIDDIM + chunk * 8);
        }
        CP_COMMIT();
    }

    auto loadKV = [&](int blk, int stage) {
        uint32_t st = sb + QBYTES + stage * KVSTG;
        const __half* pk = k16 + kvbase + (size_t)blk * 64 * HD;
        const __half* pv = v16 + kvbase + (size_t)blk * 64 * HD;
        int chunk = tid & 15, r0 = tid >> 4;
#pragma unroll
        for (int it = 0; it < 4; ++it) {
            int row = r0 + it * 16;
            uint32_t d = st + row * QPITCH + chunk * 16;
            size_t g = (size_t)row * HD + chunk * 8;
            cpa16(d,       pk + g);
            cpa16(d + KVT, pv + g);
        }
        CP_COMMIT();
    };
    loadKV(0, 0);
    loadKV(1, 1);

    float m0 = -1e30f, m1 = -1e30f, l0 = 0.f, l1 = 0.f;
    float ofr[16][4];
#pragma unroll
    for (int f = 0; f < 16; ++f)
#pragma unroll
        for (int r = 0; r < 4; ++r) ofr[f][r] = 0.f;

    const uint32_t laneOff = (lane & 15) * QPITCH + (lane >> 4) * 16;
    const uint32_t qBase = sb + (wid * 16) * QPITCH + laneOff;

    float scA[8][4], scB[8][4];

#define QK_BLOCK(SC, STG) do {                                                   \
    uint32_t kB_ = sb + QBYTES + (STG) * KVSTG + laneOff;                        \
    _Pragma("unroll")                                                            \
    for (int j = 0; j < 8; ++j) {                                                \
        SC[j][0] = 0.f; SC[j][1] = 0.f; SC[j][2] = 0.f; SC[j][3] = 0.f;          \
    }                                                                            \
    _Pragma("unroll")                                                            \
    for (int kc = 0; kc < 8; ++kc) {                                             \
        uint32_t qa[4];                                                          \
        ldsm4(qa[0], qa[1], qa[2], qa[3], qBase + kc * 32);                      \
        _Pragma("unroll")                                                        \
        for (int kg = 0; kg < 4; ++kg) {                                         \
            uint32_t kb[4];                                                      \
            ldsm4(kb[0], kb[1], kb[2], kb[3], kB_ + kg * 16 * QPITCH + kc * 32); \
            mma16816(SC[kg * 2],     qa, kb[0], kb[2]);                          \
            mma16816(SC[kg * 2 + 1], qa, kb[1], kb[3]);                          \
        }                                                                        \
    }                                                                            \
} while (0)

#define SOFTPV(SC, BLK) do {                                                     \
    float mx0 = -1e30f, mx1 = -1e30f;                                            \
    _Pragma("unroll")                                                            \
    for (int j = 0; j < 8; ++j) {                                                \
        mx0 = fmaxf(mx0, fmaxf(SC[j][0], SC[j][1]));                             \
        mx1 = fmaxf(mx1, fmaxf(SC[j][2], SC[j][3]));                             \
    }                                                                            \
    mx0 = fmaxf(mx0, __shfl_xor_sync(0xffffffffu, mx0, 1));                      \
    mx0 = fmaxf(mx0, __shfl_xor_sync(0xffffffffu, mx0, 2));                      \
    mx1 = fmaxf(mx1, __shfl_xor_sync(0xffffffffu, mx1, 1));                      \
    mx1 = fmaxf(mx1, __shfl_xor_sync(0xffffffffu, mx1, 2));                      \
    float m0n = fmaxf(m0, mx0), m1n = fmaxf(m1, mx1);                            \
    float c0 = ex2f(m0 - m0n), c1 = ex2f(m1 - m1n);                              \
    m0 = m0n; m1 = m1n;                                                          \
    float rs0 = 0.f, rs1 = 0.f;                                                  \
    _Pragma("unroll")                                                            \
    for (int j = 0; j < 8; ++j) {                                                \
        SC[j][0] = ex2f(SC[j][0] - m0); rs0 += SC[j][0];                         \
        SC[j][1] = ex2f(SC[j][1] - m0); rs0 += SC[j][1];                         \
        SC[j][2] = ex2f(SC[j][2] - m1); rs1 += SC[j][2];                         \
        SC[j][3] = ex2f(SC[j][3] - m1); rs1 += SC[j][3];                         \
    }                                                                            \
    rs0 += __shfl_xor_sync(0xffffffffu, rs0, 1);                                 \
    rs0 += __shfl_xor_sync(0xffffffffu, rs0, 2);                                 \
    rs1 += __shfl_xor_sync(0xffffffffu, rs1, 1);                                 \
    rs1 += __shfl_xor_sync(0xffffffffu, rs1, 2);                                 \
    l0 = l0 * c0 + rs0;                                                          \
    l1 = l1 * c1 + rs1;                                                          \
    _Pragma("unroll")                                                            \
    for (int f = 0; f < 16; ++f) {                                               \
        ofr[f][0] *= c0; ofr[f][1] *= c0;                                        \
        ofr[f][2] *= c1; ofr[f][3] *= c1;                                        \
    }                                                                            \
    uint32_t pa[4][4];                                                           \
    _Pragma("unroll")                                                            \
    for (int kc = 0; kc < 4; ++kc) {                                             \
        _Pragma("unroll")                                                        \
        for (int hf = 0; hf < 2; ++hf) {                                         \
            pa[kc][hf * 2]     = packh2(SC[2 * kc + hf][0], SC[2 * kc + hf][1]); \
            pa[kc][hf * 2 + 1] = packh2(SC[2 * kc + hf][2], SC[2 * kc + hf][3]); \
        }                                                                        \
    }                                                                            \
    uint32_t vB_ = sb + QBYTES + ((BLK) % 3) * KVSTG + KVT + laneOff;            \
    _Pragma("unroll")                                                            \
    for (int dg = 0; dg < 8; ++dg) {                                             \
        _Pragma("unroll")                                                        \
        for (int kc = 0; kc < 4; ++kc) {                                         \
            uint32_t vb[4];                                                      \
            ldsm4t(vb[0], vb[1], vb[2], vb[3], vB_ + kc * 16 * QPITCH + dg * 32);\
            mma16816(ofr[dg * 2],     pa[kc], vb[0], vb[1]);                     \
            mma16816(ofr[dg * 2 + 1], pa[kc], vb[2], vb[3]);                     \
        }                                                                        \
    }                                                                            \
} while (0)

    asm volatile("cp.async.wait_group 1;" ::: "memory");
    __syncthreads();
    QK_BLOCK(scA, 0);

    for (int blk = 0; blk < 32; blk += 2) {
        if (blk < 30) {
            loadKV(blk + 2, (blk + 2) % 3);
            asm volatile("cp.async.wait_group 1;" ::: "memory");
        } else {
            asm volatile("cp.async.wait_group 0;" ::: "memory");
        }
        __syncthreads();
        if (blk < 31) QK_BLOCK(scB, (blk + 1) % 3);
        SOFTPV(scA, blk);
        __syncthreads();

        int bo = blk + 1;
        if (bo < 30) {
            loadKV(bo + 2, (bo + 2) % 3);
            asm volatile("cp.async.wait_group 1;" ::: "memory");
        } else if (bo == 30) {
            asm volatile("cp.async.wait_group 0;" ::: "memory");
        }
        __syncthreads();
        if (bo < 31) QK_BLOCK(scA, (bo + 1) % 3);
        SOFTPV(scB, bo);
        __syncthreads();
    }

    float inv0 = 1.f / l0, inv1 = 1.f / l1;
    int rowA = b * SEQ + s0 + wid * 16 + (lane >> 2);
    int colB = h * HD + (lane & 3) * 2;
#pragma unroll
    for (int f = 0; f < 16; ++f) {
        int col = colB + f * 8;
        *(__half2*)(o16 + (size_t)rowA * HIDDIM + col) =
            __floats2half2_rn(ofr[f][0] * inv0, ofr[f][1] * inv0);
        *(__half2*)(o16 + (size_t)(rowA + 8) * HIDDIM + col) =
            __floats2half2_rn(ofr[f][2] * inv1, ofr[f][3] * inv1);
    }
}

// ---------------- launch ----------------------------------------------------
extern "C" void kernel_launch(void* const* d_in, const int* in_sizes, int n_in,
                              void* d_out, int out_size)
{
    (void)in_sizes; (void)n_in; (void)out_size;
    const float* x   = (const float*)d_in[0];
    const float* c   = (const float*)d_in[1];
    const float* wq  = (const float*)d_in[2];
    const float* wkv = (const float*)d_in[3];
    const float* wo  = (const float*)d_in[4];
    const float* nqw = (const float*)d_in[5];
    const float* nkw = (const float*)d_in[6];
    float* out = (float*)d_out;

    __half *x16, *c16, *q16, *k16, *v16, *wqT, *wkvT, *woT;
    cudaGetSymbolAddress((void**)&x16,  g_x16);
    cudaGetSymbolAddress((void**)&c16,  g_c16);
    cudaGetSymbolAddress((void**)&q16,  g_q16);
    cudaGetSymbolAddress((void**)&k16,  g_k16);
    cudaGetSymbolAddress((void**)&v16,  g_v16);
    cudaGetSymbolAddress((void**)&wqT,  g_wqT);
    cudaGetSymbolAddress((void**)&wkvT, g_wkvT);
    cudaGetSymbolAddress((void**)&woT,  g_woT);

    const int M = BATCH * SEQ;            // 4096
    const int K = HIDDIM;                 // 2048
    const int gemm256_smem = NST1 * STB1; // 92160
    const int gemm128_smem = 3 * STB128;  // 61440
    cudaFuncSetAttribute(gemm_q_fused_kernel,
                         cudaFuncAttributeMaxDynamicSharedMemorySize, gemm128_smem);
    cudaFuncSetAttribute(gemm_o_kernel,
                         cudaFuncAttributeMaxDynamicSharedMemorySize, gemm128_smem);
    cudaFuncSetAttribute(gemm_kv_fused_kernel,
                         cudaFuncAttributeMaxDynamicSharedMemorySize, gemm256_smem);
    cudaFuncSetAttribute(attn_f16_kernel,
                         cudaFuncAttributeMaxDynamicSharedMemorySize, ATTN_SMEM);

    // 0) all conversions in one launch: x16, c16, wqT, wkvT, woT
    prep_kernel<<<26624, 256>>>((const float4*)x, (const float4*)c,
                                wq, wkv, wo, x16, c16, wqT, wkvT, woT);

    // 1) Q projection + fused rmsnorm + softmax-scale fold (128x128, occ 2)
    gemm_q_fused_kernel<<<dim3(HIDDIM / 128, M / 128), 256, gemm128_smem>>>(
        x16, wqT, nqw, q16, M, HIDDIM, K);

    // 2) KV projection + fused split/K-rmsnorm (128x256, occ 1)
    gemm_kv_fused_kernel<<<dim3((NKVH * HD * 2) / 256, M / 128), 256, gemm256_smem>>>(
        c16, wkvT, nkw, k16, v16, M, NKVH * HD * 2, K);

    // 3) pipelined fp16 attention -> fp16 activations (reuse x16)
    attn_f16_kernel<<<dim3(SEQ / 128, NH, BATCH), 256, ATTN_SMEM>>>(
        q16, k16, v16, x16);

    // 4) output projection (128x128, occ 2) -> fp32 out
    gemm_o_kernel<<<dim3(HIDDIM / 128, M / 128), 256, gemm128_smem>>>(
        x16, woT, out, M, HIDDIM, K);
}

// round 12
// speedup vs baseline: 5.9480x; 1.0242x over previous
#include <cuda_runtime.h>
#include <cuda_fp16.h>
#include <math.h>
#include <stdint.h>

#define BATCH 2
#define SEQ   2048
#define CLEN  2048
#define NH    16
#define NKVH  4
#define HD    128
#define HIDDIM 2048
#define EPSF  1e-6f
#define QSCL  (0.08838834764831845f * 1.4426950408889634f)

// ---------------- scratch (device globals) ---------------------------------
__device__ __half g_x16[BATCH*SEQ*HIDDIM];
__device__ __half g_c16[BATCH*SEQ*HIDDIM];
__device__ __half g_q16[BATCH*SEQ*HIDDIM];
__device__ __half g_k16[BATCH*NKVH*CLEN*HD];
__device__ __half g_v16[BATCH*NKVH*CLEN*HD];
__device__ __half g_wqT [HIDDIM*HIDDIM];
__device__ __half g_wkvT[HIDDIM*NKVH*HD*2];
__device__ __half g_woT [HIDDIM*HIDDIM];

// ======================= helpers ============================================
__device__ __forceinline__ uint32_t smem_u32(const void* p) {
    uint32_t a;
    asm("{ .reg .u64 t; cvta.to.shared.u64 t, %1; cvt.u32.u64 %0, t; }" : "=r"(a) : "l"(p));
    return a;
}
__device__ __forceinline__ void cpa16(uint32_t d, const void* g) {
    asm volatile("cp.async.cg.shared.global [%0], [%1], 16;" :: "r"(d), "l"(g) : "memory");
}
#define CP_COMMIT() asm volatile("cp.async.commit_group;" ::: "memory")

__device__ __forceinline__ void ldsm4(uint32_t& r0, uint32_t& r1, uint32_t& r2, uint32_t& r3,
                                      uint32_t a) {
    asm volatile("ldmatrix.sync.aligned.m8n8.x4.shared.b16 {%0,%1,%2,%3}, [%4];"
                 : "=r"(r0), "=r"(r1), "=r"(r2), "=r"(r3) : "r"(a));
}
__device__ __forceinline__ void ldsm4t(uint32_t& r0, uint32_t& r1, uint32_t& r2, uint32_t& r3,
                                       uint32_t a) {
    asm volatile("ldmatrix.sync.aligned.m8n8.x4.trans.shared.b16 {%0,%1,%2,%3}, [%4];"
                 : "=r"(r0), "=r"(r1), "=r"(r2), "=r"(r3) : "r"(a));
}
__device__ __forceinline__ void mma16816(float* c, const uint32_t* a, uint32_t b0, uint32_t b1) {
    asm volatile(
        "mma.sync.aligned.m16n8k16.row.col.f32.f16.f16.f32 "
        "{%0,%1,%2,%3}, {%4,%5,%6,%7}, {%8,%9}, {%0,%1,%2,%3};"
        : "+f"(c[0]), "+f"(c[1]), "+f"(c[2]), "+f"(c[3])
        : "r"(a[0]), "r"(a[1]), "r"(a[2]), "r"(a[3]), "r"(b0), "r"(b1));
}
__device__ __forceinline__ uint32_t packh2(float a, float b) {
    __half2 h = __floats2half2_rn(a, b);
    return *(uint32_t*)&h;
}
__device__ __forceinline__ float ex2f(float x) {
    float y;
    asm("ex2.approx.f32 %0, %1;" : "=f"(y) : "f"(x));
    return y;
}

// ---------------- fused prep kernel -----------------------------------------
#define NF4 ((size_t)BATCH * SEQ * HIDDIM / 4)

__global__ __launch_bounds__(256) void prep_kernel(
    const float4* __restrict__ x, const float4* __restrict__ c,
    const float* __restrict__ wq, const float* __restrict__ wkv,
    const float* __restrict__ wo,
    __half* __restrict__ x16, __half* __restrict__ c16,
    __half* __restrict__ wqT, __half* __restrict__ wkvT, __half* __restrict__ woT)
{
    __shared__ float s[32][33];
    int bid = blockIdx.x;

    if (bid < 16384) {
        size_t i = (size_t)bid * 256 + threadIdx.x;
        const float4* src; __half* dst; size_t j;
        if (i < NF4) { src = x; dst = x16; j = i; }
        else         { src = c; dst = c16; j = i - NF4; }
        float4 v = src[j];
        ((__half2*)dst)[j * 2]     = __floats2half2_rn(v.x, v.y);
        ((__half2*)dst)[j * 2 + 1] = __floats2half2_rn(v.z, v.w);
        return;
    }
    bid -= 16384;

    const float* w; __half* o; int N;
    if (bid < 4096)      {              w = wq;  o = wqT;  N = HIDDIM; }
    else if (bid < 6144) { bid -= 4096; w = wkv; o = wkvT; N = NKVH * HD * 2; }
    else                 { bid -= 6144; w = wo;  o = woT;  N = HIDDIM; }

    const int K = HIDDIM;
    int nb = N / 32;
    int n0 = (bid % nb) * 32, k0 = (bid / nb) * 32;
    int tx = threadIdx.x & 31, ty = threadIdx.x >> 5;
#pragma unroll
    for (int i = ty; i < 32; i += 8)
        s[i][tx] = w[(size_t)(k0 + i) * N + n0 + tx];
    __syncthreads();
#pragma unroll
    for (int j = ty; j < 32; j += 8)
        o[(size_t)(n0 + j) * K + k0 + tx] = __float2half_rn(s[tx][j]);
}

// ============ GEMM mainloop macros ==========================================
#define TP2  80
#define A_T  (128 * TP2)             // 10240
#define B_T  (256 * TP2)             // 20480
#define STB1 (A_T + B_T)             // 30720  (128x256)
#define NST1 3
#define B1_T (128 * TP2)
#define STB128 (A_T + B1_T)          // 20480  (128x128)

// 128x256 tile mainloop, runtime bn (occ 1)
#define GEMM_MAINLOOP256(APTR, BPTR, BNVAL, KDIM)                                \
    extern __shared__ char smc[];                                                \
    const uint32_t sb = smem_u32(smc);                                           \
    const int tid  = threadIdx.x;                                                \
    const int lane = tid & 31;                                                   \
    const int wid  = tid >> 5;                                                   \
    const int wm   = wid & 1;                                                    \
    const int wn   = wid >> 1;                                                   \
    const int bm   = blockIdx.y * 128;                                           \
    const int bn   = (BNVAL);                                                    \
    const int arow = tid >> 1;                                                   \
    const int ahalf = tid & 1;                                                   \
    const size_t gA = (size_t)(bm + arow) * (KDIM) + ahalf * 16;                 \
    const uint32_t sA = arow * TP2 + ahalf * 32;                                 \
    const size_t gB = (size_t)(bn + tid) * (KDIM);                               \
    const uint32_t sB = tid * TP2;                                               \
    const uint32_t laneOff = (lane & 15) * TP2 + (lane >> 4) * 16;               \
    float acc[4][8][4];                                                          \
    _Pragma("unroll")                                                            \
    for (int i = 0; i < 4; i++)                                                  \
        _Pragma("unroll")                                                        \
        for (int j = 0; j < 8; j++)                                              \
            _Pragma("unroll")                                                    \
            for (int r = 0; r < 4; r++) acc[i][j][r] = 0.f;                      \
    const int nst = (KDIM) / 32;                                                 \
    auto loadStage = [&](int s, int buf) {                                       \
        uint32_t st = sb + buf * STB1;                                           \
        int k0 = s * 32;                                                         \
        cpa16(st + sA,      (APTR) + gA + k0);                                   \
        cpa16(st + sA + 16, (APTR) + gA + k0 + 8);                               \
        uint32_t bb = st + A_T + sB;                                             \
        cpa16(bb,      (BPTR) + gB + k0);                                        \
        cpa16(bb + 16, (BPTR) + gB + k0 + 8);                                    \
        cpa16(bb + 32, (BPTR) + gB + k0 + 16);                                   \
        cpa16(bb + 48, (BPTR) + gB + k0 + 24);                                   \
        CP_COMMIT();                                                             \
    };                                                                           \
    loadStage(0, 0);                                                             \
    loadStage(1, 1);                                                             \
    int buf = 0;                                                                 \
    for (int s = 0; s < nst; ++s) {                                              \
        if (s + 1 < nst) asm volatile("cp.async.wait_group 1;" ::: "memory");    \
        else             asm volatile("cp.async.wait_group 0;" ::: "memory");    \
        __syncthreads();                                                         \
        if (s + 2 < nst) loadStage(s + 2, (buf + 2) % NST1);                     \
        uint32_t st = sb + buf * STB1;                                           \
        uint32_t aBase  = st + (wm * 64) * TP2 + laneOff;                        \
        uint32_t bBase  = st + A_T + (wn * 64) * TP2 + laneOff;                  \
        _Pragma("unroll")                                                        \
        for (int ks = 0; ks < 2; ++ks) {                                         \
            uint32_t ko = ks * 32;                                               \
            uint32_t af[4][4];                                                   \
            _Pragma("unroll")                                                    \
            for (int mi = 0; mi < 4; ++mi)                                       \
                ldsm4(af[mi][0], af[mi][1], af[mi][2], af[mi][3],                \
                      aBase + mi * 16 * TP2 + ko);                               \
            _Pragma("unroll")                                                    \
            for (int bi = 0; bi < 4; ++bi) {                                     \
                uint32_t bf[4];                                                  \
                ldsm4(bf[0], bf[1], bf[2], bf[3], bBase + bi * 16 * TP2 + ko);   \
                _Pragma("unroll")                                                \
                for (int mi = 0; mi < 4; ++mi) {                                 \
                    _Pragma("unroll")                                            \
                    for (int sub = 0; sub < 2; ++sub)                            \
                        mma16816(acc[mi][bi * 2 + sub], af[mi], bf[sub], bf[sub + 2]); \
                }                                                                \
            }                                                                    \
        }                                                                        \
        buf = (buf + 1) % NST1;                                                  \
        __syncthreads();                                                         \
    }

// 128x128 tile mainloop (occ 2) — O-projection
#define GEMM_MAINLOOP128(APTR, BPTR, KDIM)                                       \
    extern __shared__ char smc[];                                                \
    const uint32_t sb = smem_u32(smc);                                           \
    const int tid  = threadIdx.x;                                                \
    const int lane = tid & 31;                                                   \
    const int wid  = tid >> 5;                                                   \
    const int wm   = wid & 1;                                                    \
    const int wn   = wid >> 1;                                                   \
    const int bm   = blockIdx.y * 128;                                           \
    const int bn   = blockIdx.x * 128;                                           \
    const int arow = tid >> 1;                                                   \
    const int ahalf = tid & 1;                                                   \
    const size_t gA = (size_t)(bm + arow) * (KDIM) + ahalf * 16;                 \
    const size_t gB = (size_t)(bn + arow) * (KDIM) + ahalf * 16;                 \
    const uint32_t sA = arow * TP2 + ahalf * 32;                                 \
    const uint32_t laneOff = (lane & 15) * TP2 + (lane >> 4) * 16;               \
    float acc[4][4][4];                                                          \
    _Pragma("unroll")                                                            \
    for (int i = 0; i < 4; i++)                                                  \
        _Pragma("unroll")                                                        \
        for (int j = 0; j < 4; j++)                                              \
            _Pragma("unroll")                                                    \
            for (int r = 0; r < 4; r++) acc[i][j][r] = 0.f;                      \
    const int nst = (KDIM) / 32;                                                 \
    auto loadStage = [&](int s, int buf) {                                       \
        uint32_t st = sb + buf * STB128;                                         \
        int k0 = s * 32;                                                         \
        cpa16(st + sA,            (APTR) + gA + k0);                             \
        cpa16(st + sA + 16,       (APTR) + gA + k0 + 8);                         \
        cpa16(st + A_T + sA,      (BPTR) + gB + k0);                             \
        cpa16(st + A_T + sA + 16, (BPTR) + gB + k0 + 8);                         \
        CP_COMMIT();                                                             \
    };                                                                           \
    loadStage(0, 0);                                                             \
    loadStage(1, 1);                                                             \
    int buf = 0;                                                                 \
    for (int s = 0; s < nst; ++s) {                                              \
        if (s + 1 < nst) asm volatile("cp.async.wait_group 1;" ::: "memory");    \
        else             asm volatile("cp.async.wait_group 0;" ::: "memory");    \
        __syncthreads();                                                         \
        if (s + 2 < nst) loadStage(s + 2, (buf + 2) % 3);                        \
        uint32_t st = sb + buf * STB128;                                         \
        uint32_t aBase  = st + (wm * 64) * TP2 + laneOff;                        \
        uint32_t bBase  = st + A_T + (wn * 32) * TP2 + laneOff;                  \
        _Pragma("unroll")                                                        \
        for (int ks = 0; ks < 2; ++ks) {                                         \
            uint32_t ko = ks * 32;                                               \
            uint32_t af[4][4];                                                   \
            _Pragma("unroll")                                                    \
            for (int mi = 0; mi < 4; ++mi)                                       \
                ldsm4(af[mi][0], af[mi][1], af[mi][2], af[mi][3],                \
                      aBase + mi * 16 * TP2 + ko);                               \
            _Pragma("unroll")                                                    \
            for (int bi = 0; bi < 2; ++bi) {                                     \
                uint32_t bf[4];                                                  \
                ldsm4(bf[0], bf[1], bf[2], bf[3], bBase + bi * 16 * TP2 + ko);   \
                _Pragma("unroll")                                                \
                for (int mi = 0; mi < 4; ++mi) {                                 \
                    _Pragma("unroll")                                            \
                    for (int sub = 0; sub < 2; ++sub)                            \
                        mma16816(acc[mi][bi * 2 + sub], af[mi], bf[sub], bf[sub + 2]); \
                }                                                                \
            }                                                                    \
        }                                                                        \
        buf = (buf + 1) % 3;                                                     \
        __syncthreads();                                                         \
    }

// ---------------- O-projection GEMM -----------------------------------------
__global__ __launch_bounds__(256, 2) void gemm_o_kernel(
    const __half* __restrict__ A, const __half* __restrict__ Bh,
    float* __restrict__ C, int M, int N, int K)
{
    GEMM_MAINLOOP128(A, Bh, K)
    const int g  = lane >> 2;
    const int q4 = lane & 3;
#pragma unroll
    for (int mi = 0; mi < 4; ++mi) {
#pragma unroll
        for (int nj = 0; nj < 4; ++nj) {
            int r0 = bm + wm * 64 + mi * 16 + g;
            int c0 = bn + wn * 32 + nj * 8 + q4 * 2;
            *(float2*)(C + (size_t)r0 * N + c0)       = make_float2(acc[mi][nj][0], acc[mi][nj][1]);
            *(float2*)(C + (size_t)(r0 + 8) * N + c0) = make_float2(acc[mi][nj][2], acc[mi][nj][3]);
        }
    }
}

// ---------------- unified Q-proj + KV-proj GEMM (128x256, occ 1) -----------
// blockIdx.x 0..7: Q-proj tiles (N=2048); 8..11: KV-proj tiles (kvh = x-8)
__global__ __launch_bounds__(256, 1) void gemm_qkv_fused_kernel(
    const __half* __restrict__ x16a, const __half* __restrict__ wqT,
    const float* __restrict__ nqw, __half* __restrict__ q16,
    const __half* __restrict__ c16a, const __half* __restrict__ wkvT,
    const float* __restrict__ nkw, __half* __restrict__ k16,
    __half* __restrict__ v16)
{
    const bool isQ = blockIdx.x < 8;
    const __half* Ap = isQ ? x16a : c16a;
    const __half* Bp = isQ ? wqT : wkvT;
    const int bnIdx = isQ ? blockIdx.x : blockIdx.x - 8;

    GEMM_MAINLOOP256(Ap, Bp, bnIdx * 256, HIDDIM)

    float* red = (float*)smc;
    const int g  = lane >> 2;
    const int q4 = lane & 3;

    if (isQ) {
        const int N = HIDDIM;
#pragma unroll
        for (int mi = 0; mi < 4; ++mi) {
            float s0 = 0.f, s1 = 0.f;
#pragma unroll
            for (int nj = 0; nj < 8; ++nj) {
                s0 += acc[mi][nj][0] * acc[mi][nj][0] + acc[mi][nj][1] * acc[mi][nj][1];
                s1 += acc[mi][nj][2] * acc[mi][nj][2] + acc[mi][nj][3] * acc[mi][nj][3];
            }
            s0 += __shfl_xor_sync(0xffffffffu, s0, 1);
            s0 += __shfl_xor_sync(0xffffffffu, s0, 2);
            s1 += __shfl_xor_sync(0xffffffffu, s1, 1);
            s1 += __shfl_xor_sync(0xffffffffu, s1, 2);
            if (q4 == 0) {
                red[wid * 64 + mi * 16 + g]     = s0;
                red[wid * 64 + mi * 16 + g + 8] = s1;
            }
        }
        __syncthreads();

        const int dbase = ((wid >> 1) & 1) * 64;
#pragma unroll
        for (int mi = 0; mi < 4; ++mi) {
            int rl = mi * 16 + g;
            float ss0 = red[wid * 64 + rl]     + red[(wid ^ 2) * 64 + rl];
            float ss1 = red[wid * 64 + rl + 8] + red[(wid ^ 2) * 64 + rl + 8];
            float r0 = rsqrtf(ss0 * (1.f / 128.f) + EPSF) * QSCL;
            float r1 = rsqrtf(ss1 * (1.f / 128.f) + EPSF) * QSCL;
            int row0 = bm + wm * 64 + rl;
#pragma unroll
            for (int nj = 0; nj < 8; ++nj) {
                int d = dbase + nj * 8 + q4 * 2;
                float w0 = nqw[d], w1 = nqw[d + 1];
                size_t c0 = (size_t)row0 * N + bn + wn * 64 + nj * 8 + q4 * 2;
                *(__half2*)(q16 + c0) =
                    __floats2half2_rn(acc[mi][nj][0] * r0 * w0, acc[mi][nj][1] * r0 * w1);
                *(__half2*)(q16 + c0 + (size_t)8 * N) =
                    __floats2half2_rn(acc[mi][nj][2] * r1 * w0, acc[mi][nj][3] * r1 * w1);
            }
        }
    } else {
#pragma unroll
        for (int mi = 0; mi < 4; ++mi) {
            float s0 = 0.f, s1 = 0.f;
#pragma unroll
            for (int nj = 0; nj < 8; ++nj) {
                s0 += acc[mi][nj][0] * acc[mi][nj][0];
                s1 += acc[mi][nj][2] * acc[mi][nj][2];
            }
            s0 += __shfl_xor_sync(0xffffffffu, s0, 1);
            s0 += __shfl_xor_sync(0xffffffffu, s0, 2);
            s1 += __shfl_xor_sync(0xffffffffu, s1, 1);
            s1 += __shfl_xor_sync(0xffffffffu, s1, 2);
            if (q4 == 0) {
                red[wid * 64 + mi * 16 + g]     = s0;
                red[wid * 64 + mi * 16 + g + 8] = s1;
            }
        }
        __syncthreads();

        const int kvh = bnIdx;
#pragma unroll
        for (int mi = 0; mi < 4; ++mi) {
            int rl = mi * 16 + g;
            float ss0 = red[wm * 64 + rl] + red[(2 + wm) * 64 + rl]
                      + red[(4 + wm) * 64 + rl] + red[(6 + wm) * 64 + rl];
            float ss1 = red[wm * 64 + rl + 8] + red[(2 + wm) * 64 + rl + 8]
                      + red[(4 + wm) * 64 + rl + 8] + red[(6 + wm) * 64 + rl + 8];
            float r0 = rsqrtf(ss0 * (1.f / 128.f) + EPSF);
            float r1 = rsqrtf(ss1 * (1.f / 128.f) + EPSF);
            int m0 = bm + wm * 64 + rl;
            int b0 = m0 >> 11, l0 = m0 & 2047;
            size_t base0 = ((size_t)(b0 * NKVH + kvh) * CLEN + l0) * HD;
            size_t base1 = base0 + 8 * HD;
#pragma unroll
            for (int nj = 0; nj < 8; ++nj) {
                int d = wn * 32 + nj * 4 + q4;
                float wk = nkw[d];
                k16[base0 + d] = __float2half_rn(acc[mi][nj][0] * r0 * wk);
                v16[base0 + d] = __float2half_rn(acc[mi][nj][1]);
                k16[base1 + d] = __float2half_rn(acc[mi][nj][2] * r1 * wk);
                v16[base1 + d] = __float2half_rn(acc[mi][nj][3]);
            }
        }
    }
}

// ---------------- fp16 flash attention: BQ=64, 4 warps, occ 2 --------------
#define QPITCH  272
#define QBYTES  (64 * QPITCH)       // 17408
#define KVT     (64 * QPITCH)       // 17408
#define KVSTG   (2 * KVT)           // 34816: K, V
#define ATTN_SMEM (QBYTES + 2 * KVSTG)   // 87040

__global__ __launch_bounds__(128, 2) void attn_f16_kernel(
    const __half* __restrict__ q16, const __half* __restrict__ k16,
    const __half* __restrict__ v16, __half* __restrict__ o16)
{
    extern __shared__ char smc[];
    const uint32_t sb = smem_u32(smc);

    const int tid  = threadIdx.x;
    const int lane = tid & 31;
    const int wid  = tid >> 5;            // 0..3
    const int h    = blockIdx.y;
    const int b    = blockIdx.z;
    const int kvh  = h >> 2;
    const int s0   = blockIdx.x * 64;

    const __half* qg = q16 + ((size_t)(b * SEQ + s0) * NH + h) * HD;
    const size_t kvbase = (size_t)(b * NKVH + kvh) * CLEN * HD;

    // Q resident tile: 64 rows x 128 cols
    {
        int chunk = tid & 15, r0 = tid >> 4;   // 16 chunks, 8 row-groups
#pragma unroll
        for (int it = 0; it < 8; ++it) {
            int row = r0 + it * 8;
            cpa16(sb + row * QPITCH + chunk * 16, qg + (size_t)row * HIDDIM + chunk * 8);
        }
        CP_COMMIT();
    }

    auto loadKV = [&](int blk, int stage) {
        uint32_t st = sb + QBYTES + stage * KVSTG;
        const __half* pk = k16 + kvbase + (size_t)blk * 64 * HD;
        const __half* pv = v16 + kvbase + (size_t)blk * 64 * HD;
        int chunk = tid & 15, r0 = tid >> 4;
#pragma unroll
        for (int it = 0; it < 8; ++it) {
            int row = r0 + it * 8;
            uint32_t d = st + row * QPITCH + chunk * 16;
            size_t g = (size_t)row * HD + chunk * 8;
            cpa16(d,       pk + g);
            cpa16(d + KVT, pv + g);
        }
        CP_COMMIT();
    };
    loadKV(0, 0);

    float m0 = -1e30f, m1 = -1e30f, l0 = 0.f, l1 = 0.f;
    float ofr[16][4];
#pragma unroll
    for (int f = 0; f < 16; ++f)
#pragma unroll
        for (int r = 0; r < 4; ++r) ofr[f][r] = 0.f;

    const uint32_t laneOff = (lane & 15) * QPITCH + (lane >> 4) * 16;
    const uint32_t qBase = sb + (wid * 16) * QPITCH + laneOff;

    float scA[8][4], scB[8][4];

#define QK_BLOCK(SC, STG) do {                                                   \
    uint32_t kB_ = sb + QBYTES + (STG) * KVSTG + laneOff;                        \
    _Pragma("unroll")                                                            \
    for (int j = 0; j < 8; ++j) {                                                \
        SC[j][0] = 0.f; SC[j][1] = 0.f; SC[j][2] = 0.f; SC[j][3] = 0.f;          \
    }                                                                            \
    _Pragma("unroll")                                                            \
    for (int kc = 0; kc < 8; ++kc) {                                             \
        uint32_t qa[4];                                                          \
        ldsm4(qa[0], qa[1], qa[2], qa[3], qBase + kc * 32);                      \
        _Pragma("unroll")                                                        \
        for (int kg = 0; kg < 4; ++kg) {                                         \
            uint32_t kb[4];                                                      \
            ldsm4(kb[0], kb[1], kb[2], kb[3], kB_ + kg * 16 * QPITCH + kc * 32); \
            mma16816(SC[kg * 2],     qa, kb[0], kb[2]);                          \
            mma16816(SC[kg * 2 + 1], qa, kb[1], kb[3]);                          \
        }                                                                        \
    }                                                                            \
} while (0)

#define SOFTPV(SC, BLK) do {                                                     \
    float mx0 = -1e30f, mx1 = -1e30f;                                            \
    _Pragma("unroll")                                                            \
    for (int j = 0; j < 8; ++j) {                                                \
        mx0 = fmaxf(mx0, fmaxf(SC[j][0], SC[j][1]));                             \
        mx1 = fmaxf(mx1, fmaxf(SC[j][2], SC[j][3]));                             \
    }                                                                            \
    mx0 = fmaxf(mx0, __shfl_xor_sync(0xffffffffu, mx0, 1));                      \
    mx0 = fmaxf(mx0, __shfl_xor_sync(0xffffffffu, mx0, 2));                      \
    mx1 = fmaxf(mx1, __shfl_xor_sync(0xffffffffu, mx1, 1));                      \
    mx1 = fmaxf(mx1, __shfl_xor_sync(0xffffffffu, mx1, 2));                      \
    float c0_ = ex2f(m0 - fmaxf(m0, mx0)), c1_ = ex2f(m1 - fmaxf(m1, mx1));      \
    m0 = fmaxf(m0, mx0); m1 = fmaxf(m1, mx1);                                    \
    float rs0 = 0.f, rs1 = 0.f;                                                  \
    _Pragma("unroll")                                                            \
    for (int j = 0; j < 8; ++j) {                                                \
        SC[j][0] = ex2f(SC[j][0] - m0); rs0 += SC[j][0];                         \
        SC[j][1] = ex2f(SC[j][1] - m0); rs0 += SC[j][1];                         \
        SC[j][2] = ex2f(SC[j][2] - m1); rs1 += SC[j][2];                         \
        SC[j][3] = ex2f(SC[j][3] - m1); rs1 += SC[j][3];                         \
    }                                                                            \
    rs0 += __shfl_xor_sync(0xffffffffu, rs0, 1);                                 \
    rs0 += __shfl_xor_sync(0xffffffffu, rs0, 2);                                 \
    rs1 += __shfl_xor_sync(0xffffffffu, rs1, 1);                                 \
    rs1 += __shfl_xor_sync(0xffffffffu, rs1, 2);                                 \
    l0 = l0 * c0_ + rs0;                                                         \
    l1 = l1 * c1_ + rs1;                                                         \
    _Pragma("unroll")                                                            \
    for (int f = 0; f < 16; ++f) {                                               \
        ofr[f][0] *= c0_; ofr[f][1] *= c0_;                                      \
        ofr[f][2] *= c1_; ofr[f][3] *= c1_;                                      \
    }                                                                            \
    uint32_t pa[4][4];                                                           \
    _Pragma("unroll")                                                            \
    for (int kc = 0; kc < 4; ++kc) {                                             \
        _Pragma("unroll")                                                        \
        for (int hf = 0; hf < 2; ++hf) {                                         \
            pa[kc][hf * 2]     = packh2(SC[2 * kc + hf][0], SC[2 * kc + hf][1]); \
            pa[kc][hf * 2 + 1] = packh2(SC[2 * kc + hf][2], SC[2 * kc + hf][3]); \
        }                                                                        \
    }                                                                            \
    uint32_t vB_ = sb + QBYTES + ((BLK) & 1) * KVSTG + KVT + laneOff;            \
    _Pragma("unroll")                                                            \
    for (int dg = 0; dg < 8; ++dg) {                                             \
        _Pragma("unroll")                                                        \
        for (int kc = 0; kc < 4; ++kc) {                                         \
            uint32_t vb[4];                                                      \
            ldsm4t(vb[0], vb[1], vb[2], vb[3], vB_ + kc * 16 * QPITCH + dg * 32);\
            mma16816(ofr[dg * 2],     pa[kc], vb[0], vb[1]);                     \
            mma16816(ofr[dg * 2 + 1], pa[kc], vb[2], vb[3]);                     \
        }                                                                        \
    }                                                                            \
} while (0)

    asm volatile("cp.async.wait_group 0;" ::: "memory");   // Q + KV0
    __syncthreads();
    QK_BLOCK(scA, 0);

#pragma unroll 1
    for (int blk = 0; blk < 32; blk += 2) {
        // even block in scA
        if (blk + 1 < 32) loadKV(blk + 1, (blk + 1) & 1);
        SOFTPV(scA, blk);
        if (blk + 1 < 32) {
            asm volatile("cp.async.wait_group 0;" ::: "memory");
            __syncthreads();
            QK_BLOCK(scB, (blk + 1) & 1);
        }
        // odd block in scB
        if (blk + 2 < 32) loadKV(blk + 2, (blk + 2) & 1);
        if (blk + 1 < 32) SOFTPV(scB, blk + 1);
        if (blk + 2 < 32) {
            asm volatile("cp.async.wait_group 0;" ::: "memory");
            __syncthreads();
            QK_BLOCK(scA, (blk + 2) & 1);
        }
    }

    float inv0 = 1.f / l0, inv1 = 1.f / l1;
    int rowA = b * SEQ + s0 + wid * 16 + (lane >> 2);
    int colB = h * HD + (lane & 3) * 2;
#pragma unroll
    for (int f = 0; f < 16; ++f) {
        int col = colB + f * 8;
        *(__half2*)(o16 + (size_t)rowA * HIDDIM + col) =
            __floats2half2_rn(ofr[f][0] * inv0, ofr[f][1] * inv0);
        *(__half2*)(o16 + (size_t)(rowA + 8) * HIDDIM + col) =
            __floats2half2_rn(ofr[f][2] * inv1, ofr[f][3] * inv1);
    }
}

// ---------------- launch ----------------------------------------------------
extern "C" void kernel_launch(void* const* d_in, const int* in_sizes, int n_in,
                              void* d_out, int out_size)
{
    (void)in_sizes; (void)n_in; (void)out_size;
    const float* x   = (const float*)d_in[0];
    const float* c   = (const float*)d_in[1];
    const float* wq  = (const float*)d_in[2];
    const float* wkv = (const float*)d_in[3];
    const float* wo  = (const float*)d_in[4];
    const float* nqw = (const float*)d_in[5];
    const float* nkw = (const float*)d_in[6];
    float* out = (float*)d_out;

    __half *x16, *c16, *q16, *k16, *v16, *wqT, *wkvT, *woT;
    cudaGetSymbolAddress((void**)&x16,  g_x16);
    cudaGetSymbolAddress((void**)&c16,  g_c16);
    cudaGetSymbolAddress((void**)&q16,  g_q16);
    cudaGetSymbolAddress((void**)&k16,  g_k16);
    cudaGetSymbolAddress((void**)&v16,  g_v16);
    cudaGetSymbolAddress((void**)&wqT,  g_wqT);
    cudaGetSymbolAddress((void**)&wkvT, g_wkvT);
    cudaGetSymbolAddress((void**)&woT,  g_woT);

    const int M = BATCH * SEQ;            // 4096
    const int K = HIDDIM;                 // 2048
    const int gemm256_smem = NST1 * STB1; // 92160
    const int gemm128_smem = 3 * STB128;  // 61440
    cudaFuncSetAttribute(gemm_qkv_fused_kernel,
                         cudaFuncAttributeMaxDynamicSharedMemorySize, gemm256_smem);
    cudaFuncSetAttribute(gemm_o_kernel,
                         cudaFuncAttributeMaxDynamicSharedMemorySize, gemm128_smem);
    cudaFuncSetAttribute(attn_f16_kernel,
                         cudaFuncAttributeMaxDynamicSharedMemorySize, ATTN_SMEM);

    // 0) all conversions in one launch
    prep_kernel<<<26624, 256>>>((const float4*)x, (const float4*)c,
                                wq, wkv, wo, x16, c16, wqT, wkvT, woT);

    // 1) Q-proj + KV-proj in one launch (12 x 32 tiles of 128x256)
    gemm_qkv_fused_kernel<<<dim3(12, M / 128), 256, gemm256_smem>>>(
        x16, wqT, nqw, q16, c16, wkvT, nkw, k16, v16);

    // 2) attention: BQ=64, 4 warps, occ 2 per SM
    attn_f16_kernel<<<dim3(SEQ / 64, NH, BATCH), 128, ATTN_SMEM>>>(
        q16, k16, v16, x16);

    // 3) output projection (128x128, occ 2) -> fp32 out
    gemm_o_kernel<<<dim3(HIDDIM / 128, M / 128), 256, gemm128_smem>>>(
        x16, woT, out, M, HIDDIM, K);
}